// round 1
// baseline (speedup 1.0000x reference)
#include <cuda_runtime.h>

#define HH 128
#define WW 128
#define CC 64
#define BB 4
#define COUT 64
#define K2 9
#define CK 576         // CC*K2
#define SP 68          // S pitch (pixels dim), padded for bank-conflict relief
#define TP 64          // pixels per block in main kernel

// Scratch (device globals; no allocations allowed)
__device__ float g_xT[BB * HH * WW * CC];     // x transposed to (b,y,x,c)  ~16MB
__device__ float g_off[BB * HH * WW * 18];    // offsets, (pixel, 18)       ~4.7MB
__device__ float g_wT[K2 * CC * COUT];        // w_deform as (k,c,o)        144KB

// ---------------------------------------------------------------------------
// 1) Transpose x: NCHW -> NHWC (per b: [C][HW] -> [HW][C]) via smem tiles
// ---------------------------------------------------------------------------
__global__ void k_transpose(const float* __restrict__ x) {
    __shared__ float tile[32][33];
    int b  = blockIdx.z;
    int c0 = blockIdx.y * 32;
    int p0 = blockIdx.x * 32;
    int tx = threadIdx.x, ty = threadIdx.y;   // (32, 8)
    const float* src = x + (size_t)b * CC * HH * WW;
    float* dst = g_xT + (size_t)b * HH * WW * CC;
#pragma unroll
    for (int i = 0; i < 32; i += 8)
        tile[ty + i][tx] = src[(size_t)(c0 + ty + i) * (HH * WW) + p0 + tx];
    __syncthreads();
#pragma unroll
    for (int i = 0; i < 32; i += 8)
        dst[(size_t)(p0 + ty + i) * CC + c0 + tx] = tile[tx][ty + i];
}

// ---------------------------------------------------------------------------
// 2) Transpose w_deform: (o,c,k) -> (k,c,o)
// ---------------------------------------------------------------------------
__global__ void k_wprep(const float* __restrict__ wd) {
    int i = blockIdx.x * 256 + threadIdx.x;
    if (i < K2 * CC * COUT) {
        int o = i % COUT;
        int t = i / COUT;
        int c = t % CC;
        int k = t / CC;
        g_wT[i] = wd[(size_t)(o * CC + c) * K2 + k];
    }
}

// ---------------------------------------------------------------------------
// 3) Offset conv: out 18 channels per pixel. One thread per pixel.
//    Weights staged in smem as [(c*9+tap)*20 + j] (pitch 20 => 16B aligned
//    rows => float4 LDS broadcasts).
// ---------------------------------------------------------------------------
__global__ __launch_bounds__(256) void k_offset(const float* __restrict__ x,
                                                const float* __restrict__ wo) {
    __shared__ float ws[CK * 20];   // 46,080 B
    int tid = threadIdx.x;
    for (int s = tid; s < 18 * CC * K2; s += 256) {
        // s is linear over w_offset (j, c, tap)
        int tap = s % 9;
        int t2  = s / 9;
        int c   = t2 % CC;
        int j   = t2 / CC;
        ws[(c * 9 + tap) * 20 + j] = wo[s];
    }
    __syncthreads();

    int pix = blockIdx.x * 256 + tid;     // 0..65535
    int b = pix >> 14;
    int rem = pix & 16383;
    int y = rem >> 7;
    int xx0 = rem & 127;

    float acc[18];
#pragma unroll
    for (int j = 0; j < 18; j++) acc[j] = 0.f;

    const float* xb = x + (size_t)b * CC * HH * WW;
    for (int c = 0; c < CC; c++) {
        const float* xc = xb + (size_t)c * HH * WW;
#pragma unroll
        for (int di = 0; di < 3; di++) {
            int yy = y + di - 1;
            bool yv = ((unsigned)yy < (unsigned)HH);
            const float* xr = xc + yy * WW;
#pragma unroll
            for (int dj = 0; dj < 3; dj++) {
                int xx = xx0 + dj - 1;
                float xv = (yv && (unsigned)xx < (unsigned)WW) ? xr[xx] : 0.f;
                const float* wr = &ws[(c * 9 + di * 3 + dj) * 20];
#pragma unroll
                for (int j = 0; j < 18; j++) acc[j] += xv * wr[j];
            }
        }
    }
    float* op = g_off + (size_t)pix * 18;
#pragma unroll
    for (int j = 0; j < 18; j++) op[j] = acc[j];
}

// ---------------------------------------------------------------------------
// 4) Main: bilinear sample (into smem S) + GEMM (64 o x 64 p, K=576)
//    Block = 64 consecutive pixels (same b, same row y). 256 threads.
//    S layout: S[(kk*64 + c)*SP + p]. wT staged per-k chunk: wd_s[c*64+o].
//    GEMM thread tile: 4 o x 4 p (pg = tid%16, og = tid/16).
// ---------------------------------------------------------------------------
__global__ __launch_bounds__(256) void k_main(float* __restrict__ out) {
    extern __shared__ float sm[];
    float* S    = sm;               // CK*SP = 39168 floats
    float* wd_s = sm + CK * SP;     // 4096 floats

    int tid  = threadIdx.x;
    int lane = tid & 31;
    int wid  = tid >> 5;

    int pix0 = blockIdx.x * TP;
    int b    = pix0 >> 14;
    int rem  = pix0 & 16383;
    int y    = rem >> 7;
    int x0   = rem & 127;           // 0 or 64

    const float* xTb = g_xT + (size_t)b * HH * WW * CC;

    // ---- sampling: one warp per (kk, p) item
    for (int it = wid; it < K2 * TP; it += 8) {
        int kk = it >> 6;           // TP == 64
        int p  = it & 63;
        int ki = kk / 3, kj = kk % 3;
        const float* offp = g_off + (size_t)(pix0 + p) * 18 + kk * 2;
        float dy = offp[0], dx = offp[1];
        float ys = (float)(y - 1 + ki) + dy;
        float xs = (float)(x0 + p - 1 + kj) + dx;
        float y0f = floorf(ys), x0f = floorf(xs);
        float fy = ys - y0f, fx = xs - x0f;
        int iy = (int)y0f, ix = (int)x0f;
        bool vy0 = (iy >= 0) && (iy < HH);
        bool vy1 = (iy + 1 >= 0) && (iy + 1 < HH);
        bool vx0 = (ix >= 0) && (ix < WW);
        bool vx1 = (ix + 1 >= 0) && (ix + 1 < WW);
        long base = ((long)iy * WW + ix) * CC;
        float w00 = (1.f - fy) * (1.f - fx);
        float w01 = (1.f - fy) * fx;
        float w10 = fy * (1.f - fx);
        float w11 = fy * fx;
#pragma unroll
        for (int h = 0; h < 2; h++) {
            int c = lane + 32 * h;
            float v00 = (vy0 && vx0) ? xTb[base + c] : 0.f;
            float v01 = (vy0 && vx1) ? xTb[base + CC + c] : 0.f;
            float v10 = (vy1 && vx0) ? xTb[base + (long)WW * CC + c] : 0.f;
            float v11 = (vy1 && vx1) ? xTb[base + (long)WW * CC + CC + c] : 0.f;
            S[(kk * CC + c) * SP + p] = w00 * v00 + w01 * v01 + w10 * v10 + w11 * v11;
        }
    }

    // ---- GEMM
    int pg = tid & 15;   // p = pg*4 .. +3
    int og = tid >> 4;   // o = og*4 .. +3
    float acc[4][4];
#pragma unroll
    for (int i = 0; i < 4; i++)
#pragma unroll
        for (int j = 0; j < 4; j++) acc[i][j] = 0.f;

    for (int kk = 0; kk < K2; kk++) {
        __syncthreads();  // first iter: sampling done; later: prev chunk consumed
        const float* src = g_wT + kk * CC * COUT;
#pragma unroll
        for (int i2 = tid * 4; i2 < CC * COUT; i2 += 256 * 4) {
            *(float4*)(wd_s + i2) = *(const float4*)(src + i2);
        }
        __syncthreads();
#pragma unroll 4
        for (int c = 0; c < CC; c++) {
            float4 s4 = *(const float4*)&S[(kk * CC + c) * SP + pg * 4];
            float4 w4 = *(const float4*)&wd_s[c * COUT + og * 4];
            acc[0][0] += w4.x * s4.x; acc[0][1] += w4.x * s4.y;
            acc[0][2] += w4.x * s4.z; acc[0][3] += w4.x * s4.w;
            acc[1][0] += w4.y * s4.x; acc[1][1] += w4.y * s4.y;
            acc[1][2] += w4.y * s4.z; acc[1][3] += w4.y * s4.w;
            acc[2][0] += w4.z * s4.x; acc[2][1] += w4.z * s4.y;
            acc[2][2] += w4.z * s4.z; acc[2][3] += w4.z * s4.w;
            acc[3][0] += w4.w * s4.x; acc[3][1] += w4.w * s4.y;
            acc[3][2] += w4.w * s4.z; acc[3][3] += w4.w * s4.w;
        }
    }

    // ---- epilogue: out[b][o][y][x0 + p]
    size_t obase = (size_t)b * COUT * HH * WW + (size_t)y * WW + x0;
#pragma unroll
    for (int oi = 0; oi < 4; oi++) {
        int o = og * 4 + oi;
        float4 v = make_float4(acc[oi][0], acc[oi][1], acc[oi][2], acc[oi][3]);
        *(float4*)(out + obase + (size_t)o * HH * WW + pg * 4) = v;
    }
}

// ---------------------------------------------------------------------------
extern "C" void kernel_launch(void* const* d_in, const int* in_sizes, int n_in,
                              void* d_out, int out_size) {
    const float* x  = (const float*)d_in[0];
    const float* wo = (const float*)d_in[1];
    const float* wd = (const float*)d_in[2];
    float* out = (float*)d_out;

    // dynamic smem for k_main: (576*68 + 64*64) * 4 = 173,056 B
    cudaFuncSetAttribute(k_main, cudaFuncAttributeMaxDynamicSharedMemorySize,
                         (CK * SP + CC * COUT) * (int)sizeof(float));

    dim3 tb(32, 8);
    dim3 tg(HH * WW / 32, CC / 32, BB);
    k_transpose<<<tg, tb>>>(x);

    k_wprep<<<(K2 * CC * COUT + 255) / 256, 256>>>(wd);

    k_offset<<<BB * HH * WW / 256, 256>>>(x, wo);

    k_main<<<BB * HH * WW / TP, 256, (CK * SP + CC * COUT) * (int)sizeof(float)>>>(out);
}

// round 2
// speedup vs baseline: 1.1756x; 1.1756x over previous
#include <cuda_runtime.h>

#define HH 128
#define WW 128
#define CC 64
#define BB 4
#define COUT 64
#define K2 9
#define NPIX (BB * HH * WW)   // 65536
#define SP 68                 // S row pitch (pixels dim), padded
#define TP 64                 // pixels per block in main kernel

// Scratch (device globals; no allocations allowed)
__device__ float g_xT[BB * HH * WW * CC];        // x transposed to (b,y,x,c)
__device__ float g_off[K2 * NPIX * 2];           // offsets, [kk][pixel][{dy,dx}]
__device__ float g_wT[K2 * CC * COUT];           // w_deform as (k,c,o)

// ---------------------------------------------------------------------------
// 1) Transpose x: NCHW -> NHWC
// ---------------------------------------------------------------------------
__global__ void k_transpose(const float* __restrict__ x) {
    __shared__ float tile[32][33];
    int b  = blockIdx.z;
    int c0 = blockIdx.y * 32;
    int p0 = blockIdx.x * 32;
    int tx = threadIdx.x, ty = threadIdx.y;   // (32, 8)
    const float* src = x + (size_t)b * CC * HH * WW;
    float* dst = g_xT + (size_t)b * HH * WW * CC;
#pragma unroll
    for (int i = 0; i < 32; i += 8)
        tile[ty + i][tx] = src[(size_t)(c0 + ty + i) * (HH * WW) + p0 + tx];
    __syncthreads();
#pragma unroll
    for (int i = 0; i < 32; i += 8)
        dst[(size_t)(p0 + ty + i) * CC + c0 + tx] = tile[tx][ty + i];
}

// ---------------------------------------------------------------------------
// 2) Transpose w_deform: (o,c,k) -> (k,c,o)
// ---------------------------------------------------------------------------
__global__ void k_wprep(const float* __restrict__ wd) {
    int i = blockIdx.x * 256 + threadIdx.x;
    if (i < K2 * CC * COUT) {
        int o = i % COUT;
        int t = i / COUT;
        int c = t % CC;
        int k = t / CC;
        g_wT[i] = wd[(size_t)(o * CC + c) * K2 + k];
    }
}

// ---------------------------------------------------------------------------
// 3) Offset conv. One thread per pixel, 18 accumulators.
//    Output layout: g_off[kk*NPIX*2 + pix*2 + comp]  (kk = j>>1, comp = j&1)
// ---------------------------------------------------------------------------
__global__ __launch_bounds__(256) void k_offset(const float* __restrict__ x,
                                                const float* __restrict__ wo) {
    __shared__ float ws[CC * K2 * 20];   // 46,080 B
    int tid = threadIdx.x;
    for (int s = tid; s < 18 * CC * K2; s += 256) {
        int tap = s % 9;
        int t2  = s / 9;
        int c   = t2 % CC;
        int j   = t2 / CC;
        ws[(c * 9 + tap) * 20 + j] = wo[s];
    }
    __syncthreads();

    int pix = blockIdx.x * 256 + tid;
    int b = pix >> 14;
    int rem = pix & 16383;
    int y = rem >> 7;
    int xx0 = rem & 127;

    float acc[18];
#pragma unroll
    for (int j = 0; j < 18; j++) acc[j] = 0.f;

    const float* xb = x + (size_t)b * CC * HH * WW;
    for (int c = 0; c < CC; c++) {
        const float* xc = xb + (size_t)c * HH * WW;
#pragma unroll
        for (int di = 0; di < 3; di++) {
            int yy = y + di - 1;
            bool yv = ((unsigned)yy < (unsigned)HH);
            const float* xr = xc + yy * WW;
#pragma unroll
            for (int dj = 0; dj < 3; dj++) {
                int xx = xx0 + dj - 1;
                float xv = (yv && (unsigned)xx < (unsigned)WW) ? xr[xx] : 0.f;
                const float* wr = &ws[(c * 9 + di * 3 + dj) * 20];
#pragma unroll
                for (int j = 0; j < 18; j++) acc[j] += xv * wr[j];
            }
        }
    }
#pragma unroll
    for (int j = 0; j < 18; j++)
        g_off[(size_t)(j >> 1) * (NPIX * 2) + (size_t)pix * 2 + (j & 1)] = acc[j];
}

// ---------------------------------------------------------------------------
// 4) Main: per-kk pipelined bilinear sample + GEMM.
//    Block = 64 pixels (same b, y). 256 threads. 3 blocks/SM.
//    smem: S[2][64*SP] + W[2][64*64]  = 67,584 B
// ---------------------------------------------------------------------------
__device__ __forceinline__ void sample_chunk(int kk, int pix0, int y, int x0,
                                             const float* __restrict__ xTb,
                                             float* __restrict__ Sb, int tid) {
    int p = tid & 63;
    int q = tid >> 6;   // 0..3, 16 channels each
    int ki = kk / 3, kj = kk % 3;
    float2 o2 = *(const float2*)(g_off + ((size_t)kk * NPIX + pix0 + p) * 2);
    float ys = (float)(y - 1 + ki) + o2.x;
    float xs = (float)(x0 + p - 1 + kj) + o2.y;
    float y0f = floorf(ys), x0f = floorf(xs);
    float fy = ys - y0f, fx = xs - x0f;
    int iy = (int)y0f, ix = (int)x0f;
    bool vy0 = ((unsigned)iy < (unsigned)HH);
    bool vy1 = ((unsigned)(iy + 1) < (unsigned)HH);
    bool vx0 = ((unsigned)ix < (unsigned)WW);
    bool vx1 = ((unsigned)(ix + 1) < (unsigned)WW);
    long base = ((long)iy * WW + ix) * CC + q * 16;
    float w00 = (1.f - fy) * (1.f - fx);
    float w01 = (1.f - fy) * fx;
    float w10 = fy * (1.f - fx);
    float w11 = fy * fx;
    const float4* p00 = (const float4*)(xTb + base);
    const float4* p01 = (const float4*)(xTb + base + CC);
    const float4* p10 = (const float4*)(xTb + base + (long)WW * CC);
    const float4* p11 = (const float4*)(xTb + base + (long)WW * CC + CC);
    float4 z = make_float4(0.f, 0.f, 0.f, 0.f);
#pragma unroll
    for (int j = 0; j < 4; j++) {
        float4 v00 = (vy0 && vx0) ? p00[j] : z;
        float4 v01 = (vy0 && vx1) ? p01[j] : z;
        float4 v10 = (vy1 && vx0) ? p10[j] : z;
        float4 v11 = (vy1 && vx1) ? p11[j] : z;
        float4 r;
        r.x = w00 * v00.x + w01 * v01.x + w10 * v10.x + w11 * v11.x;
        r.y = w00 * v00.y + w01 * v01.y + w10 * v10.y + w11 * v11.y;
        r.z = w00 * v00.z + w01 * v01.z + w10 * v10.z + w11 * v11.z;
        r.w = w00 * v00.w + w01 * v01.w + w10 * v10.w + w11 * v11.w;
        int c = q * 16 + j * 4;
        Sb[(c + 0) * SP + p] = r.x;
        Sb[(c + 1) * SP + p] = r.y;
        Sb[(c + 2) * SP + p] = r.z;
        Sb[(c + 3) * SP + p] = r.w;
    }
}

__device__ __forceinline__ void load_wchunk(int kk, float* __restrict__ Wd, int tid) {
    const float* src = g_wT + kk * CC * COUT;
#pragma unroll
    for (int i = tid * 4; i < CC * COUT; i += 256 * 4)
        *(float4*)(Wd + i) = *(const float4*)(src + i);
}

__global__ __launch_bounds__(256, 3) void k_main(float* __restrict__ out) {
    extern __shared__ float sm[];
    float* S0 = sm;                       // CC*SP
    float* S1 = sm + CC * SP;
    float* W0 = sm + 2 * CC * SP;         // CC*COUT
    float* W1 = W0 + CC * COUT;

    int tid = threadIdx.x;
    int pix0 = blockIdx.x * TP;
    int b    = pix0 >> 14;
    int rem  = pix0 & 16383;
    int y    = rem >> 7;
    int x0   = rem & 127;

    const float* xTb = g_xT + (size_t)b * HH * WW * CC;

    // prologue: stage chunk 0
    sample_chunk(0, pix0, y, x0, xTb, S0, tid);
    load_wchunk(0, W0, tid);

    int pg = tid & 15;   // pixel group: p = pg*4..+3
    int og = tid >> 4;   // out group:   o = og*4..+3
    float acc[4][4];
#pragma unroll
    for (int i = 0; i < 4; i++)
#pragma unroll
        for (int j = 0; j < 4; j++) acc[i][j] = 0.f;

    for (int kk = 0; kk < K2; kk++) {
        __syncthreads();   // chunk kk buffers ready; (kk+1)&1 buffers free
        float* Sc = (kk & 1) ? S1 : S0;
        float* Wc = (kk & 1) ? W1 : W0;
        if (kk < K2 - 1) {
            sample_chunk(kk + 1, pix0, y, x0, xTb, (kk & 1) ? S0 : S1, tid);
            load_wchunk(kk + 1, (kk & 1) ? W0 : W1, tid);
        }
#pragma unroll 8
        for (int c = 0; c < CC; c++) {
            float4 s4 = *(const float4*)&Sc[c * SP + pg * 4];
            float4 w4 = *(const float4*)&Wc[c * COUT + og * 4];
            acc[0][0] += w4.x * s4.x; acc[0][1] += w4.x * s4.y;
            acc[0][2] += w4.x * s4.z; acc[0][3] += w4.x * s4.w;
            acc[1][0] += w4.y * s4.x; acc[1][1] += w4.y * s4.y;
            acc[1][2] += w4.y * s4.z; acc[1][3] += w4.y * s4.w;
            acc[2][0] += w4.z * s4.x; acc[2][1] += w4.z * s4.y;
            acc[2][2] += w4.z * s4.z; acc[2][3] += w4.z * s4.w;
            acc[3][0] += w4.w * s4.x; acc[3][1] += w4.w * s4.y;
            acc[3][2] += w4.w * s4.z; acc[3][3] += w4.w * s4.w;
        }
    }

    // epilogue: out[b][o][y][x0 + p]
    size_t obase = (size_t)b * COUT * HH * WW + (size_t)y * WW + x0;
#pragma unroll
    for (int oi = 0; oi < 4; oi++) {
        int o = og * 4 + oi;
        float4 v = make_float4(acc[oi][0], acc[oi][1], acc[oi][2], acc[oi][3]);
        *(float4*)(out + obase + (size_t)o * HH * WW + pg * 4) = v;
    }
}

// ---------------------------------------------------------------------------
extern "C" void kernel_launch(void* const* d_in, const int* in_sizes, int n_in,
                              void* d_out, int out_size) {
    const float* x  = (const float*)d_in[0];
    const float* wo = (const float*)d_in[1];
    const float* wd = (const float*)d_in[2];
    float* out = (float*)d_out;

    int smem_main = (2 * CC * SP + 2 * CC * COUT) * (int)sizeof(float);  // 67,584
    cudaFuncSetAttribute(k_main, cudaFuncAttributeMaxDynamicSharedMemorySize,
                         smem_main);

    dim3 tb(32, 8);
    dim3 tg(HH * WW / 32, CC / 32, BB);
    k_transpose<<<tg, tb>>>(x);

    k_wprep<<<(K2 * CC * COUT + 255) / 256, 256>>>(wd);

    k_offset<<<BB * HH * WW / 256, 256>>>(x, wo);

    k_main<<<BB * HH * WW / TP, 256, smem_main>>>(out);
}

// round 3
// speedup vs baseline: 1.7588x; 1.4961x over previous
#include <cuda_runtime.h>

#define HH 128
#define WW 128
#define CC 64
#define BB 4
#define COUT 64
#define K2 9
#define NPIX (BB * HH * WW)   // 65536
#define SP 68                 // S row pitch (pixels dim), padded
#define TP 64                 // pixels per block in main kernel

// Scratch (device globals; no allocations allowed)
__device__ float g_xT[BB * HH * WW * CC];        // x transposed to (b,y,x,c)
__device__ float g_off[K2 * NPIX * 2];           // offsets, [kk][pixel][{dy,dx}]
__device__ float g_wT[K2 * CC * COUT];           // w_deform as (k,c,o)

// ---------------------------------------------------------------------------
// 1) Transpose x: NCHW -> NHWC
// ---------------------------------------------------------------------------
__global__ void k_transpose(const float* __restrict__ x) {
    __shared__ float tile[32][33];
    int b  = blockIdx.z;
    int c0 = blockIdx.y * 32;
    int p0 = blockIdx.x * 32;
    int tx = threadIdx.x, ty = threadIdx.y;   // (32, 8)
    const float* src = x + (size_t)b * CC * HH * WW;
    float* dst = g_xT + (size_t)b * HH * WW * CC;
#pragma unroll
    for (int i = 0; i < 32; i += 8)
        tile[ty + i][tx] = src[(size_t)(c0 + ty + i) * (HH * WW) + p0 + tx];
    __syncthreads();
#pragma unroll
    for (int i = 0; i < 32; i += 8)
        dst[(size_t)(p0 + ty + i) * CC + c0 + tx] = tile[tx][ty + i];
}

// ---------------------------------------------------------------------------
// 2) Transpose w_deform: (o,c,k) -> (k,c,o)
// ---------------------------------------------------------------------------
__global__ void k_wprep(const float* __restrict__ wd) {
    int i = blockIdx.x * 256 + threadIdx.x;
    if (i < K2 * CC * COUT) {
        int o = i % COUT;
        int t = i / COUT;
        int c = t % CC;
        int k = t / CC;
        g_wT[i] = wd[(size_t)(o * CC + c) * K2 + k];
    }
}

// ---------------------------------------------------------------------------
// 3) Offset conv. One thread per pixel, 18 accumulators.
// ---------------------------------------------------------------------------
__global__ __launch_bounds__(256) void k_offset(const float* __restrict__ x,
                                                const float* __restrict__ wo) {
    __shared__ float ws[CC * K2 * 20];   // 46,080 B
    int tid = threadIdx.x;
    for (int s = tid; s < 18 * CC * K2; s += 256) {
        int tap = s % 9;
        int t2  = s / 9;
        int c   = t2 % CC;
        int j   = t2 / CC;
        ws[(c * 9 + tap) * 20 + j] = wo[s];
    }
    __syncthreads();

    int pix = blockIdx.x * 256 + tid;
    int b = pix >> 14;
    int rem = pix & 16383;
    int y = rem >> 7;
    int xx0 = rem & 127;

    float acc[18];
#pragma unroll
    for (int j = 0; j < 18; j++) acc[j] = 0.f;

    const float* xb = x + (size_t)b * CC * HH * WW;
    for (int c = 0; c < CC; c++) {
        const float* xc = xb + (size_t)c * HH * WW;
#pragma unroll
        for (int di = 0; di < 3; di++) {
            int yy = y + di - 1;
            bool yv = ((unsigned)yy < (unsigned)HH);
            const float* xr = xc + yy * WW;
#pragma unroll
            for (int dj = 0; dj < 3; dj++) {
                int xx = xx0 + dj - 1;
                float xv = (yv && (unsigned)xx < (unsigned)WW) ? xr[xx] : 0.f;
                const float* wr = &ws[(c * 9 + di * 3 + dj) * 20];
#pragma unroll
                for (int j = 0; j < 18; j++) acc[j] += xv * wr[j];
            }
        }
    }
#pragma unroll
    for (int j = 0; j < 18; j++)
        g_off[(size_t)(j >> 1) * (NPIX * 2) + (size_t)pix * 2 + (j & 1)] = acc[j];
}

// ---------------------------------------------------------------------------
// 4) Main: per-kk pipelined bilinear sample + GEMM.
//    Sampling: half-warp (16 lanes) owns ONE pixel; lanes own channel pairs.
//    Corner gathers are 128B-contiguous per pixel -> ~2 L1 lines per LDG.64
//    (was 32 lines per LDG.128 with lane-per-pixel mapping).
// ---------------------------------------------------------------------------
__device__ __forceinline__ void sample_chunk(int kk, int pix0, int y, int x0,
                                             const float* __restrict__ xTb,
                                             float* __restrict__ Sb, int tid) {
    int l    = tid & 15;    // channel pair group
    int pgrp = tid >> 4;    // 0..15
    int ki = kk / 3, kj = kk % 3;
    float2 z2 = make_float2(0.f, 0.f);
#pragma unroll
    for (int pass = 0; pass < 4; pass++) {
        int p = pass * 16 + pgrp;
        float2 o2 = *(const float2*)(g_off + ((size_t)kk * NPIX + pix0 + p) * 2);
        float ys = (float)(y - 1 + ki) + o2.x;
        float xs = (float)(x0 + p - 1 + kj) + o2.y;
        float y0f = floorf(ys), x0f = floorf(xs);
        float fy = ys - y0f, fx = xs - x0f;
        int iy = (int)y0f, ix = (int)x0f;
        bool vy0 = ((unsigned)iy < (unsigned)HH);
        bool vy1 = ((unsigned)(iy + 1) < (unsigned)HH);
        bool vx0 = ((unsigned)ix < (unsigned)WW);
        bool vx1 = ((unsigned)(ix + 1) < (unsigned)WW);
        float w00 = (1.f - fy) * (1.f - fx);
        float w01 = (1.f - fy) * fx;
        float w10 = fy * (1.f - fx);
        float w11 = fy * fx;
        const float* b0 = xTb + ((long)iy * WW + ix) * CC + 2 * l;
#pragma unroll
        for (int h = 0; h < 2; h++) {
            const float* bh = b0 + 32 * h;
            float2 v00 = (vy0 && vx0) ? *(const float2*)(bh) : z2;
            float2 v01 = (vy0 && vx1) ? *(const float2*)(bh + CC) : z2;
            float2 v10 = (vy1 && vx0) ? *(const float2*)(bh + WW * CC) : z2;
            float2 v11 = (vy1 && vx1) ? *(const float2*)(bh + WW * CC + CC) : z2;
            int c = 2 * l + 32 * h;
            Sb[c * SP + p]       = w00 * v00.x + w01 * v01.x + w10 * v10.x + w11 * v11.x;
            Sb[(c + 1) * SP + p] = w00 * v00.y + w01 * v01.y + w10 * v10.y + w11 * v11.y;
        }
    }
}

__device__ __forceinline__ void load_wchunk(int kk, float* __restrict__ Wd, int tid) {
    const float* src = g_wT + kk * CC * COUT;
#pragma unroll
    for (int i = tid * 4; i < CC * COUT; i += 256 * 4)
        *(float4*)(Wd + i) = *(const float4*)(src + i);
}

__global__ __launch_bounds__(256, 3) void k_main(float* __restrict__ out) {
    extern __shared__ float sm[];
    float* S0 = sm;                       // CC*SP
    float* S1 = sm + CC * SP;
    float* W0 = sm + 2 * CC * SP;         // CC*COUT
    float* W1 = W0 + CC * COUT;

    int tid = threadIdx.x;
    int pix0 = blockIdx.x * TP;
    int b    = pix0 >> 14;
    int rem  = pix0 & 16383;
    int y    = rem >> 7;
    int x0   = rem & 127;

    const float* xTb = g_xT + (size_t)b * HH * WW * CC;

    // prologue: stage chunk 0
    sample_chunk(0, pix0, y, x0, xTb, S0, tid);
    load_wchunk(0, W0, tid);

    int pg = tid & 15;   // pixel group: p = pg*4..+3
    int og = tid >> 4;   // out group:   o = og*4..+3
    float acc[4][4];
#pragma unroll
    for (int i = 0; i < 4; i++)
#pragma unroll
        for (int j = 0; j < 4; j++) acc[i][j] = 0.f;

    for (int kk = 0; kk < K2; kk++) {
        __syncthreads();   // chunk kk buffers ready; other buffers free
        float* Sc = (kk & 1) ? S1 : S0;
        float* Wc = (kk & 1) ? W1 : W0;
        if (kk < K2 - 1) {
            sample_chunk(kk + 1, pix0, y, x0, xTb, (kk & 1) ? S0 : S1, tid);
            load_wchunk(kk + 1, (kk & 1) ? W0 : W1, tid);
        }
#pragma unroll 8
        for (int c = 0; c < CC; c++) {
            float4 s4 = *(const float4*)&Sc[c * SP + pg * 4];
            float4 w4 = *(const float4*)&Wc[c * COUT + og * 4];
            acc[0][0] += w4.x * s4.x; acc[0][1] += w4.x * s4.y;
            acc[0][2] += w4.x * s4.z; acc[0][3] += w4.x * s4.w;
            acc[1][0] += w4.y * s4.x; acc[1][1] += w4.y * s4.y;
            acc[1][2] += w4.y * s4.z; acc[1][3] += w4.y * s4.w;
            acc[2][0] += w4.z * s4.x; acc[2][1] += w4.z * s4.y;
            acc[2][2] += w4.z * s4.z; acc[2][3] += w4.z * s4.w;
            acc[3][0] += w4.w * s4.x; acc[3][1] += w4.w * s4.y;
            acc[3][2] += w4.w * s4.z; acc[3][3] += w4.w * s4.w;
        }
    }

    // epilogue: out[b][o][y][x0 + p]
    size_t obase = (size_t)b * COUT * HH * WW + (size_t)y * WW + x0;
#pragma unroll
    for (int oi = 0; oi < 4; oi++) {
        int o = og * 4 + oi;
        float4 v = make_float4(acc[oi][0], acc[oi][1], acc[oi][2], acc[oi][3]);
        *(float4*)(out + obase + (size_t)o * HH * WW + pg * 4) = v;
    }
}

// ---------------------------------------------------------------------------
extern "C" void kernel_launch(void* const* d_in, const int* in_sizes, int n_in,
                              void* d_out, int out_size) {
    const float* x  = (const float*)d_in[0];
    const float* wo = (const float*)d_in[1];
    const float* wd = (const float*)d_in[2];
    float* out = (float*)d_out;

    int smem_main = (2 * CC * SP + 2 * CC * COUT) * (int)sizeof(float);  // 67,584
    cudaFuncSetAttribute(k_main, cudaFuncAttributeMaxDynamicSharedMemorySize,
                         smem_main);

    dim3 tb(32, 8);
    dim3 tg(HH * WW / 32, CC / 32, BB);
    k_transpose<<<tg, tb>>>(x);

    k_wprep<<<(K2 * CC * COUT + 255) / 256, 256>>>(wd);

    k_offset<<<BB * HH * WW / 256, 256>>>(x, wo);

    k_main<<<BB * HH * WW / TP, 256, smem_main>>>(out);
}

// round 5
// speedup vs baseline: 2.1385x; 1.2159x over previous
#include <cuda_runtime.h>
#include <cstdint>

#define HH 128
#define WW 128
#define CC 64
#define BB 4
#define COUT 64
#define K2 9
#define NPIX (BB * HH * WW)   // 65536
#define SP 132                // S row pitch (pixels dim): mult of 4, 4-way STS ok
#define TP 128                // pixels per block in main kernel (one image row)

// Scratch (device globals; no allocations allowed)
__device__ __align__(16) float g_xT[BB * HH * WW * CC];   // x as (b,y,x,c)
__device__ __align__(16) float g_off[K2 * NPIX * 2];      // [kk][pixel][{dy,dx}]
__device__ __align__(16) float g_wT[K2 * CC * COUT];      // w_deform as (k,c,o)

// ---- packed f32x2 helpers --------------------------------------------------
__device__ __forceinline__ unsigned long long pack2(float v) {
    unsigned long long r;
    asm("mov.b64 %0, {%1, %1};" : "=l"(r) : "f"(v));
    return r;
}
__device__ __forceinline__ void ffma2(unsigned long long& d,
                                      unsigned long long a,
                                      unsigned long long b) {
    asm("fma.rn.f32x2 %0, %1, %2, %0;" : "+l"(d) : "l"(a), "l"(b));
}
__device__ __forceinline__ float2 unpack2(unsigned long long v) {
    float2 f;
    asm("mov.b64 {%0, %1}, %2;" : "=f"(f.x), "=f"(f.y) : "l"(v));
    return f;
}

// ---------------------------------------------------------------------------
// 1) Transpose x: NCHW -> NHWC
// ---------------------------------------------------------------------------
__global__ void k_transpose(const float* __restrict__ x) {
    __shared__ float tile[32][33];
    int b  = blockIdx.z;
    int c0 = blockIdx.y * 32;
    int p0 = blockIdx.x * 32;
    int tx = threadIdx.x, ty = threadIdx.y;   // (32, 8)
    const float* src = x + (size_t)b * CC * HH * WW;
    float* dst = g_xT + (size_t)b * HH * WW * CC;
#pragma unroll
    for (int i = 0; i < 32; i += 8)
        tile[ty + i][tx] = src[(size_t)(c0 + ty + i) * (HH * WW) + p0 + tx];
    __syncthreads();
#pragma unroll
    for (int i = 0; i < 32; i += 8)
        dst[(size_t)(p0 + ty + i) * CC + c0 + tx] = tile[tx][ty + i];
}

// ---------------------------------------------------------------------------
// 2) Transpose w_deform: (o,c,k) -> (k,c,o)
// ---------------------------------------------------------------------------
__global__ void k_wprep(const float* __restrict__ wd) {
    int i = blockIdx.x * 256 + threadIdx.x;
    if (i < K2 * CC * COUT) {
        int o = i % COUT;
        int t = i / COUT;
        int c = t % CC;
        int k = t / CC;
        g_wT[i] = wd[(size_t)(o * CC + c) * K2 + k];
    }
}

// ---------------------------------------------------------------------------
// 3) Offset conv with f32x2: 9 packed (dy,dx) accumulators per pixel.
// ---------------------------------------------------------------------------
__global__ __launch_bounds__(256) void k_offset(const float* __restrict__ x,
                                                const float* __restrict__ wo) {
    __shared__ float ws[CC * K2 * 20];   // rows of 20 floats (80 B, 16B aligned)
    int tid = threadIdx.x;
    for (int s = tid; s < 18 * CC * K2; s += 256) {
        int tap = s % 9;
        int t2  = s / 9;
        int c   = t2 % CC;
        int j   = t2 / CC;
        ws[(c * 9 + tap) * 20 + j] = wo[s];
    }
    __syncthreads();

    int pix = blockIdx.x * 256 + tid;
    int b = pix >> 14;
    int rem = pix & 16383;
    int y = rem >> 7;
    int xx0 = rem & 127;

    unsigned long long acc[9];
#pragma unroll
    for (int j = 0; j < 9; j++) acc[j] = 0ull;

    const float* xb = x + (size_t)b * CC * HH * WW;
    for (int c = 0; c < CC; c++) {
        const float* xc = xb + (size_t)c * HH * WW;
#pragma unroll
        for (int di = 0; di < 3; di++) {
            int yy = y + di - 1;
            bool yv = ((unsigned)yy < (unsigned)HH);
            const float* xr = xc + yy * WW;
#pragma unroll
            for (int dj = 0; dj < 3; dj++) {
                int xx = xx0 + dj - 1;
                float xv = (yv && (unsigned)xx < (unsigned)WW) ? xr[xx] : 0.f;
                unsigned long long xv2 = pack2(xv);
                const unsigned long long* wr =
                    (const unsigned long long*)&ws[(c * 9 + di * 3 + dj) * 20];
#pragma unroll
                for (int j = 0; j < 9; j++) ffma2(acc[j], xv2, wr[j]);
            }
        }
    }
    // acc[kk] = packed (dy, dx) for tap kk
#pragma unroll
    for (int kk = 0; kk < 9; kk++) {
        float2 v = unpack2(acc[kk]);
        *(float2*)(g_off + ((size_t)kk * NPIX + pix) * 2) = v;
    }
}

// ---------------------------------------------------------------------------
// 4) Main: per-kk pipelined bilinear sample + f32x2 GEMM.
//    Block = 128 pixels (one image row). 256 threads, 2 CTAs/SM.
//    Thread GEMM tile: 8 o (4 o-pairs, packed) x 4 p.
// ---------------------------------------------------------------------------
__device__ __forceinline__ void sample_chunk(int kk, int pix0, int y,
                                             const float* __restrict__ xTb,
                                             float* __restrict__ Sb, int tid) {
    int l  = tid & 15;    // channel pair: c = 2l (+32h)
    int hw = tid >> 4;    // 0..15
    int ki = kk / 3, kj = kk % 3;
    float2 z2 = make_float2(0.f, 0.f);
#pragma unroll
    for (int pass = 0; pass < 8; pass++) {
        int p = pass * 16 + hw;
        float2 o2 = *(const float2*)(g_off + ((size_t)kk * NPIX + pix0 + p) * 2);
        float ys = (float)(y - 1 + ki) + o2.x;
        float xs = (float)(p - 1 + kj) + o2.y;
        float y0f = floorf(ys), x0f = floorf(xs);
        float fy = ys - y0f, fx = xs - x0f;
        int iy = (int)y0f, ix = (int)x0f;
        bool vy0 = ((unsigned)iy < (unsigned)HH);
        bool vy1 = ((unsigned)(iy + 1) < (unsigned)HH);
        bool vx0 = ((unsigned)ix < (unsigned)WW);
        bool vx1 = ((unsigned)(ix + 1) < (unsigned)WW);
        float w00 = (1.f - fy) * (1.f - fx);
        float w01 = (1.f - fy) * fx;
        float w10 = fy * (1.f - fx);
        float w11 = fy * fx;
        const float* b0 = xTb + ((long)iy * WW + ix) * CC + 2 * l;
#pragma unroll
        for (int h = 0; h < 2; h++) {
            const float* bh = b0 + 32 * h;
            float2 v00 = (vy0 && vx0) ? *(const float2*)(bh) : z2;
            float2 v01 = (vy0 && vx1) ? *(const float2*)(bh + CC) : z2;
            float2 v10 = (vy1 && vx0) ? *(const float2*)(bh + WW * CC) : z2;
            float2 v11 = (vy1 && vx1) ? *(const float2*)(bh + WW * CC + CC) : z2;
            int c = 2 * l + 32 * h;
            Sb[c * SP + p]       = w00 * v00.x + w01 * v01.x + w10 * v10.x + w11 * v11.x;
            Sb[(c + 1) * SP + p] = w00 * v00.y + w01 * v01.y + w10 * v10.y + w11 * v11.y;
        }
    }
}

__device__ __forceinline__ void load_wchunk(int kk, float* __restrict__ Wd, int tid) {
    const float* src = g_wT + kk * CC * COUT;
#pragma unroll
    for (int i = tid * 4; i < CC * COUT; i += 256 * 4)
        *(float4*)(Wd + i) = *(const float4*)(src + i);
}

__global__ __launch_bounds__(256, 2) void k_main(float* __restrict__ out) {
    extern __shared__ __align__(16) float sm[];
    float* S0 = sm;                        // CC*SP = 8448
    float* S1 = sm + CC * SP;
    float* W0 = sm + 2 * CC * SP;          // CC*COUT = 4096
    float* W1 = W0 + CC * COUT;

    int tid = threadIdx.x;
    int pix0 = blockIdx.x * TP;
    int b    = pix0 >> 14;
    int y    = (pix0 & 16383) >> 7;

    const float* xTb = g_xT + (size_t)b * HH * WW * CC;

    // prologue: stage chunk 0
    sample_chunk(0, pix0, y, xTb, S0, tid);
    load_wchunk(0, W0, tid);

    int pg = tid & 31;   // pixel group: p = pg*4..+3  (128 px)
    int og = tid >> 5;   // out group:   o = og*8..+7  (64 o)
    unsigned long long acc[4][4];   // [o-pair][p], pair = (o even, o odd)
#pragma unroll
    for (int i = 0; i < 4; i++)
#pragma unroll
        for (int j = 0; j < 4; j++) acc[i][j] = 0ull;

    for (int kk = 0; kk < K2; kk++) {
        __syncthreads();   // chunk kk buffers ready; other buffers free
        float* Sc = (kk & 1) ? S1 : S0;
        float* Wc = (kk & 1) ? W1 : W0;
        if (kk < K2 - 1) {
            sample_chunk(kk + 1, pix0, y, xTb, (kk & 1) ? S0 : S1, tid);
            load_wchunk(kk + 1, (kk & 1) ? W0 : W1, tid);
        }
#pragma unroll 4
        for (int c = 0; c < CC; c++) {
            // W row for this thread: 8 consecutive o -> 4 packed pairs (broadcast)
            const ulonglong2* wp = (const ulonglong2*)&Wc[c * COUT + og * 8];
            ulonglong2 wa = wp[0];   // pairs (o0,o1), (o2,o3)
            ulonglong2 wb = wp[1];   // pairs (o4,o5), (o6,o7)
            float4 s4 = *(const float4*)&Sc[c * SP + pg * 4];
            unsigned long long sd[4];
            sd[0] = pack2(s4.x); sd[1] = pack2(s4.y);
            sd[2] = pack2(s4.z); sd[3] = pack2(s4.w);
#pragma unroll
            for (int j = 0; j < 4; j++) {
                ffma2(acc[0][j], wa.x, sd[j]);
                ffma2(acc[1][j], wa.y, sd[j]);
                ffma2(acc[2][j], wb.x, sd[j]);
                ffma2(acc[3][j], wb.y, sd[j]);
            }
        }
    }

    // epilogue: out[b][o][y][pg*4 + p], o = og*8 + 2*op (+1 for .y half)
    size_t obase = (size_t)b * COUT * HH * WW + (size_t)y * WW + pg * 4;
#pragma unroll
    for (int op = 0; op < 4; op++) {
        float2 u0 = unpack2(acc[op][0]);
        float2 u1 = unpack2(acc[op][1]);
        float2 u2 = unpack2(acc[op][2]);
        float2 u3 = unpack2(acc[op][3]);
        int o0 = og * 8 + 2 * op;
        float4 ve = make_float4(u0.x, u1.x, u2.x, u3.x);
        float4 vo = make_float4(u0.y, u1.y, u2.y, u3.y);
        *(float4*)(out + obase + (size_t)o0 * (HH * WW)) = ve;
        *(float4*)(out + obase + (size_t)(o0 + 1) * (HH * WW)) = vo;
    }
}

// ---------------------------------------------------------------------------
extern "C" void kernel_launch(void* const* d_in, const int* in_sizes, int n_in,
                              void* d_out, int out_size) {
    const float* x  = (const float*)d_in[0];
    const float* wo = (const float*)d_in[1];
    const float* wd = (const float*)d_in[2];
    float* out = (float*)d_out;

    int smem_main = (2 * CC * SP + 2 * CC * COUT) * (int)sizeof(float);  // 100,352
    cudaFuncSetAttribute(k_main, cudaFuncAttributeMaxDynamicSharedMemorySize,
                         smem_main);

    dim3 tb(32, 8);
    dim3 tg(HH * WW / 32, CC / 32, BB);
    k_transpose<<<tg, tb>>>(x);

    k_wprep<<<(K2 * CC * COUT + 255) / 256, 256>>>(wd);

    k_offset<<<BB * HH * WW / 256, 256>>>(x, wo);

    k_main<<<BB * HH * WW / TP, 256, smem_main>>>(out);
}

// round 6
// speedup vs baseline: 3.1457x; 1.4710x over previous
#include <cuda_runtime.h>
#include <cuda_bf16.h>
#include <cstdint>

#define HH 128
#define WW 128
#define CC 64
#define BB 4
#define COUT 64
#define K2 9
#define NPIX (BB * HH * WW)   // 65536
#define TP 128                // pixels per block (one image row)
#define PD 132                // epilogue smem pitch (floats)

// Scratch (device globals)
__device__ __align__(16) float g_xT[BB * HH * WW * CC];          // x as (b,y,x,c)
__device__ __align__(16) float g_off[K2 * NPIX * 2];             // [kk][pixel][{dy,dx}]
__device__ __align__(16) unsigned short g_wB[K2][2][64 * 64];    // [kk][hi/lo][swizzled 64x64 bf16]

// ---- f32x2 helpers (k_offset) ----------------------------------------------
__device__ __forceinline__ unsigned long long pack2(float v) {
    unsigned long long r;
    asm("mov.b64 %0, {%1, %1};" : "=l"(r) : "f"(v));
    return r;
}
__device__ __forceinline__ void ffma2(unsigned long long& d,
                                      unsigned long long a,
                                      unsigned long long b) {
    asm("fma.rn.f32x2 %0, %1, %2, %0;" : "+l"(d) : "l"(a), "l"(b));
}
__device__ __forceinline__ float2 unpack2(unsigned long long v) {
    float2 f;
    asm("mov.b64 {%0, %1}, %2;" : "=f"(f.x), "=f"(f.y) : "l"(v));
    return f;
}

// ---- mma helpers ------------------------------------------------------------
__device__ __forceinline__ uint32_t smem_u32(const void* p) {
    uint32_t a;
    asm("{ .reg .u64 t; cvta.to.shared.u64 t, %1; cvt.u32.u64 %0, t; }" : "=r"(a) : "l"(p));
    return a;
}
__device__ __forceinline__ void ldsm4(uint32_t addr, uint32_t* r) {
    asm volatile("ldmatrix.sync.aligned.m8n8.x4.shared.b16 {%0,%1,%2,%3}, [%4];"
                 : "=r"(r[0]), "=r"(r[1]), "=r"(r[2]), "=r"(r[3]) : "r"(addr));
}
__device__ __forceinline__ void ldsm4t(uint32_t addr, uint32_t* r) {
    asm volatile("ldmatrix.sync.aligned.m8n8.x4.trans.shared.b16 {%0,%1,%2,%3}, [%4];"
                 : "=r"(r[0]), "=r"(r[1]), "=r"(r[2]), "=r"(r[3]) : "r"(addr));
}
__device__ __forceinline__ void mma16816(float* d, const uint32_t* a, const uint32_t* b) {
    asm volatile(
        "mma.sync.aligned.m16n8k16.row.col.f32.bf16.bf16.f32 "
        "{%0,%1,%2,%3}, {%4,%5,%6,%7}, {%8,%9}, {%0,%1,%2,%3};"
        : "+f"(d[0]), "+f"(d[1]), "+f"(d[2]), "+f"(d[3])
        : "r"(a[0]), "r"(a[1]), "r"(a[2]), "r"(a[3]), "r"(b[0]), "r"(b[1]));
}

// ---------------------------------------------------------------------------
// 1) Transpose x: NCHW -> NHWC
// ---------------------------------------------------------------------------
__global__ void k_transpose(const float* __restrict__ x) {
    __shared__ float tile[32][33];
    int b  = blockIdx.z;
    int c0 = blockIdx.y * 32;
    int p0 = blockIdx.x * 32;
    int tx = threadIdx.x, ty = threadIdx.y;   // (32, 8)
    const float* src = x + (size_t)b * CC * HH * WW;
    float* dst = g_xT + (size_t)b * HH * WW * CC;
#pragma unroll
    for (int i = 0; i < 32; i += 8)
        tile[ty + i][tx] = src[(size_t)(c0 + ty + i) * (HH * WW) + p0 + tx];
    __syncthreads();
#pragma unroll
    for (int i = 0; i < 32; i += 8)
        dst[(size_t)(p0 + ty + i) * CC + c0 + tx] = tile[tx][ty + i];
}

// ---------------------------------------------------------------------------
// 2) Weight prep: split bf16 hi/lo, layout [kk][plane][k=c rows][n=o], swizzled.
// ---------------------------------------------------------------------------
__global__ void k_wprep(const float* __restrict__ wd) {
    int i = blockIdx.x * 256 + threadIdx.x;
    if (i >= K2 * 64 * 64) return;
    int kk = i >> 12;
    int r  = i & 4095;
    int c  = r >> 6;     // cin (k-dim row)
    int o  = r & 63;     // cout (n-dim col)
    float val = wd[((size_t)o * CC + c) * K2 + kk];
    __nv_bfloat16 h = __float2bfloat16(val);
    __nv_bfloat16 l = __float2bfloat16(val - __bfloat162float(h));
    uint32_t off = (uint32_t)c * 128 + (((uint32_t)o * 2) ^ (((uint32_t)c & 7) << 4));
    g_wB[kk][0][off >> 1] = *(const unsigned short*)&h;
    g_wB[kk][1][off >> 1] = *(const unsigned short*)&l;
}

// ---------------------------------------------------------------------------
// 3) Offset conv with f32x2 (unchanged from round 5)
// ---------------------------------------------------------------------------
__global__ __launch_bounds__(256) void k_offset(const float* __restrict__ x,
                                                const float* __restrict__ wo) {
    __shared__ float ws[CC * K2 * 20];
    int tid = threadIdx.x;
    for (int s = tid; s < 18 * CC * K2; s += 256) {
        int tap = s % 9;
        int t2  = s / 9;
        int c   = t2 % CC;
        int j   = t2 / CC;
        ws[(c * 9 + tap) * 20 + j] = wo[s];
    }
    __syncthreads();

    int pix = blockIdx.x * 256 + tid;
    int b = pix >> 14;
    int rem = pix & 16383;
    int y = rem >> 7;
    int xx0 = rem & 127;

    unsigned long long acc[9];
#pragma unroll
    for (int j = 0; j < 9; j++) acc[j] = 0ull;

    const float* xb = x + (size_t)b * CC * HH * WW;
    for (int c = 0; c < CC; c++) {
        const float* xc = xb + (size_t)c * HH * WW;
#pragma unroll
        for (int di = 0; di < 3; di++) {
            int yy = y + di - 1;
            bool yv = ((unsigned)yy < (unsigned)HH);
            const float* xr = xc + yy * WW;
#pragma unroll
            for (int dj = 0; dj < 3; dj++) {
                int xx = xx0 + dj - 1;
                float xv = (yv && (unsigned)xx < (unsigned)WW) ? xr[xx] : 0.f;
                unsigned long long xv2 = pack2(xv);
                const unsigned long long* wr =
                    (const unsigned long long*)&ws[(c * 9 + di * 3 + dj) * 20];
#pragma unroll
                for (int j = 0; j < 9; j++) ffma2(acc[j], xv2, wr[j]);
            }
        }
    }
#pragma unroll
    for (int kk = 0; kk < 9; kk++) {
        float2 v = unpack2(acc[kk]);
        *(float2*)(g_off + ((size_t)kk * NPIX + pix) * 2) = v;
    }
}

// ---------------------------------------------------------------------------
// 4) Main: bilinear sample -> bf16 hi/lo swizzled smem -> mma.sync (3-term)
// smem bytes: AH0=0 AL0=16384 AH1=32768 AL1=49152 | W0(hi+lo)=65536 W1=81920
// ---------------------------------------------------------------------------
__device__ __forceinline__ void sample_chunk(int kk, int pix0, int y,
                                             const float* __restrict__ xTb,
                                             char* __restrict__ AH,
                                             char* __restrict__ AL, int tid) {
    int l  = tid & 15;    // channel pair: c = 2l (+32h)
    int hw = tid >> 4;    // 0..15
    int ki = kk / 3, kj = kk % 3;
    float2 z2 = make_float2(0.f, 0.f);
#pragma unroll
    for (int pass = 0; pass < 8; pass++) {
        int p = pass * 16 + hw;
        float2 o2 = *(const float2*)(g_off + ((size_t)kk * NPIX + pix0 + p) * 2);
        float ys = (float)(y - 1 + ki) + o2.x;
        float xs = (float)(p - 1 + kj) + o2.y;
        float y0f = floorf(ys), x0f = floorf(xs);
        float fy = ys - y0f, fx = xs - x0f;
        int iy = (int)y0f, ix = (int)x0f;
        bool vy0 = ((unsigned)iy < (unsigned)HH);
        bool vy1 = ((unsigned)(iy + 1) < (unsigned)HH);
        bool vx0 = ((unsigned)ix < (unsigned)WW);
        bool vx1 = ((unsigned)(ix + 1) < (unsigned)WW);
        float w00 = (1.f - fy) * (1.f - fx);
        float w01 = (1.f - fy) * fx;
        float w10 = fy * (1.f - fx);
        float w11 = fy * fx;
        const float* b0 = xTb + ((long)iy * WW + ix) * CC + 2 * l;
        uint32_t rowbase = (uint32_t)p * 128;
        uint32_t xorm = ((uint32_t)p & 7) << 4;
#pragma unroll
        for (int h = 0; h < 2; h++) {
            const float* bh = b0 + 32 * h;
            float2 v00 = (vy0 && vx0) ? *(const float2*)(bh) : z2;
            float2 v01 = (vy0 && vx1) ? *(const float2*)(bh + CC) : z2;
            float2 v10 = (vy1 && vx0) ? *(const float2*)(bh + WW * CC) : z2;
            float2 v11 = (vy1 && vx1) ? *(const float2*)(bh + WW * CC + CC) : z2;
            float rx = w00 * v00.x + w01 * v01.x + w10 * v10.x + w11 * v11.x;
            float ry = w00 * v00.y + w01 * v01.y + w10 * v10.y + w11 * v11.y;
            __nv_bfloat162 h2 = __floats2bfloat162_rn(rx, ry);
            float hx = __bfloat162float(h2.x);
            float hy = __bfloat162float(h2.y);
            __nv_bfloat162 l2 = __floats2bfloat162_rn(rx - hx, ry - hy);
            uint32_t off = rowbase + (((uint32_t)(4 * l + 64 * h)) ^ xorm);
            *(uint32_t*)(AH + off) = *(const uint32_t*)&h2;
            *(uint32_t*)(AL + off) = *(const uint32_t*)&l2;
        }
    }
}

__device__ __forceinline__ void copy_W(int kk, char* __restrict__ Wd, int tid) {
    const float4* src = (const float4*)&g_wB[kk][0][0];   // hi then lo, 16384 B
    float4* dst = (float4*)Wd;
#pragma unroll
    for (int i = tid; i < 1024; i += 256)
        dst[i] = src[i];
}

__global__ __launch_bounds__(256, 2) void k_main(float* __restrict__ out) {
    extern __shared__ __align__(16) char sm[];

    int tid  = threadIdx.x;
    int lane = tid & 31;
    int wid  = tid >> 5;

    int pix0 = blockIdx.x * TP;
    int b    = pix0 >> 14;
    int y    = (pix0 & 16383) >> 7;
    const float* xTb = g_xT + (size_t)b * HH * WW * CC;

    // prologue
    sample_chunk(0, pix0, y, xTb, sm, sm + 16384, tid);
    copy_W(0, sm + 65536, tid);

    // warp GEMM tile: 32 rows (m) x 32 cols (n)
    int m0 = (wid & 3) * 32;
    int wn = wid >> 2;
    // ldmatrix lane geometry
    int rA = (lane & 7) + 8 * ((lane >> 3) & 1);   // row-in-16 for A / k-in-16 for B
    int cg = lane >> 4;                             // 0/1: +8 col tile
    uint32_t xorA0 = ((uint32_t)(m0 + rA) & 7) << 4;   // = (rA&7)<<4
    // B column byte (fixed per nt16): wn*64 + nt16*32 + cg*16, xor with (rA&7)<<4
    uint32_t bcol[2];
#pragma unroll
    for (int nt = 0; nt < 2; nt++)
        bcol[nt] = (((uint32_t)(wn * 64 + nt * 32 + cg * 16)) ^ xorA0);

    float acc[2][4][4];
#pragma unroll
    for (int i = 0; i < 2; i++)
#pragma unroll
        for (int j = 0; j < 4; j++)
#pragma unroll
            for (int q = 0; q < 4; q++) acc[i][j][q] = 0.f;

    for (int kk = 0; kk < K2; kk++) {
        __syncthreads();
        int buf = kk & 1;
        char* Acur = sm + buf * 32768;
        char* Wcur = sm + 65536 + buf * 16384;
        if (kk + 1 < K2) {
            int nb = buf ^ 1;
            sample_chunk(kk + 1, pix0, y, xTb, sm + nb * 32768, sm + nb * 32768 + 16384, tid);
            copy_W(kk + 1, sm + 65536 + nb * 16384, tid);
        }
        uint32_t aHbase = smem_u32(Acur);
        uint32_t aLbase = aHbase + 16384;
        uint32_t wHbase = smem_u32(Wcur);
        uint32_t wLbase = wHbase + 8192;

#pragma unroll
        for (int ks = 0; ks < 4; ks++) {
            int k0 = ks * 16;
            uint32_t a_hi[2][4], a_lo[2][4];
            uint32_t acolb = ((uint32_t)(2 * k0 + cg * 16)) ^ xorA0;
#pragma unroll
            for (int mt = 0; mt < 2; mt++) {
                uint32_t arow = (uint32_t)(m0 + mt * 16 + rA) * 128;
                ldsm4(aHbase + arow + acolb, a_hi[mt]);
                ldsm4(aLbase + arow + acolb, a_lo[mt]);
            }
            uint32_t b_hi[2][4], b_lo[2][4];
            uint32_t brow = (uint32_t)(k0 + rA) * 128;
#pragma unroll
            for (int nt = 0; nt < 2; nt++) {
                ldsm4t(wHbase + brow + bcol[nt], b_hi[nt]);
                ldsm4t(wLbase + brow + bcol[nt], b_lo[nt]);
            }
#pragma unroll
            for (int mt = 0; mt < 2; mt++)
#pragma unroll
                for (int n8 = 0; n8 < 4; n8++) {
                    const uint32_t* bh = &b_hi[n8 >> 1][(n8 & 1) * 2];
                    const uint32_t* bl = &b_lo[n8 >> 1][(n8 & 1) * 2];
                    mma16816(acc[mt][n8], a_hi[mt], bh);
                    mma16816(acc[mt][n8], a_hi[mt], bl);
                    mma16816(acc[mt][n8], a_lo[mt], bh);
                }
        }
    }

    // ---- epilogue: frags -> smem [o][p] (pitch PD) -> coalesced gmem
    __syncthreads();                 // all MMAs done before overwriting smem
    float* Sd = (float*)sm;          // 64*PD floats = 33792 B
#pragma unroll
    for (int mt = 0; mt < 2; mt++)
#pragma unroll
        for (int n8 = 0; n8 < 4; n8++) {
            int pr = m0 + mt * 16 + (lane >> 2);
            int o0 = wn * 32 + n8 * 8 + 2 * (lane & 3);
            float* bse = Sd + o0 * PD;
            bse[pr]          = acc[mt][n8][0];
            bse[PD + pr]     = acc[mt][n8][1];
            bse[pr + 8]      = acc[mt][n8][2];
            bse[PD + pr + 8] = acc[mt][n8][3];
        }
    __syncthreads();

    size_t obase = (size_t)b * COUT * (HH * WW) + (size_t)y * WW;
#pragma unroll
    for (int i = tid; i < 64 * 32; i += 256) {
        int o  = i >> 5;
        int pq = i & 31;
        float4 v = *(const float4*)&Sd[o * PD + pq * 4];
        *(float4*)(out + obase + (size_t)o * (HH * WW) + pq * 4) = v;
    }
}

// ---------------------------------------------------------------------------
extern "C" void kernel_launch(void* const* d_in, const int* in_sizes, int n_in,
                              void* d_out, int out_size) {
    const float* x  = (const float*)d_in[0];
    const float* wo = (const float*)d_in[1];
    const float* wd = (const float*)d_in[2];
    float* out = (float*)d_out;

    int smem_main = 98304;
    cudaFuncSetAttribute(k_main, cudaFuncAttributeMaxDynamicSharedMemorySize,
                         smem_main);

    dim3 tb(32, 8);
    dim3 tg(HH * WW / 32, CC / 32, BB);
    k_transpose<<<tg, tb>>>(x);

    k_wprep<<<(K2 * 64 * 64 + 255) / 256, 256>>>(wd);

    k_offset<<<BB * HH * WW / 256, 256>>>(x, wo);

    k_main<<<BB * HH * WW / TP, 256, smem_main>>>(out);
}

// round 7
// speedup vs baseline: 3.2974x; 1.0483x over previous
#include <cuda_runtime.h>
#include <cuda_bf16.h>
#include <cstdint>

#define HH 128
#define WW 128
#define CC 64
#define BB 4
#define COUT 64
#define K2 9
#define NPIX (BB * HH * WW)   // 65536
#define TP 64                 // pixels per block (half image row)
#define PD 68                 // epilogue smem pitch (floats)

// Scratch (device globals)
__device__ __align__(16) float g_xT[BB * HH * WW * CC];          // x as (b,y,x,c)
__device__ __align__(16) float g_off[K2 * NPIX * 2];             // [kk][pixel][{dy,dx}]
__device__ __align__(16) unsigned short g_wB[K2][2][64 * 64];    // [kk][hi/lo][swizzled 64x64 bf16]

// ---- f32x2 helpers (k_offset) ----------------------------------------------
__device__ __forceinline__ unsigned long long pack2(float v) {
    unsigned long long r;
    asm("mov.b64 %0, {%1, %1};" : "=l"(r) : "f"(v));
    return r;
}
__device__ __forceinline__ void ffma2(unsigned long long& d,
                                      unsigned long long a,
                                      unsigned long long b) {
    asm("fma.rn.f32x2 %0, %1, %2, %0;" : "+l"(d) : "l"(a), "l"(b));
}
__device__ __forceinline__ float2 unpack2(unsigned long long v) {
    float2 f;
    asm("mov.b64 {%0, %1}, %2;" : "=f"(f.x), "=f"(f.y) : "l"(v));
    return f;
}

// ---- mma helpers ------------------------------------------------------------
__device__ __forceinline__ uint32_t smem_u32(const void* p) {
    uint32_t a;
    asm("{ .reg .u64 t; cvta.to.shared.u64 t, %1; cvt.u32.u64 %0, t; }" : "=r"(a) : "l"(p));
    return a;
}
__device__ __forceinline__ void ldsm4(uint32_t addr, uint32_t* r) {
    asm volatile("ldmatrix.sync.aligned.m8n8.x4.shared.b16 {%0,%1,%2,%3}, [%4];"
                 : "=r"(r[0]), "=r"(r[1]), "=r"(r[2]), "=r"(r[3]) : "r"(addr));
}
__device__ __forceinline__ void ldsm4t(uint32_t addr, uint32_t* r) {
    asm volatile("ldmatrix.sync.aligned.m8n8.x4.trans.shared.b16 {%0,%1,%2,%3}, [%4];"
                 : "=r"(r[0]), "=r"(r[1]), "=r"(r[2]), "=r"(r[3]) : "r"(addr));
}
__device__ __forceinline__ void mma16816(float* d, const uint32_t* a, const uint32_t* b) {
    asm volatile(
        "mma.sync.aligned.m16n8k16.row.col.f32.bf16.bf16.f32 "
        "{%0,%1,%2,%3}, {%4,%5,%6,%7}, {%8,%9}, {%0,%1,%2,%3};"
        : "+f"(d[0]), "+f"(d[1]), "+f"(d[2]), "+f"(d[3])
        : "r"(a[0]), "r"(a[1]), "r"(a[2]), "r"(a[3]), "r"(b[0]), "r"(b[1]));
}
__device__ __forceinline__ void cp16(uint32_t dst, const void* src) {
    asm volatile("cp.async.cg.shared.global [%0], [%1], 16;"
                 :: "r"(dst), "l"(src) : "memory");
}
__device__ __forceinline__ void cp_commit() {
    asm volatile("cp.async.commit_group;" ::: "memory");
}
__device__ __forceinline__ void cp_wait0() {
    asm volatile("cp.async.wait_group 0;" ::: "memory");
}

// ---------------------------------------------------------------------------
// 1) Transpose x: NCHW -> NHWC
// ---------------------------------------------------------------------------
__global__ void k_transpose(const float* __restrict__ x) {
    __shared__ float tile[32][33];
    int b  = blockIdx.z;
    int c0 = blockIdx.y * 32;
    int p0 = blockIdx.x * 32;
    int tx = threadIdx.x, ty = threadIdx.y;   // (32, 8)
    const float* src = x + (size_t)b * CC * HH * WW;
    float* dst = g_xT + (size_t)b * HH * WW * CC;
#pragma unroll
    for (int i = 0; i < 32; i += 8)
        tile[ty + i][tx] = src[(size_t)(c0 + ty + i) * (HH * WW) + p0 + tx];
    __syncthreads();
#pragma unroll
    for (int i = 0; i < 32; i += 8)
        dst[(size_t)(p0 + ty + i) * CC + c0 + tx] = tile[tx][ty + i];
}

// ---------------------------------------------------------------------------
// 2) Weight prep: split bf16 hi/lo, layout [kk][plane][k=c rows][n=o], swizzled.
// ---------------------------------------------------------------------------
__global__ void k_wprep(const float* __restrict__ wd) {
    int i = blockIdx.x * 256 + threadIdx.x;
    if (i >= K2 * 64 * 64) return;
    int kk = i >> 12;
    int r  = i & 4095;
    int c  = r >> 6;     // cin (k-dim row)
    int o  = r & 63;     // cout (n-dim col)
    float val = wd[((size_t)o * CC + c) * K2 + kk];
    __nv_bfloat16 h = __float2bfloat16(val);
    __nv_bfloat16 l = __float2bfloat16(val - __bfloat162float(h));
    uint32_t off = (uint32_t)c * 128 + (((uint32_t)o * 2) ^ (((uint32_t)c & 7) << 4));
    g_wB[kk][0][off >> 1] = *(const unsigned short*)&h;
    g_wB[kk][1][off >> 1] = *(const unsigned short*)&l;
}

// ---------------------------------------------------------------------------
// 3) Offset conv with f32x2 (unchanged)
// ---------------------------------------------------------------------------
__global__ __launch_bounds__(256) void k_offset(const float* __restrict__ x,
                                                const float* __restrict__ wo) {
    __shared__ float ws[CC * K2 * 20];
    int tid = threadIdx.x;
    for (int s = tid; s < 18 * CC * K2; s += 256) {
        int tap = s % 9;
        int t2  = s / 9;
        int c   = t2 % CC;
        int j   = t2 / CC;
        ws[(c * 9 + tap) * 20 + j] = wo[s];
    }
    __syncthreads();

    int pix = blockIdx.x * 256 + tid;
    int b = pix >> 14;
    int rem = pix & 16383;
    int y = rem >> 7;
    int xx0 = rem & 127;

    unsigned long long acc[9];
#pragma unroll
    for (int j = 0; j < 9; j++) acc[j] = 0ull;

    const float* xb = x + (size_t)b * CC * HH * WW;
    for (int c = 0; c < CC; c++) {
        const float* xc = xb + (size_t)c * HH * WW;
#pragma unroll
        for (int di = 0; di < 3; di++) {
            int yy = y + di - 1;
            bool yv = ((unsigned)yy < (unsigned)HH);
            const float* xr = xc + yy * WW;
#pragma unroll
            for (int dj = 0; dj < 3; dj++) {
                int xx = xx0 + dj - 1;
                float xv = (yv && (unsigned)xx < (unsigned)WW) ? xr[xx] : 0.f;
                unsigned long long xv2 = pack2(xv);
                const unsigned long long* wr =
                    (const unsigned long long*)&ws[(c * 9 + di * 3 + dj) * 20];
#pragma unroll
                for (int j = 0; j < 9; j++) ffma2(acc[j], xv2, wr[j]);
            }
        }
    }
#pragma unroll
    for (int kk = 0; kk < 9; kk++) {
        float2 v = unpack2(acc[kk]);
        *(float2*)(g_off + ((size_t)kk * NPIX + pix) * 2) = v;
    }
}

// ---------------------------------------------------------------------------
// 4) Main: bilinear sample -> bf16 hi/lo swizzled smem -> mma.sync (3-term)
// smem bytes (64 KB): AH0=0 AL0=8192 AH1=16384 AL1=24576 | W0=32768 W1=49152
// ---------------------------------------------------------------------------
__device__ __forceinline__ void sample_chunk(int kk, int pix0, int y, int x0,
                                             const float* __restrict__ xTb,
                                             char* __restrict__ AH,
                                             char* __restrict__ AL, int tid) {
    int l  = tid & 15;    // channel pair: c = 2l (+32h)
    int hw = tid >> 4;    // 0..15
    int ki = kk / 3, kj = kk % 3;
    float2 z2 = make_float2(0.f, 0.f);
#pragma unroll
    for (int pass = 0; pass < 4; pass++) {
        int p = pass * 16 + hw;
        float2 o2 = *(const float2*)(g_off + ((size_t)kk * NPIX + pix0 + p) * 2);
        float ys = (float)(y - 1 + ki) + o2.x;
        float xs = (float)(x0 + p - 1 + kj) + o2.y;
        float y0f = floorf(ys), x0f = floorf(xs);
        float fy = ys - y0f, fx = xs - x0f;
        int iy = (int)y0f, ix = (int)x0f;
        bool vy0 = ((unsigned)iy < (unsigned)HH);
        bool vy1 = ((unsigned)(iy + 1) < (unsigned)HH);
        bool vx0 = ((unsigned)ix < (unsigned)WW);
        bool vx1 = ((unsigned)(ix + 1) < (unsigned)WW);
        float w00 = (1.f - fy) * (1.f - fx);
        float w01 = (1.f - fy) * fx;
        float w10 = fy * (1.f - fx);
        float w11 = fy * fx;
        const float* b0 = xTb + ((long)iy * WW + ix) * CC + 2 * l;
        uint32_t rowbase = (uint32_t)p * 128;
        uint32_t xorm = ((uint32_t)p & 7) << 4;
#pragma unroll
        for (int h = 0; h < 2; h++) {
            const float* bh = b0 + 32 * h;
            float2 v00 = (vy0 && vx0) ? *(const float2*)(bh) : z2;
            float2 v01 = (vy0 && vx1) ? *(const float2*)(bh + CC) : z2;
            float2 v10 = (vy1 && vx0) ? *(const float2*)(bh + WW * CC) : z2;
            float2 v11 = (vy1 && vx1) ? *(const float2*)(bh + WW * CC + CC) : z2;
            float rx = w00 * v00.x + w01 * v01.x + w10 * v10.x + w11 * v11.x;
            float ry = w00 * v00.y + w01 * v01.y + w10 * v10.y + w11 * v11.y;
            __nv_bfloat162 h2 = __floats2bfloat162_rn(rx, ry);
            float hx = __bfloat162float(h2.x);
            float hy = __bfloat162float(h2.y);
            __nv_bfloat162 l2 = __floats2bfloat162_rn(rx - hx, ry - hy);
            uint32_t off = rowbase + (((uint32_t)(4 * l + 64 * h)) ^ xorm);
            *(uint32_t*)(AH + off) = *(const uint32_t*)&h2;
            *(uint32_t*)(AL + off) = *(const uint32_t*)&l2;
        }
    }
}

__device__ __forceinline__ void copy_W_async(int kk, uint32_t Wd, int tid) {
    const char* src = (const char*)&g_wB[kk][0][0];   // hi then lo, 16384 B
#pragma unroll
    for (int i = 0; i < 4; i++) {
        int off = (tid + i * 256) * 16;
        cp16(Wd + off, src + off);
    }
}

__global__ __launch_bounds__(256, 3) void k_main(float* __restrict__ out) {
    extern __shared__ __align__(16) char sm[];

    int tid  = threadIdx.x;
    int lane = tid & 31;
    int wid  = tid >> 5;

    int pix0 = blockIdx.x * TP;
    int b    = pix0 >> 14;
    int y    = (pix0 & 16383) >> 7;
    int x0   = pix0 & 127;             // 0 or 64
    const float* xTb = g_xT + (size_t)b * HH * WW * CC;

    uint32_t sbase = smem_u32(sm);

    // prologue
    copy_W_async(0, sbase + 32768, tid);
    cp_commit();
    sample_chunk(0, pix0, y, x0, xTb, sm, sm + 8192, tid);

    // warp GEMM tile: 16 rows (m) x 32 cols (n);  M=64, N=64
    int m0 = (wid & 3) * 16;
    int wn = wid >> 2;
    int rA = (lane & 7) + 8 * ((lane >> 3) & 1);
    int cg = lane >> 4;
    uint32_t xorA0 = ((uint32_t)rA & 7) << 4;
    uint32_t bcol[2];
#pragma unroll
    for (int nt = 0; nt < 2; nt++)
        bcol[nt] = (((uint32_t)(wn * 64 + nt * 32 + cg * 16)) ^ xorA0);

    float acc[4][4];
#pragma unroll
    for (int j = 0; j < 4; j++)
#pragma unroll
        for (int q = 0; q < 4; q++) acc[j][q] = 0.f;

    for (int kk = 0; kk < K2; kk++) {
        cp_wait0();
        __syncthreads();
        int buf = kk & 1;
        uint32_t aHbase = sbase + buf * 16384;
        uint32_t aLbase = aHbase + 8192;
        uint32_t wHbase = sbase + 32768 + buf * 16384;
        uint32_t wLbase = wHbase + 8192;
        if (kk + 1 < K2) {
            int nb = buf ^ 1;
            copy_W_async(kk + 1, sbase + 32768 + nb * 16384, tid);
            cp_commit();
            sample_chunk(kk + 1, pix0, y, x0, xTb,
                         sm + nb * 16384, sm + nb * 16384 + 8192, tid);
        }

#pragma unroll
        for (int ks = 0; ks < 4; ks++) {
            int k0 = ks * 16;
            uint32_t a_hi[4], a_lo[4];
            uint32_t acolb = ((uint32_t)(2 * k0 + cg * 16)) ^ xorA0;
            uint32_t arow = (uint32_t)(m0 + rA) * 128;
            ldsm4(aHbase + arow + acolb, a_hi);
            ldsm4(aLbase + arow + acolb, a_lo);
            uint32_t b_hi[2][4], b_lo[2][4];
            uint32_t brow = (uint32_t)(k0 + rA) * 128;
#pragma unroll
            for (int nt = 0; nt < 2; nt++) {
                ldsm4t(wHbase + brow + bcol[nt], b_hi[nt]);
                ldsm4t(wLbase + brow + bcol[nt], b_lo[nt]);
            }
#pragma unroll
            for (int n8 = 0; n8 < 4; n8++) {
                const uint32_t* bh = &b_hi[n8 >> 1][(n8 & 1) * 2];
                const uint32_t* bl = &b_lo[n8 >> 1][(n8 & 1) * 2];
                mma16816(acc[n8], a_hi, bh);
                mma16816(acc[n8], a_hi, bl);
                mma16816(acc[n8], a_lo, bh);
            }
        }
    }

    // ---- epilogue: frags -> smem [o][p] (pitch PD) -> coalesced gmem
    __syncthreads();
    float* Sd = (float*)sm;          // 64*PD floats = 17408 B
#pragma unroll
    for (int n8 = 0; n8 < 4; n8++) {
        int pr = m0 + (lane >> 2);
        int o0 = wn * 32 + n8 * 8 + 2 * (lane & 3);
        float* bse = Sd + o0 * PD;
        bse[pr]          = acc[n8][0];
        bse[PD + pr]     = acc[n8][1];
        bse[pr + 8]      = acc[n8][2];
        bse[PD + pr + 8] = acc[n8][3];
    }
    __syncthreads();

    size_t obase = (size_t)b * COUT * (HH * WW) + (size_t)y * WW + x0;
#pragma unroll
    for (int i = tid; i < 64 * 16; i += 256) {
        int o  = i >> 4;
        int pq = i & 15;
        float4 v = *(const float4*)&Sd[o * PD + pq * 4];
        *(float4*)(out + obase + (size_t)o * (HH * WW) + pq * 4) = v;
    }
}

// ---------------------------------------------------------------------------
extern "C" void kernel_launch(void* const* d_in, const int* in_sizes, int n_in,
                              void* d_out, int out_size) {
    const float* x  = (const float*)d_in[0];
    const float* wo = (const float*)d_in[1];
    const float* wd = (const float*)d_in[2];
    float* out = (float*)d_out;

    int smem_main = 65536;
    cudaFuncSetAttribute(k_main, cudaFuncAttributeMaxDynamicSharedMemorySize,
                         smem_main);

    dim3 tb(32, 8);
    dim3 tg(HH * WW / 32, CC / 32, BB);
    k_transpose<<<tg, tb>>>(x);

    k_wprep<<<(K2 * 64 * 64 + 255) / 256, 256>>>(wd);

    k_offset<<<BB * HH * WW / 256, 256>>>(x, wo);

    k_main<<<BB * HH * WW / TP, 256, smem_main>>>(out);
}

// round 8
// speedup vs baseline: 3.4877x; 1.0577x over previous
#include <cuda_runtime.h>
#include <cuda_bf16.h>
#include <cstdint>

#define HH 128
#define WW 128
#define CC 64
#define BB 4
#define COUT 64
#define K2 9
#define NPIX (BB * HH * WW)   // 65536
#define TP 64                 // pixels per block
#define PD 68                 // epilogue smem pitch (floats)

// Scratch (device globals)
__device__ __align__(16) float g_xT[BB * HH * WW * CC];          // x as (b,y,x,c)
__device__ __align__(16) float g_off[K2 * NPIX * 2];             // [kk][pixel][{dy,dx}]
__device__ __align__(16) unsigned short g_wB[K2][2][64 * 64];    // deform W: [kk][hi/lo] swizzled 64x64
__device__ __align__(16) unsigned short g_wO[K2][2][64 * 32];    // offset W: [kk][hi/lo] swizzled 64x32

// ---- mma helpers ------------------------------------------------------------
__device__ __forceinline__ uint32_t smem_u32(const void* p) {
    uint32_t a;
    asm("{ .reg .u64 t; cvta.to.shared.u64 t, %1; cvt.u32.u64 %0, t; }" : "=r"(a) : "l"(p));
    return a;
}
__device__ __forceinline__ void ldsm4(uint32_t addr, uint32_t* r) {
    asm volatile("ldmatrix.sync.aligned.m8n8.x4.shared.b16 {%0,%1,%2,%3}, [%4];"
                 : "=r"(r[0]), "=r"(r[1]), "=r"(r[2]), "=r"(r[3]) : "r"(addr));
}
__device__ __forceinline__ void ldsm4t(uint32_t addr, uint32_t* r) {
    asm volatile("ldmatrix.sync.aligned.m8n8.x4.trans.shared.b16 {%0,%1,%2,%3}, [%4];"
                 : "=r"(r[0]), "=r"(r[1]), "=r"(r[2]), "=r"(r[3]) : "r"(addr));
}
__device__ __forceinline__ void mma16816(float* d, const uint32_t* a, const uint32_t* b) {
    asm volatile(
        "mma.sync.aligned.m16n8k16.row.col.f32.bf16.bf16.f32 "
        "{%0,%1,%2,%3}, {%4,%5,%6,%7}, {%8,%9}, {%0,%1,%2,%3};"
        : "+f"(d[0]), "+f"(d[1]), "+f"(d[2]), "+f"(d[3])
        : "r"(a[0]), "r"(a[1]), "r"(a[2]), "r"(a[3]), "r"(b[0]), "r"(b[1]));
}
__device__ __forceinline__ void cp16(uint32_t dst, const void* src) {
    asm volatile("cp.async.cg.shared.global [%0], [%1], 16;"
                 :: "r"(dst), "l"(src) : "memory");
}
__device__ __forceinline__ void cp_commit() {
    asm volatile("cp.async.commit_group;" ::: "memory");
}
__device__ __forceinline__ void cp_wait0() {
    asm volatile("cp.async.wait_group 0;" ::: "memory");
}

// ---------------------------------------------------------------------------
// 1) Transpose x: NCHW -> NHWC
// ---------------------------------------------------------------------------
__global__ void k_transpose(const float* __restrict__ x) {
    __shared__ float tile[32][33];
    int b  = blockIdx.z;
    int c0 = blockIdx.y * 32;
    int p0 = blockIdx.x * 32;
    int tx = threadIdx.x, ty = threadIdx.y;   // (32, 8)
    const float* src = x + (size_t)b * CC * HH * WW;
    float* dst = g_xT + (size_t)b * HH * WW * CC;
#pragma unroll
    for (int i = 0; i < 32; i += 8)
        tile[ty + i][tx] = src[(size_t)(c0 + ty + i) * (HH * WW) + p0 + tx];
    __syncthreads();
#pragma unroll
    for (int i = 0; i < 32; i += 8)
        dst[(size_t)(p0 + ty + i) * CC + c0 + tx] = tile[tx][ty + i];
}

// ---------------------------------------------------------------------------
// 2a) Deform-weight prep: bf16 hi/lo, [kk][plane][c rows(128B)][o], swizzled
// ---------------------------------------------------------------------------
__global__ void k_wprep(const float* __restrict__ wd) {
    int i = blockIdx.x * 256 + threadIdx.x;
    if (i >= K2 * 64 * 64) return;
    int kk = i >> 12;
    int r  = i & 4095;
    int c  = r >> 6;
    int o  = r & 63;
    float val = wd[((size_t)o * CC + c) * K2 + kk];
    __nv_bfloat16 h = __float2bfloat16(val);
    __nv_bfloat16 l = __float2bfloat16(val - __bfloat162float(h));
    uint32_t off = (uint32_t)c * 128 + (((uint32_t)o * 2) ^ (((uint32_t)c & 7) << 4));
    g_wB[kk][0][off >> 1] = *(const unsigned short*)&h;
    g_wB[kk][1][off >> 1] = *(const unsigned short*)&l;
}

// 2b) Offset-weight prep: bf16 hi/lo, [kk][plane][c rows(64B)][n(32, pad 18)]
__global__ void k_woprep(const float* __restrict__ wo) {
    int i = blockIdx.x * 256 + threadIdx.x;
    if (i >= K2 * 64 * 32) return;
    int n  = i & 31;
    int c  = (i >> 5) & 63;
    int kk = i >> 11;
    float val = (n < 18) ? wo[((size_t)n * CC + c) * K2 + kk] : 0.f;
    __nv_bfloat16 h = __float2bfloat16(val);
    __nv_bfloat16 l = __float2bfloat16(val - __bfloat162float(h));
    uint32_t off = (uint32_t)c * 64 + (((uint32_t)n * 2) ^ (((uint32_t)c & 3) << 4));
    g_wO[kk][0][off >> 1] = *(const unsigned short*)&h;
    g_wO[kk][1][off >> 1] = *(const unsigned short*)&l;
}

// ---------------------------------------------------------------------------
// 3) Offset conv via mma.sync (3-term): D[64 px][32 n] over K=576
// smem (48KB): AH0=0 AL0=8192 AH1=16384 AL1=24576 | W0=32768 W1=40960
// ---------------------------------------------------------------------------
__device__ __forceinline__ void stage_x(int kk, int pix0, int y, int x0,
                                        const float* __restrict__ xTb,
                                        char* __restrict__ AH,
                                        char* __restrict__ AL, int tid) {
    int l  = tid & 15;
    int hw = tid >> 4;
    int ki = kk / 3, kj = kk % 3;
    int yy = y - 1 + ki;
    bool vy = ((unsigned)yy < (unsigned)HH);
    float2 z2 = make_float2(0.f, 0.f);
#pragma unroll
    for (int s = 0; s < 4; s++) {
        int p  = s * 16 + hw;
        int xx = x0 + p - 1 + kj;
        bool v = vy && ((unsigned)xx < (unsigned)WW);
        const float* b0 = xTb + ((long)yy * WW + xx) * CC + 2 * l;
        uint32_t rowbase = (uint32_t)p * 128;
        uint32_t xorm = ((uint32_t)p & 7) << 4;
#pragma unroll
        for (int h = 0; h < 2; h++) {
            float2 vv = v ? *(const float2*)(b0 + 32 * h) : z2;
            __nv_bfloat162 h2 = __floats2bfloat162_rn(vv.x, vv.y);
            float hx = __bfloat162float(h2.x);
            float hy = __bfloat162float(h2.y);
            __nv_bfloat162 l2 = __floats2bfloat162_rn(vv.x - hx, vv.y - hy);
            uint32_t off = rowbase + (((uint32_t)(4 * l + 64 * h)) ^ xorm);
            *(uint32_t*)(AH + off) = *(const uint32_t*)&h2;
            *(uint32_t*)(AL + off) = *(const uint32_t*)&l2;
        }
    }
}

__global__ __launch_bounds__(256, 3) void k_off2() {
    extern __shared__ __align__(16) char sm[];
    int tid  = threadIdx.x;
    int lane = tid & 31;
    int wid  = tid >> 5;

    int pix0 = blockIdx.x * TP;
    int b    = pix0 >> 14;
    int y    = (pix0 & 16383) >> 7;
    int x0   = pix0 & 127;
    const float* xTb = g_xT + (size_t)b * HH * WW * CC;

    uint32_t sbase = smem_u32(sm);

    // prologue
    {
        const char* src = (const char*)&g_wO[0][0][0];
#pragma unroll
        for (int i = 0; i < 2; i++) {
            int off = (tid + i * 256) * 16;
            cp16(sbase + 32768 + off, src + off);
        }
        cp_commit();
    }
    stage_x(0, pix0, y, x0, xTb, sm, sm + 8192, tid);

    int m0 = (wid & 3) * 16;
    int n0 = (wid >> 2) * 16;
    int rA = (lane & 7) + 8 * ((lane >> 3) & 1);
    int cg = lane >> 4;
    uint32_t xorA0 = ((uint32_t)rA & 7) << 4;
    uint32_t bcol = (((uint32_t)(n0 * 2 + cg * 16)) ^ (((uint32_t)rA & 3) << 4));

    float acc[2][4];
#pragma unroll
    for (int j = 0; j < 2; j++)
#pragma unroll
        for (int q = 0; q < 4; q++) acc[j][q] = 0.f;

    for (int kk = 0; kk < K2; kk++) {
        cp_wait0();
        __syncthreads();
        int buf = kk & 1;
        uint32_t aHbase = sbase + buf * 16384;
        uint32_t aLbase = aHbase + 8192;
        uint32_t wHbase = sbase + 32768 + buf * 8192;
        uint32_t wLbase = wHbase + 4096;
        if (kk + 1 < K2) {
            int nb = buf ^ 1;
            const char* src = (const char*)&g_wO[kk + 1][0][0];
#pragma unroll
            for (int i = 0; i < 2; i++) {
                int off = (tid + i * 256) * 16;
                cp16(sbase + 32768 + nb * 8192 + off, src + off);
            }
            cp_commit();
            stage_x(kk + 1, pix0, y, x0, xTb, sm + nb * 16384, sm + nb * 16384 + 8192, tid);
        }
#pragma unroll
        for (int ks = 0; ks < 4; ks++) {
            int k0 = ks * 16;
            uint32_t a_hi[4], a_lo[4];
            uint32_t acolb = ((uint32_t)(2 * k0 + cg * 16)) ^ xorA0;
            uint32_t arow = (uint32_t)(m0 + rA) * 128;
            ldsm4(aHbase + arow + acolb, a_hi);
            ldsm4(aLbase + arow + acolb, a_lo);
            uint32_t b_hi[4], b_lo[4];
            uint32_t brow = (uint32_t)(k0 + rA) * 64;
            ldsm4t(wHbase + brow + bcol, b_hi);
            ldsm4t(wLbase + brow + bcol, b_lo);
#pragma unroll
            for (int n8 = 0; n8 < 2; n8++) {
                const uint32_t* bh = &b_hi[n8 * 2];
                const uint32_t* bl = &b_lo[n8 * 2];
                mma16816(acc[n8], a_hi, bh);
                mma16816(acc[n8], a_hi, bl);
                mma16816(acc[n8], a_lo, bh);
            }
        }
    }

    // epilogue: frags -> Sd[n][p] -> g_off[kk][pix][2]
    __syncthreads();
    float* Sd = (float*)sm;   // 32*PD floats
#pragma unroll
    for (int n8 = 0; n8 < 2; n8++) {
        int pr = m0 + (lane >> 2);
        int nn = n0 + n8 * 8 + 2 * (lane & 3);
        float* bse = Sd + nn * PD;
        bse[pr]          = acc[n8][0];
        bse[PD + pr]     = acc[n8][1];
        bse[pr + 8]      = acc[n8][2];
        bse[PD + pr + 8] = acc[n8][3];
    }
    __syncthreads();
#pragma unroll
    for (int i = tid; i < K2 * TP; i += 256) {
        int kk = i >> 6;
        int p  = i & 63;
        float2 v = make_float2(Sd[(2 * kk) * PD + p], Sd[(2 * kk + 1) * PD + p]);
        *(float2*)(g_off + ((size_t)kk * NPIX + pix0 + p) * 2) = v;
    }
}

// ---------------------------------------------------------------------------
// 4) Main: pipelined sample + mma.sync (3-term)
// smem (64KB): AH0=0 AL0=8192 AH1=16384 AL1=24576 | W0=32768 W1=49152
// ---------------------------------------------------------------------------
__device__ __forceinline__ void sample_chunk(int kk, int pix0, int y, int x0,
                                             const float* __restrict__ xTb,
                                             char* __restrict__ AH,
                                             char* __restrict__ AL, int tid) {
    int l  = tid & 15;
    int hw = tid >> 4;
    int ki = kk / 3, kj = kk % 3;
    float2 z2 = make_float2(0.f, 0.f);
#pragma unroll
    for (int pass = 0; pass < 4; pass++) {
        int p = pass * 16 + hw;
        float2 o2 = *(const float2*)(g_off + ((size_t)kk * NPIX + pix0 + p) * 2);
        float ys = (float)(y - 1 + ki) + o2.x;
        float xs = (float)(x0 + p - 1 + kj) + o2.y;
        float y0f = floorf(ys), x0f = floorf(xs);
        float fy = ys - y0f, fx = xs - x0f;
        int iy = (int)y0f, ix = (int)x0f;
        bool vy0 = ((unsigned)iy < (unsigned)HH);
        bool vy1 = ((unsigned)(iy + 1) < (unsigned)HH);
        bool vx0 = ((unsigned)ix < (unsigned)WW);
        bool vx1 = ((unsigned)(ix + 1) < (unsigned)WW);
        float w00 = (1.f - fy) * (1.f - fx);
        float w01 = (1.f - fy) * fx;
        float w10 = fy * (1.f - fx);
        float w11 = fy * fx;
        const float* b0 = xTb + ((long)iy * WW + ix) * CC + 2 * l;
        uint32_t rowbase = (uint32_t)p * 128;
        uint32_t xorm = ((uint32_t)p & 7) << 4;
#pragma unroll
        for (int h = 0; h < 2; h++) {
            const float* bh = b0 + 32 * h;
            float2 v00 = (vy0 && vx0) ? *(const float2*)(bh) : z2;
            float2 v01 = (vy0 && vx1) ? *(const float2*)(bh + CC) : z2;
            float2 v10 = (vy1 && vx0) ? *(const float2*)(bh + WW * CC) : z2;
            float2 v11 = (vy1 && vx1) ? *(const float2*)(bh + WW * CC + CC) : z2;
            float rx = w00 * v00.x + w01 * v01.x + w10 * v10.x + w11 * v11.x;
            float ry = w00 * v00.y + w01 * v01.y + w10 * v10.y + w11 * v11.y;
            __nv_bfloat162 h2 = __floats2bfloat162_rn(rx, ry);
            float hx = __bfloat162float(h2.x);
            float hy = __bfloat162float(h2.y);
            __nv_bfloat162 l2 = __floats2bfloat162_rn(rx - hx, ry - hy);
            uint32_t off = rowbase + (((uint32_t)(4 * l + 64 * h)) ^ xorm);
            *(uint32_t*)(AH + off) = *(const uint32_t*)&h2;
            *(uint32_t*)(AL + off) = *(const uint32_t*)&l2;
        }
    }
}

__device__ __forceinline__ void copy_W_async(int kk, uint32_t Wd, int tid) {
    const char* src = (const char*)&g_wB[kk][0][0];
#pragma unroll
    for (int i = 0; i < 4; i++) {
        int off = (tid + i * 256) * 16;
        cp16(Wd + off, src + off);
    }
}

__global__ __launch_bounds__(256, 3) void k_main(float* __restrict__ out) {
    extern __shared__ __align__(16) char sm[];

    int tid  = threadIdx.x;
    int lane = tid & 31;
    int wid  = tid >> 5;

    int pix0 = blockIdx.x * TP;
    int b    = pix0 >> 14;
    int y    = (pix0 & 16383) >> 7;
    int x0   = pix0 & 127;
    const float* xTb = g_xT + (size_t)b * HH * WW * CC;

    uint32_t sbase = smem_u32(sm);

    // prologue
    copy_W_async(0, sbase + 32768, tid);
    cp_commit();
    sample_chunk(0, pix0, y, x0, xTb, sm, sm + 8192, tid);

    int m0 = (wid & 3) * 16;
    int wn = wid >> 2;
    int rA = (lane & 7) + 8 * ((lane >> 3) & 1);
    int cg = lane >> 4;
    uint32_t xorA0 = ((uint32_t)rA & 7) << 4;
    uint32_t bcol[2];
#pragma unroll
    for (int nt = 0; nt < 2; nt++)
        bcol[nt] = (((uint32_t)(wn * 64 + nt * 32 + cg * 16)) ^ xorA0);

    int l  = tid & 15;    // sampler mapping
    int hw = tid >> 4;

    float acc[4][4];
#pragma unroll
    for (int j = 0; j < 4; j++)
#pragma unroll
        for (int q = 0; q < 4; q++) acc[j][q] = 0.f;

    for (int kk = 0; kk < K2; kk++) {
        cp_wait0();
        __syncthreads();
        int buf = kk & 1;
        uint32_t aHbase = sbase + buf * 16384;
        uint32_t aLbase = aHbase + 8192;
        uint32_t wHbase = sbase + 32768 + buf * 16384;
        uint32_t wLbase = wHbase + 8192;

        bool pre = (kk + 1 < K2);
        int nb = buf ^ 1;
        char* AHn = sm + nb * 16384;
        char* ALn = AHn + 8192;

        int ki = 0, kj = 0;
        float2 offs2[4];
        if (pre) {
            copy_W_async(kk + 1, sbase + 32768 + nb * 16384, tid);
            cp_commit();
            ki = (kk + 1) / 3;
            kj = (kk + 1) % 3;
#pragma unroll
            for (int s = 0; s < 4; s++)
                offs2[s] = *(const float2*)(g_off +
                    ((size_t)(kk + 1) * NPIX + pix0 + s * 16 + hw) * 2);
        }

        float2 z2 = make_float2(0.f, 0.f);
#pragma unroll
        for (int s = 0; s < 4; s++) {
            // --- issue gather LDGs for pass s of chunk kk+1 ---
            float2 c00a, c01a, c10a, c11a, c00b, c01b, c10b, c11b;
            float fy = 0.f, fx = 0.f;
            if (pre) {
                int p = s * 16 + hw;
                float ys = (float)(y - 1 + ki) + offs2[s].x;
                float xs = (float)(x0 + p - 1 + kj) + offs2[s].y;
                float y0f = floorf(ys), x0f = floorf(xs);
                fy = ys - y0f; fx = xs - x0f;
                int iy = (int)y0f, ix = (int)x0f;
                bool vy0 = ((unsigned)iy < (unsigned)HH);
                bool vy1 = ((unsigned)(iy + 1) < (unsigned)HH);
                bool vx0 = ((unsigned)ix < (unsigned)WW);
                bool vx1 = ((unsigned)(ix + 1) < (unsigned)WW);
                const float* b0 = xTb + ((long)iy * WW + ix) * CC + 2 * l;
                c00a = (vy0 && vx0) ? *(const float2*)(b0) : z2;
                c01a = (vy0 && vx1) ? *(const float2*)(b0 + CC) : z2;
                c10a = (vy1 && vx0) ? *(const float2*)(b0 + WW * CC) : z2;
                c11a = (vy1 && vx1) ? *(const float2*)(b0 + WW * CC + CC) : z2;
                const float* b1 = b0 + 32;
                c00b = (vy0 && vx0) ? *(const float2*)(b1) : z2;
                c01b = (vy0 && vx1) ? *(const float2*)(b1 + CC) : z2;
                c10b = (vy1 && vx0) ? *(const float2*)(b1 + WW * CC) : z2;
                c11b = (vy1 && vx1) ? *(const float2*)(b1 + WW * CC + CC) : z2;
            }

            // --- MMA step s on chunk kk ---
            {
                int k0 = s * 16;
                uint32_t a_hi[4], a_lo[4];
                uint32_t acolb = ((uint32_t)(2 * k0 + cg * 16)) ^ xorA0;
                uint32_t arow = (uint32_t)(m0 + rA) * 128;
                ldsm4(aHbase + arow + acolb, a_hi);
                ldsm4(aLbase + arow + acolb, a_lo);
                uint32_t b_hi[2][4], b_lo[2][4];
                uint32_t brow = (uint32_t)(k0 + rA) * 128;
#pragma unroll
                for (int nt = 0; nt < 2; nt++) {
                    ldsm4t(wHbase + brow + bcol[nt], b_hi[nt]);
                    ldsm4t(wLbase + brow + bcol[nt], b_lo[nt]);
                }
#pragma unroll
                for (int n8 = 0; n8 < 4; n8++) {
                    const uint32_t* bh = &b_hi[n8 >> 1][(n8 & 1) * 2];
                    const uint32_t* bl = &b_lo[n8 >> 1][(n8 & 1) * 2];
                    mma16816(acc[n8], a_hi, bh);
                    mma16816(acc[n8], a_hi, bl);
                    mma16816(acc[n8], a_lo, bh);
                }
            }

            // --- interp + STS pass s to next buffers ---
            if (pre) {
                int p = s * 16 + hw;
                float w00 = (1.f - fy) * (1.f - fx);
                float w01 = (1.f - fy) * fx;
                float w10 = fy * (1.f - fx);
                float w11 = fy * fx;
                uint32_t rowbase = (uint32_t)p * 128;
                uint32_t xorm = ((uint32_t)p & 7) << 4;
                {
                    float rx = w00 * c00a.x + w01 * c01a.x + w10 * c10a.x + w11 * c11a.x;
                    float ry = w00 * c00a.y + w01 * c01a.y + w10 * c10a.y + w11 * c11a.y;
                    __nv_bfloat162 h2 = __floats2bfloat162_rn(rx, ry);
                    float hx = __bfloat162float(h2.x);
                    float hy = __bfloat162float(h2.y);
                    __nv_bfloat162 l2 = __floats2bfloat162_rn(rx - hx, ry - hy);
                    uint32_t off = rowbase + (((uint32_t)(4 * l)) ^ xorm);
                    *(uint32_t*)(AHn + off) = *(const uint32_t*)&h2;
                    *(uint32_t*)(ALn + off) = *(const uint32_t*)&l2;
                }
                {
                    float rx = w00 * c00b.x + w01 * c01b.x + w10 * c10b.x + w11 * c11b.x;
                    float ry = w00 * c00b.y + w01 * c01b.y + w10 * c10b.y + w11 * c11b.y;
                    __nv_bfloat162 h2 = __floats2bfloat162_rn(rx, ry);
                    float hx = __bfloat162float(h2.x);
                    float hy = __bfloat162float(h2.y);
                    __nv_bfloat162 l2 = __floats2bfloat162_rn(rx - hx, ry - hy);
                    uint32_t off = rowbase + (((uint32_t)(4 * l + 64)) ^ xorm);
                    *(uint32_t*)(AHn + off) = *(const uint32_t*)&h2;
                    *(uint32_t*)(ALn + off) = *(const uint32_t*)&l2;
                }
            }
        }
    }

    // ---- epilogue ----
    __syncthreads();
    float* Sd = (float*)sm;
#pragma unroll
    for (int n8 = 0; n8 < 4; n8++) {
        int pr = m0 + (lane >> 2);
        int o0 = wn * 32 + n8 * 8 + 2 * (lane & 3);
        float* bse = Sd + o0 * PD;
        bse[pr]          = acc[n8][0];
        bse[PD + pr]     = acc[n8][1];
        bse[pr + 8]      = acc[n8][2];
        bse[PD + pr + 8] = acc[n8][3];
    }
    __syncthreads();

    size_t obase = (size_t)b * COUT * (HH * WW) + (size_t)y * WW + x0;
#pragma unroll
    for (int i = tid; i < 64 * 16; i += 256) {
        int o  = i >> 4;
        int pq = i & 15;
        float4 v = *(const float4*)&Sd[o * PD + pq * 4];
        *(float4*)(out + obase + (size_t)o * (HH * WW) + pq * 4) = v;
    }
}

// ---------------------------------------------------------------------------
extern "C" void kernel_launch(void* const* d_in, const int* in_sizes, int n_in,
                              void* d_out, int out_size) {
    const float* x  = (const float*)d_in[0];
    const float* wo = (const float*)d_in[1];
    const float* wd = (const float*)d_in[2];
    float* out = (float*)d_out;

    cudaFuncSetAttribute(k_main, cudaFuncAttributeMaxDynamicSharedMemorySize, 65536);
    cudaFuncSetAttribute(k_off2, cudaFuncAttributeMaxDynamicSharedMemorySize, 49152);

    dim3 tb(32, 8);
    dim3 tg(HH * WW / 32, CC / 32, BB);
    k_transpose<<<tg, tb>>>(x);

    k_wprep<<<(K2 * 64 * 64 + 255) / 256, 256>>>(wd);
    k_woprep<<<(K2 * 64 * 32 + 255) / 256, 256>>>(wo);

    k_off2<<<NPIX / TP, 256, 49152>>>();

    k_main<<<NPIX / TP, 256, 65536>>>(out);
}

// round 9
// speedup vs baseline: 3.6695x; 1.0521x over previous
#include <cuda_runtime.h>
#include <cuda_bf16.h>
#include <cstdint>

#define HH 128
#define WW 128
#define CC 64
#define BB 4
#define COUT 64
#define K2 9
#define NPIX (BB * HH * WW)   // 65536
#define TP 64                 // pixels per block
#define PD 68                 // epilogue smem pitch (floats)

// Scratch (device globals)
__device__ __align__(16) float g_xT[BB * HH * WW * CC];          // x as (b,y,x,c)
__device__ __align__(16) float g_off[K2 * NPIX * 2];             // [kk][pixel][{dy,dx}]
__device__ __align__(16) unsigned short g_wB[K2][2][64 * 64];    // deform W: [kk][hi/lo] swizzled 64x64
__device__ __align__(16) unsigned short g_wO[K2][2][64 * 32];    // offset W: [kk][hi/lo] swizzled 64x32

// ---- mma helpers ------------------------------------------------------------
__device__ __forceinline__ uint32_t smem_u32(const void* p) {
    uint32_t a;
    asm("{ .reg .u64 t; cvta.to.shared.u64 t, %1; cvt.u32.u64 %0, t; }" : "=r"(a) : "l"(p));
    return a;
}
__device__ __forceinline__ void ldsm4(uint32_t addr, uint32_t* r) {
    asm volatile("ldmatrix.sync.aligned.m8n8.x4.shared.b16 {%0,%1,%2,%3}, [%4];"
                 : "=r"(r[0]), "=r"(r[1]), "=r"(r[2]), "=r"(r[3]) : "r"(addr));
}
__device__ __forceinline__ void ldsm4t(uint32_t addr, uint32_t* r) {
    asm volatile("ldmatrix.sync.aligned.m8n8.x4.trans.shared.b16 {%0,%1,%2,%3}, [%4];"
                 : "=r"(r[0]), "=r"(r[1]), "=r"(r[2]), "=r"(r[3]) : "r"(addr));
}
__device__ __forceinline__ void mma16816(float* d, const uint32_t* a, const uint32_t* b) {
    asm volatile(
        "mma.sync.aligned.m16n8k16.row.col.f32.bf16.bf16.f32 "
        "{%0,%1,%2,%3}, {%4,%5,%6,%7}, {%8,%9}, {%0,%1,%2,%3};"
        : "+f"(d[0]), "+f"(d[1]), "+f"(d[2]), "+f"(d[3])
        : "r"(a[0]), "r"(a[1]), "r"(a[2]), "r"(a[3]), "r"(b[0]), "r"(b[1]));
}
__device__ __forceinline__ void cp16(uint32_t dst, const void* src) {
    asm volatile("cp.async.cg.shared.global [%0], [%1], 16;"
                 :: "r"(dst), "l"(src) : "memory");
}
__device__ __forceinline__ void cp_commit() {
    asm volatile("cp.async.commit_group;" ::: "memory");
}
__device__ __forceinline__ void cp_wait0() {
    asm volatile("cp.async.wait_group 0;" ::: "memory");
}

// ---------------------------------------------------------------------------
// 1) Transpose x: NCHW -> NHWC
// ---------------------------------------------------------------------------
__global__ void k_transpose(const float* __restrict__ x) {
    __shared__ float tile[32][33];
    int b  = blockIdx.z;
    int c0 = blockIdx.y * 32;
    int p0 = blockIdx.x * 32;
    int tx = threadIdx.x, ty = threadIdx.y;   // (32, 8)
    const float* src = x + (size_t)b * CC * HH * WW;
    float* dst = g_xT + (size_t)b * HH * WW * CC;
#pragma unroll
    for (int i = 0; i < 32; i += 8)
        tile[ty + i][tx] = src[(size_t)(c0 + ty + i) * (HH * WW) + p0 + tx];
    __syncthreads();
#pragma unroll
    for (int i = 0; i < 32; i += 8)
        dst[(size_t)(p0 + ty + i) * CC + c0 + tx] = tile[tx][ty + i];
}

// ---------------------------------------------------------------------------
// 2a) Deform-weight prep: bf16 hi/lo, [kk][plane][c rows(128B)][o], swizzled
// ---------------------------------------------------------------------------
__global__ void k_wprep(const float* __restrict__ wd) {
    int i = blockIdx.x * 256 + threadIdx.x;
    if (i >= K2 * 64 * 64) return;
    int kk = i >> 12;
    int r  = i & 4095;
    int c  = r >> 6;
    int o  = r & 63;
    float val = wd[((size_t)o * CC + c) * K2 + kk];
    __nv_bfloat16 h = __float2bfloat16(val);
    __nv_bfloat16 l = __float2bfloat16(val - __bfloat162float(h));
    uint32_t off = (uint32_t)c * 128 + (((uint32_t)o * 2) ^ (((uint32_t)c & 7) << 4));
    g_wB[kk][0][off >> 1] = *(const unsigned short*)&h;
    g_wB[kk][1][off >> 1] = *(const unsigned short*)&l;
}

// 2b) Offset-weight prep: bf16 hi/lo, [kk][plane][c rows(64B)][n(32, pad 18)]
__global__ void k_woprep(const float* __restrict__ wo) {
    int i = blockIdx.x * 256 + threadIdx.x;
    if (i >= K2 * 64 * 32) return;
    int n  = i & 31;
    int c  = (i >> 5) & 63;
    int kk = i >> 11;
    float val = (n < 18) ? wo[((size_t)n * CC + c) * K2 + kk] : 0.f;
    __nv_bfloat16 h = __float2bfloat16(val);
    __nv_bfloat16 l = __float2bfloat16(val - __bfloat162float(h));
    uint32_t off = (uint32_t)c * 64 + (((uint32_t)n * 2) ^ (((uint32_t)c & 3) << 4));
    g_wO[kk][0][off >> 1] = *(const unsigned short*)&h;
    g_wO[kk][1][off >> 1] = *(const unsigned short*)&l;
}

// ---------------------------------------------------------------------------
// 3) Offset conv via mma.sync, stage-once shifted-view A.
// A staged once: 3 y-rows x 68(66 used) x-rows x 64ch, bf16, hi/lo planes.
//   physical row = yrow*68 + j, j = pixel + kj (halo: j=p+kj, x = x0-1+j... )
// smem: AH=0 (26112), AL=26112 (26112), W0=52224+0, W1=52224+8192  => 68608 B
// ---------------------------------------------------------------------------
#define APLANE 26112          // 3*68*128
#define WOFF   52224

__global__ __launch_bounds__(256, 3) void k_off2() {
    extern __shared__ __align__(16) char sm[];
    int tid  = threadIdx.x;
    int lane = tid & 31;
    int wid  = tid >> 5;

    int pix0 = blockIdx.x * TP;
    int b    = pix0 >> 14;
    int y    = (pix0 & 16383) >> 7;
    int x0   = pix0 & 127;
    const float* xTb = g_xT + (size_t)b * HH * WW * CC;

    uint32_t sbase = smem_u32(sm);

    // W chunk 0 prefetch
    {
        const char* src = (const char*)&g_wO[0][0][0];
#pragma unroll
        for (int i = 0; i < 2; i++) {
            int off = (tid + i * 256) * 16;
            cp16(sbase + WOFF + off, src + off);
        }
        cp_commit();
    }

    // ---- stage A once: items = (yrow i, xrow j 0..65, quarter q 0..3)
    {
        float4 z4 = make_float4(0.f, 0.f, 0.f, 0.f);
        for (int it = tid; it < 3 * 66 * 4; it += 256) {
            int i = it / 264;
            int r = it - i * 264;
            int j = r >> 2;
            int q = r & 3;
            int yy = y - 1 + i;
            int xx = x0 - 1 + j;
            bool v = ((unsigned)yy < (unsigned)HH) && ((unsigned)xx < (unsigned)WW);
            const float4* src = (const float4*)(xTb + ((long)yy * WW + xx) * CC + q * 16);
            uint32_t hi[4], lo[4];
#pragma unroll
            for (int u = 0; u < 2; u++) {
                float4 f0 = v ? src[2 * u] : z4;
                float4 f1 = v ? src[2 * u + 1] : z4;
                __nv_bfloat162 ha = __floats2bfloat162_rn(f0.x, f0.y);
                __nv_bfloat162 hb = __floats2bfloat162_rn(f0.z, f0.w);
                __nv_bfloat162 hc = __floats2bfloat162_rn(f1.x, f1.y);
                __nv_bfloat162 hd = __floats2bfloat162_rn(f1.z, f1.w);
                __nv_bfloat162 la = __floats2bfloat162_rn(f0.x - __bfloat162float(ha.x), f0.y - __bfloat162float(ha.y));
                __nv_bfloat162 lb = __floats2bfloat162_rn(f0.z - __bfloat162float(hb.x), f0.w - __bfloat162float(hb.y));
                __nv_bfloat162 lc = __floats2bfloat162_rn(f1.x - __bfloat162float(hc.x), f1.y - __bfloat162float(hc.y));
                __nv_bfloat162 ld = __floats2bfloat162_rn(f1.z - __bfloat162float(hd.x), f1.w - __bfloat162float(hd.y));
                hi[0] = *(uint32_t*)&ha; hi[1] = *(uint32_t*)&hb;
                hi[2] = *(uint32_t*)&hc; hi[3] = *(uint32_t*)&hd;
                lo[0] = *(uint32_t*)&la; lo[1] = *(uint32_t*)&lb;
                lo[2] = *(uint32_t*)&lc; lo[3] = *(uint32_t*)&ld;
                uint32_t row = (uint32_t)(i * 68 + j);
                uint32_t addr = row * 128 + (((uint32_t)(q * 32 + u * 16)) ^ ((row & 7) << 4));
                *(uint4*)(sm + addr) = *(uint4*)hi;
                *(uint4*)(sm + APLANE + addr) = *(uint4*)lo;
            }
        }
    }
    __syncthreads();

    int m0 = (wid & 3) * 16;
    int n0 = (wid >> 2) * 16;
    int rA = (lane & 7) + 8 * ((lane >> 3) & 1);
    int cg = lane >> 4;
    uint32_t bcol = (((uint32_t)(n0 * 2 + cg * 16)) ^ (((uint32_t)rA & 3) << 4));

    float acc[2][4];
#pragma unroll
    for (int j = 0; j < 2; j++)
#pragma unroll
        for (int q = 0; q < 4; q++) acc[j][q] = 0.f;

    for (int kk = 0; kk < K2; kk++) {
        cp_wait0();
        __syncthreads();
        int buf = kk & 1;
        uint32_t wHbase = sbase + WOFF + buf * 8192;
        uint32_t wLbase = wHbase + 4096;
        if (kk + 1 < K2) {
            int nb = buf ^ 1;
            const char* src = (const char*)&g_wO[kk + 1][0][0];
#pragma unroll
            for (int i = 0; i < 2; i++) {
                int off = (tid + i * 256) * 16;
                cp16(sbase + WOFF + nb * 8192 + off, src + off);
            }
            cp_commit();
        }
        int ki = kk / 3, kj = kk % 3;
        uint32_t prow = (uint32_t)(ki * 68 + m0 + rA + kj);
        uint32_t arowb = prow * 128;
        uint32_t xorA = (prow & 7) << 4;
#pragma unroll
        for (int ks = 0; ks < 4; ks++) {
            int k0 = ks * 16;
            uint32_t a_hi[4], a_lo[4];
            uint32_t acolb = ((uint32_t)(2 * k0 + cg * 16)) ^ xorA;
            ldsm4(sbase + arowb + acolb, a_hi);
            ldsm4(sbase + APLANE + arowb + acolb, a_lo);
            uint32_t b_hi[4], b_lo[4];
            uint32_t brow = (uint32_t)(k0 + rA) * 64;
            ldsm4t(wHbase + brow + bcol, b_hi);
            ldsm4t(wLbase + brow + bcol, b_lo);
#pragma unroll
            for (int n8 = 0; n8 < 2; n8++) {
                const uint32_t* bh = &b_hi[n8 * 2];
                const uint32_t* bl = &b_lo[n8 * 2];
                mma16816(acc[n8], a_hi, bh);
                mma16816(acc[n8], a_hi, bl);
                mma16816(acc[n8], a_lo, bh);
            }
        }
    }

    // epilogue: frags -> Sd[n][p] -> g_off[kk][pix][2]
    __syncthreads();
    float* Sd = (float*)sm;   // 32*PD floats, overlaps A (done)
#pragma unroll
    for (int n8 = 0; n8 < 2; n8++) {
        int pr = m0 + (lane >> 2);
        int nn = n0 + n8 * 8 + 2 * (lane & 3);
        float* bse = Sd + nn * PD;
        bse[pr]          = acc[n8][0];
        bse[PD + pr]     = acc[n8][1];
        bse[pr + 8]      = acc[n8][2];
        bse[PD + pr + 8] = acc[n8][3];
    }
    __syncthreads();
#pragma unroll
    for (int i = tid; i < K2 * TP; i += 256) {
        int kk = i >> 6;
        int p  = i & 63;
        float2 v = make_float2(Sd[(2 * kk) * PD + p], Sd[(2 * kk + 1) * PD + p]);
        *(float2*)(g_off + ((size_t)kk * NPIX + pix0 + p) * 2) = v;
    }
}

// ---------------------------------------------------------------------------
// 4) Main: pipelined sample + mma.sync (3-term)  (unchanged from round 8)
// smem (64KB): AH0=0 AL0=8192 AH1=16384 AL1=24576 | W0=32768 W1=49152
// ---------------------------------------------------------------------------
__device__ __forceinline__ void sample_chunk(int kk, int pix0, int y, int x0,
                                             const float* __restrict__ xTb,
                                             char* __restrict__ AH,
                                             char* __restrict__ AL, int tid) {
    int l  = tid & 15;
    int hw = tid >> 4;
    int ki = kk / 3, kj = kk % 3;
    float2 z2 = make_float2(0.f, 0.f);
#pragma unroll
    for (int pass = 0; pass < 4; pass++) {
        int p = pass * 16 + hw;
        float2 o2 = *(const float2*)(g_off + ((size_t)kk * NPIX + pix0 + p) * 2);
        float ys = (float)(y - 1 + ki) + o2.x;
        float xs = (float)(x0 + p - 1 + kj) + o2.y;
        float y0f = floorf(ys), x0f = floorf(xs);
        float fy = ys - y0f, fx = xs - x0f;
        int iy = (int)y0f, ix = (int)x0f;
        bool vy0 = ((unsigned)iy < (unsigned)HH);
        bool vy1 = ((unsigned)(iy + 1) < (unsigned)HH);
        bool vx0 = ((unsigned)ix < (unsigned)WW);
        bool vx1 = ((unsigned)(ix + 1) < (unsigned)WW);
        float w00 = (1.f - fy) * (1.f - fx);
        float w01 = (1.f - fy) * fx;
        float w10 = fy * (1.f - fx);
        float w11 = fy * fx;
        const float* b0 = xTb + ((long)iy * WW + ix) * CC + 2 * l;
        uint32_t rowbase = (uint32_t)p * 128;
        uint32_t xorm = ((uint32_t)p & 7) << 4;
#pragma unroll
        for (int h = 0; h < 2; h++) {
            const float* bh = b0 + 32 * h;
            float2 v00 = (vy0 && vx0) ? *(const float2*)(bh) : z2;
            float2 v01 = (vy0 && vx1) ? *(const float2*)(bh + CC) : z2;
            float2 v10 = (vy1 && vx0) ? *(const float2*)(bh + WW * CC) : z2;
            float2 v11 = (vy1 && vx1) ? *(const float2*)(bh + WW * CC + CC) : z2;
            float rx = w00 * v00.x + w01 * v01.x + w10 * v10.x + w11 * v11.x;
            float ry = w00 * v00.y + w01 * v01.y + w10 * v10.y + w11 * v11.y;
            __nv_bfloat162 h2 = __floats2bfloat162_rn(rx, ry);
            float hx = __bfloat162float(h2.x);
            float hy = __bfloat162float(h2.y);
            __nv_bfloat162 l2 = __floats2bfloat162_rn(rx - hx, ry - hy);
            uint32_t off = rowbase + (((uint32_t)(4 * l + 64 * h)) ^ xorm);
            *(uint32_t*)(AH + off) = *(const uint32_t*)&h2;
            *(uint32_t*)(AL + off) = *(const uint32_t*)&l2;
        }
    }
}

__device__ __forceinline__ void copy_W_async(int kk, uint32_t Wd, int tid) {
    const char* src = (const char*)&g_wB[kk][0][0];
#pragma unroll
    for (int i = 0; i < 4; i++) {
        int off = (tid + i * 256) * 16;
        cp16(Wd + off, src + off);
    }
}

__global__ __launch_bounds__(256, 3) void k_main(float* __restrict__ out) {
    extern __shared__ __align__(16) char sm[];

    int tid  = threadIdx.x;
    int lane = tid & 31;
    int wid  = tid >> 5;

    int pix0 = blockIdx.x * TP;
    int b    = pix0 >> 14;
    int y    = (pix0 & 16383) >> 7;
    int x0   = pix0 & 127;
    const float* xTb = g_xT + (size_t)b * HH * WW * CC;

    uint32_t sbase = smem_u32(sm);

    // prologue
    copy_W_async(0, sbase + 32768, tid);
    cp_commit();
    sample_chunk(0, pix0, y, x0, xTb, sm, sm + 8192, tid);

    int m0 = (wid & 3) * 16;
    int wn = wid >> 2;
    int rA = (lane & 7) + 8 * ((lane >> 3) & 1);
    int cg = lane >> 4;
    uint32_t xorA0 = ((uint32_t)rA & 7) << 4;
    uint32_t bcol[2];
#pragma unroll
    for (int nt = 0; nt < 2; nt++)
        bcol[nt] = (((uint32_t)(wn * 64 + nt * 32 + cg * 16)) ^ xorA0);

    int l  = tid & 15;    // sampler mapping
    int hw = tid >> 4;

    float acc[4][4];
#pragma unroll
    for (int j = 0; j < 4; j++)
#pragma unroll
        for (int q = 0; q < 4; q++) acc[j][q] = 0.f;

    for (int kk = 0; kk < K2; kk++) {
        cp_wait0();
        __syncthreads();
        int buf = kk & 1;
        uint32_t aHbase = sbase + buf * 16384;
        uint32_t aLbase = aHbase + 8192;
        uint32_t wHbase = sbase + 32768 + buf * 16384;
        uint32_t wLbase = wHbase + 8192;

        bool pre = (kk + 1 < K2);
        int nb = buf ^ 1;
        char* AHn = sm + nb * 16384;
        char* ALn = AHn + 8192;

        int ki = 0, kj = 0;
        float2 offs2[4];
        if (pre) {
            copy_W_async(kk + 1, sbase + 32768 + nb * 16384, tid);
            cp_commit();
            ki = (kk + 1) / 3;
            kj = (kk + 1) % 3;
#pragma unroll
            for (int s = 0; s < 4; s++)
                offs2[s] = *(const float2*)(g_off +
                    ((size_t)(kk + 1) * NPIX + pix0 + s * 16 + hw) * 2);
        }

        float2 z2 = make_float2(0.f, 0.f);
#pragma unroll
        for (int s = 0; s < 4; s++) {
            // --- issue gather LDGs for pass s of chunk kk+1 ---
            float2 c00a, c01a, c10a, c11a, c00b, c01b, c10b, c11b;
            float fy = 0.f, fx = 0.f;
            if (pre) {
                int p = s * 16 + hw;
                float ys = (float)(y - 1 + ki) + offs2[s].x;
                float xs = (float)(x0 + p - 1 + kj) + offs2[s].y;
                float y0f = floorf(ys), x0f = floorf(xs);
                fy = ys - y0f; fx = xs - x0f;
                int iy = (int)y0f, ix = (int)x0f;
                bool vy0 = ((unsigned)iy < (unsigned)HH);
                bool vy1 = ((unsigned)(iy + 1) < (unsigned)HH);
                bool vx0 = ((unsigned)ix < (unsigned)WW);
                bool vx1 = ((unsigned)(ix + 1) < (unsigned)WW);
                const float* b0 = xTb + ((long)iy * WW + ix) * CC + 2 * l;
                c00a = (vy0 && vx0) ? *(const float2*)(b0) : z2;
                c01a = (vy0 && vx1) ? *(const float2*)(b0 + CC) : z2;
                c10a = (vy1 && vx0) ? *(const float2*)(b0 + WW * CC) : z2;
                c11a = (vy1 && vx1) ? *(const float2*)(b0 + WW * CC + CC) : z2;
                const float* b1 = b0 + 32;
                c00b = (vy0 && vx0) ? *(const float2*)(b1) : z2;
                c01b = (vy0 && vx1) ? *(const float2*)(b1 + CC) : z2;
                c10b = (vy1 && vx0) ? *(const float2*)(b1 + WW * CC) : z2;
                c11b = (vy1 && vx1) ? *(const float2*)(b1 + WW * CC + CC) : z2;
            }

            // --- MMA step s on chunk kk ---
            {
                int k0 = s * 16;
                uint32_t a_hi[4], a_lo[4];
                uint32_t acolb = ((uint32_t)(2 * k0 + cg * 16)) ^ xorA0;
                uint32_t arow = (uint32_t)(m0 + rA) * 128;
                ldsm4(aHbase + arow + acolb, a_hi);
                ldsm4(aLbase + arow + acolb, a_lo);
                uint32_t b_hi[2][4], b_lo[2][4];
                uint32_t brow = (uint32_t)(k0 + rA) * 128;
#pragma unroll
                for (int nt = 0; nt < 2; nt++) {
                    ldsm4t(wHbase + brow + bcol[nt], b_hi[nt]);
                    ldsm4t(wLbase + brow + bcol[nt], b_lo[nt]);
                }
#pragma unroll
                for (int n8 = 0; n8 < 4; n8++) {
                    const uint32_t* bh = &b_hi[n8 >> 1][(n8 & 1) * 2];
                    const uint32_t* bl = &b_lo[n8 >> 1][(n8 & 1) * 2];
                    mma16816(acc[n8], a_hi, bh);
                    mma16816(acc[n8], a_hi, bl);
                    mma16816(acc[n8], a_lo, bh);
                }
            }

            // --- interp + STS pass s to next buffers ---
            if (pre) {
                int p = s * 16 + hw;
                float w00 = (1.f - fy) * (1.f - fx);
                float w01 = (1.f - fy) * fx;
                float w10 = fy * (1.f - fx);
                float w11 = fy * fx;
                uint32_t rowbase = (uint32_t)p * 128;
                uint32_t xorm = ((uint32_t)p & 7) << 4;
                {
                    float rx = w00 * c00a.x + w01 * c01a.x + w10 * c10a.x + w11 * c11a.x;
                    float ry = w00 * c00a.y + w01 * c01a.y + w10 * c10a.y + w11 * c11a.y;
                    __nv_bfloat162 h2 = __floats2bfloat162_rn(rx, ry);
                    float hx = __bfloat162float(h2.x);
                    float hy = __bfloat162float(h2.y);
                    __nv_bfloat162 l2 = __floats2bfloat162_rn(rx - hx, ry - hy);
                    uint32_t off = rowbase + (((uint32_t)(4 * l)) ^ xorm);
                    *(uint32_t*)(AHn + off) = *(const uint32_t*)&h2;
                    *(uint32_t*)(ALn + off) = *(const uint32_t*)&l2;
                }
                {
                    float rx = w00 * c00b.x + w01 * c01b.x + w10 * c10b.x + w11 * c11b.x;
                    float ry = w00 * c00b.y + w01 * c01b.y + w10 * c10b.y + w11 * c11b.y;
                    __nv_bfloat162 h2 = __floats2bfloat162_rn(rx, ry);
                    float hx = __bfloat162float(h2.x);
                    float hy = __bfloat162float(h2.y);
                    __nv_bfloat162 l2 = __floats2bfloat162_rn(rx - hx, ry - hy);
                    uint32_t off = rowbase + (((uint32_t)(4 * l + 64)) ^ xorm);
                    *(uint32_t*)(AHn + off) = *(const uint32_t*)&h2;
                    *(uint32_t*)(ALn + off) = *(const uint32_t*)&l2;
                }
            }
        }
    }

    // ---- epilogue ----
    __syncthreads();
    float* Sd = (float*)sm;
#pragma unroll
    for (int n8 = 0; n8 < 4; n8++) {
        int pr = m0 + (lane >> 2);
        int o0 = wn * 32 + n8 * 8 + 2 * (lane & 3);
        float* bse = Sd + o0 * PD;
        bse[pr]          = acc[n8][0];
        bse[PD + pr]     = acc[n8][1];
        bse[pr + 8]      = acc[n8][2];
        bse[PD + pr + 8] = acc[n8][3];
    }
    __syncthreads();

    size_t obase = (size_t)b * COUT * (HH * WW) + (size_t)y * WW + x0;
#pragma unroll
    for (int i = tid; i < 64 * 16; i += 256) {
        int o  = i >> 4;
        int pq = i & 15;
        float4 v = *(const float4*)&Sd[o * PD + pq * 4];
        *(float4*)(out + obase + (size_t)o * (HH * WW) + pq * 4) = v;
    }
}

// ---------------------------------------------------------------------------
extern "C" void kernel_launch(void* const* d_in, const int* in_sizes, int n_in,
                              void* d_out, int out_size) {
    const float* x  = (const float*)d_in[0];
    const float* wo = (const float*)d_in[1];
    const float* wd = (const float*)d_in[2];
    float* out = (float*)d_out;

    cudaFuncSetAttribute(k_main, cudaFuncAttributeMaxDynamicSharedMemorySize, 65536);
    cudaFuncSetAttribute(k_off2, cudaFuncAttributeMaxDynamicSharedMemorySize, 68608);

    dim3 tb(32, 8);
    dim3 tg(HH * WW / 32, CC / 32, BB);
    k_transpose<<<tg, tb>>>(x);

    k_wprep<<<(K2 * 64 * 64 + 255) / 256, 256>>>(wd);
    k_woprep<<<(K2 * 64 * 32 + 255) / 256, 256>>>(wo);

    k_off2<<<NPIX / TP, 256, 68608>>>();

    k_main<<<NPIX / TP, 256, 65536>>>(out);
}

// round 10
// speedup vs baseline: 3.8756x; 1.0562x over previous
#include <cuda_runtime.h>
#include <cuda_bf16.h>
#include <cstdint>

#define HH 128
#define WW 128
#define CC 64
#define BB 4
#define COUT 64
#define K2 9
#define NPIX (BB * HH * WW)   // 65536
#define TP 64                 // pixels per block
#define PD 68                 // epilogue smem pitch (floats)

#define APLANE 26112          // 3*68*128 bytes (halo A plane)
#define WAOFF  52224          // phase-A W buffers
#define OFFS_OFF 68608        // offs_s: 64*20 floats = 5120 B
#define SMEM_TOTAL 73728

// Scratch (device globals)
__device__ __align__(16) float g_xT[BB * HH * WW * CC];          // x as (b,y,x,c)
__device__ __align__(16) unsigned short g_wB[K2][2][64 * 64];    // deform W: [kk][hi/lo] swizzled
__device__ __align__(16) unsigned short g_wO[K2][2][64 * 32];    // offset W: [kk][hi/lo] swizzled

// ---- helpers ---------------------------------------------------------------
__device__ __forceinline__ uint32_t smem_u32(const void* p) {
    uint32_t a;
    asm("{ .reg .u64 t; cvta.to.shared.u64 t, %1; cvt.u32.u64 %0, t; }" : "=r"(a) : "l"(p));
    return a;
}
__device__ __forceinline__ void ldsm4(uint32_t addr, uint32_t* r) {
    asm volatile("ldmatrix.sync.aligned.m8n8.x4.shared.b16 {%0,%1,%2,%3}, [%4];"
                 : "=r"(r[0]), "=r"(r[1]), "=r"(r[2]), "=r"(r[3]) : "r"(addr));
}
__device__ __forceinline__ void ldsm4t(uint32_t addr, uint32_t* r) {
    asm volatile("ldmatrix.sync.aligned.m8n8.x4.trans.shared.b16 {%0,%1,%2,%3}, [%4];"
                 : "=r"(r[0]), "=r"(r[1]), "=r"(r[2]), "=r"(r[3]) : "r"(addr));
}
__device__ __forceinline__ void mma16816(float* d, const uint32_t* a, const uint32_t* b) {
    asm volatile(
        "mma.sync.aligned.m16n8k16.row.col.f32.bf16.bf16.f32 "
        "{%0,%1,%2,%3}, {%4,%5,%6,%7}, {%8,%9}, {%0,%1,%2,%3};"
        : "+f"(d[0]), "+f"(d[1]), "+f"(d[2]), "+f"(d[3])
        : "r"(a[0]), "r"(a[1]), "r"(a[2]), "r"(a[3]), "r"(b[0]), "r"(b[1]));
}
__device__ __forceinline__ void cp16(uint32_t dst, const void* src) {
    asm volatile("cp.async.cg.shared.global [%0], [%1], 16;"
                 :: "r"(dst), "l"(src) : "memory");
}
__device__ __forceinline__ void cp_commit() {
    asm volatile("cp.async.commit_group;" ::: "memory");
}
__device__ __forceinline__ void cp_wait0() {
    asm volatile("cp.async.wait_group 0;" ::: "memory");
}

// ---------------------------------------------------------------------------
// 1) Transpose x: NCHW -> NHWC
// ---------------------------------------------------------------------------
__global__ void k_transpose(const float* __restrict__ x) {
    __shared__ float tile[32][33];
    int b  = blockIdx.z;
    int c0 = blockIdx.y * 32;
    int p0 = blockIdx.x * 32;
    int tx = threadIdx.x, ty = threadIdx.y;   // (32, 8)
    const float* src = x + (size_t)b * CC * HH * WW;
    float* dst = g_xT + (size_t)b * HH * WW * CC;
#pragma unroll
    for (int i = 0; i < 32; i += 8)
        tile[ty + i][tx] = src[(size_t)(c0 + ty + i) * (HH * WW) + p0 + tx];
    __syncthreads();
#pragma unroll
    for (int i = 0; i < 32; i += 8)
        dst[(size_t)(p0 + ty + i) * CC + c0 + tx] = tile[tx][ty + i];
}

// ---------------------------------------------------------------------------
// 2a) Deform-weight prep
// ---------------------------------------------------------------------------
__global__ void k_wprep(const float* __restrict__ wd) {
    int i = blockIdx.x * 256 + threadIdx.x;
    if (i >= K2 * 64 * 64) return;
    int kk = i >> 12;
    int r  = i & 4095;
    int c  = r >> 6;
    int o  = r & 63;
    float val = wd[((size_t)o * CC + c) * K2 + kk];
    __nv_bfloat16 h = __float2bfloat16(val);
    __nv_bfloat16 l = __float2bfloat16(val - __bfloat162float(h));
    uint32_t off = (uint32_t)c * 128 + (((uint32_t)o * 2) ^ (((uint32_t)c & 7) << 4));
    g_wB[kk][0][off >> 1] = *(const unsigned short*)&h;
    g_wB[kk][1][off >> 1] = *(const unsigned short*)&l;
}

// 2b) Offset-weight prep
__global__ void k_woprep(const float* __restrict__ wo) {
    int i = blockIdx.x * 256 + threadIdx.x;
    if (i >= K2 * 64 * 32) return;
    int n  = i & 31;
    int c  = (i >> 5) & 63;
    int kk = i >> 11;
    float val = (n < 18) ? wo[((size_t)n * CC + c) * K2 + kk] : 0.f;
    __nv_bfloat16 h = __float2bfloat16(val);
    __nv_bfloat16 l = __float2bfloat16(val - __bfloat162float(h));
    uint32_t off = (uint32_t)c * 64 + (((uint32_t)n * 2) ^ (((uint32_t)c & 3) << 4));
    g_wO[kk][0][off >> 1] = *(const unsigned short*)&h;
    g_wO[kk][1][off >> 1] = *(const unsigned short*)&l;
}

// ---------------------------------------------------------------------------
// 3) Fused kernel: phase A (offset conv) + phase B (sample + main GEMM)
// ---------------------------------------------------------------------------
__device__ __forceinline__ void copy_W_async(int kk, uint32_t Wd, int tid) {
    const char* src = (const char*)&g_wB[kk][0][0];
#pragma unroll
    for (int i = 0; i < 4; i++) {
        int off = (tid + i * 256) * 16;
        cp16(Wd + off, src + off);
    }
}

__global__ __launch_bounds__(256, 3) void k_fused(float* __restrict__ out) {
    extern __shared__ __align__(16) char sm[];

    int tid  = threadIdx.x;
    int lane = tid & 31;
    int wid  = tid >> 5;

    int pix0 = blockIdx.x * TP;
    int b    = pix0 >> 14;
    int y    = (pix0 & 16383) >> 7;
    int x0   = pix0 & 127;
    const float* xTb = g_xT + (size_t)b * HH * WW * CC;

    uint32_t sbase = smem_u32(sm);
    float* offs_s = (float*)(sm + OFFS_OFF);   // [p][20]

    // ============================ PHASE A ============================
    // W chunk 0 prefetch
    {
        const char* src = (const char*)&g_wO[0][0][0];
#pragma unroll
        for (int i = 0; i < 2; i++) {
            int off = (tid + i * 256) * 16;
            cp16(sbase + WAOFF + off, src + off);
        }
        cp_commit();
    }

    // stage halo A view once: 3 y-rows x 66 x-rows x 64ch, hi/lo bf16
    {
        float4 z4 = make_float4(0.f, 0.f, 0.f, 0.f);
        for (int it = tid; it < 3 * 66 * 4; it += 256) {
            int i = it / 264;
            int r = it - i * 264;
            int j = r >> 2;
            int q = r & 3;
            int yy = y - 1 + i;
            int xx = x0 - 1 + j;
            bool v = ((unsigned)yy < (unsigned)HH) && ((unsigned)xx < (unsigned)WW);
            const float4* src = (const float4*)(xTb + ((long)yy * WW + xx) * CC + q * 16);
            uint32_t hi[4], lo[4];
#pragma unroll
            for (int u = 0; u < 2; u++) {
                float4 f0 = v ? src[2 * u] : z4;
                float4 f1 = v ? src[2 * u + 1] : z4;
                __nv_bfloat162 ha = __floats2bfloat162_rn(f0.x, f0.y);
                __nv_bfloat162 hb = __floats2bfloat162_rn(f0.z, f0.w);
                __nv_bfloat162 hc = __floats2bfloat162_rn(f1.x, f1.y);
                __nv_bfloat162 hd = __floats2bfloat162_rn(f1.z, f1.w);
                __nv_bfloat162 la = __floats2bfloat162_rn(f0.x - __bfloat162float(ha.x), f0.y - __bfloat162float(ha.y));
                __nv_bfloat162 lb = __floats2bfloat162_rn(f0.z - __bfloat162float(hb.x), f0.w - __bfloat162float(hb.y));
                __nv_bfloat162 lc = __floats2bfloat162_rn(f1.x - __bfloat162float(hc.x), f1.y - __bfloat162float(hc.y));
                __nv_bfloat162 ld = __floats2bfloat162_rn(f1.z - __bfloat162float(hd.x), f1.w - __bfloat162float(hd.y));
                hi[0] = *(uint32_t*)&ha; hi[1] = *(uint32_t*)&hb;
                hi[2] = *(uint32_t*)&hc; hi[3] = *(uint32_t*)&hd;
                lo[0] = *(uint32_t*)&la; lo[1] = *(uint32_t*)&lb;
                lo[2] = *(uint32_t*)&lc; lo[3] = *(uint32_t*)&ld;
                uint32_t row = (uint32_t)(i * 68 + j);
                uint32_t addr = row * 128 + (((uint32_t)(q * 32 + u * 16)) ^ ((row & 7) << 4));
                *(uint4*)(sm + addr) = *(uint4*)hi;
                *(uint4*)(sm + APLANE + addr) = *(uint4*)lo;
            }
        }
    }
    __syncthreads();

    {
        int m0 = (wid & 3) * 16;
        int n0 = (wid >> 2) * 16;
        int rA = (lane & 7) + 8 * ((lane >> 3) & 1);
        int cg = lane >> 4;
        uint32_t bcol = (((uint32_t)(n0 * 2 + cg * 16)) ^ (((uint32_t)rA & 3) << 4));

        float acc[2][4];
#pragma unroll
        for (int j = 0; j < 2; j++)
#pragma unroll
            for (int q = 0; q < 4; q++) acc[j][q] = 0.f;

        for (int kk = 0; kk < K2; kk++) {
            cp_wait0();
            __syncthreads();
            int buf = kk & 1;
            uint32_t wHbase = sbase + WAOFF + buf * 8192;
            uint32_t wLbase = wHbase + 4096;
            if (kk + 1 < K2) {
                int nb = buf ^ 1;
                const char* src = (const char*)&g_wO[kk + 1][0][0];
#pragma unroll
                for (int i = 0; i < 2; i++) {
                    int off = (tid + i * 256) * 16;
                    cp16(sbase + WAOFF + nb * 8192 + off, src + off);
                }
                cp_commit();
            }
            int ki = kk / 3, kj = kk % 3;
            uint32_t prow = (uint32_t)(ki * 68 + m0 + rA + kj);
            uint32_t arowb = prow * 128;
            uint32_t xorA = (prow & 7) << 4;
#pragma unroll
            for (int ks = 0; ks < 4; ks++) {
                int k0 = ks * 16;
                uint32_t a_hi[4], a_lo[4];
                uint32_t acolb = ((uint32_t)(2 * k0 + cg * 16)) ^ xorA;
                ldsm4(sbase + arowb + acolb, a_hi);
                ldsm4(sbase + APLANE + arowb + acolb, a_lo);
                uint32_t b_hi[4], b_lo[4];
                uint32_t brow = (uint32_t)(k0 + rA) * 64;
                ldsm4t(wHbase + brow + bcol, b_hi);
                ldsm4t(wLbase + brow + bcol, b_lo);
#pragma unroll
                for (int n8 = 0; n8 < 2; n8++) {
                    const uint32_t* bh = &b_hi[n8 * 2];
                    const uint32_t* bl = &b_lo[n8 * 2];
                    mma16816(acc[n8], a_hi, bh);
                    mma16816(acc[n8], a_hi, bl);
                    mma16816(acc[n8], a_lo, bh);
                }
            }
        }

        // phase-A epilogue: frags -> offs_s[p][n]
        __syncthreads();   // MMAs of all warps done before offs written? (writes go to OFFS region, disjoint; but keep order)
#pragma unroll
        for (int n8 = 0; n8 < 2; n8++) {
            int pr = m0 + (lane >> 2);
            int nn = n0 + n8 * 8 + 2 * (lane & 3);
            if (nn < 18) {
                offs_s[pr * 20 + nn]           = acc[n8][0];
                offs_s[pr * 20 + nn + 1]       = acc[n8][1];
                offs_s[(pr + 8) * 20 + nn]     = acc[n8][2];
                offs_s[(pr + 8) * 20 + nn + 1] = acc[n8][3];
            }
        }
    }
    __syncthreads();

    // ============================ PHASE B ============================
    // smem reuse: AH0=0 AL0=8192 AH1=16384 AL1=24576 | W0=32768 W1=49152
    int l  = tid & 15;
    int hw = tid >> 4;

    // prologue: W chunk 0 + sample chunk 0
    copy_W_async(0, sbase + 32768, tid);
    cp_commit();
    {
        float2 z2 = make_float2(0.f, 0.f);
#pragma unroll
        for (int pass = 0; pass < 4; pass++) {
            int p = pass * 16 + hw;
            float dy = offs_s[p * 20 + 0];
            float dx = offs_s[p * 20 + 1];
            float ys = (float)(y - 1) + dy;
            float xs = (float)(x0 + p - 1) + dx;
            float y0f = floorf(ys), x0f = floorf(xs);
            float fy = ys - y0f, fx = xs - x0f;
            int iy = (int)y0f, ix = (int)x0f;
            bool vy0 = ((unsigned)iy < (unsigned)HH);
            bool vy1 = ((unsigned)(iy + 1) < (unsigned)HH);
            bool vx0 = ((unsigned)ix < (unsigned)WW);
            bool vx1 = ((unsigned)(ix + 1) < (unsigned)WW);
            float w00 = (1.f - fy) * (1.f - fx);
            float w01 = (1.f - fy) * fx;
            float w10 = fy * (1.f - fx);
            float w11 = fy * fx;
            const float* b0 = xTb + ((long)iy * WW + ix) * CC + 2 * l;
            uint32_t rowbase = (uint32_t)p * 128;
            uint32_t xorm = ((uint32_t)p & 7) << 4;
#pragma unroll
            for (int h = 0; h < 2; h++) {
                const float* bh = b0 + 32 * h;
                float2 v00 = (vy0 && vx0) ? *(const float2*)(bh) : z2;
                float2 v01 = (vy0 && vx1) ? *(const float2*)(bh + CC) : z2;
                float2 v10 = (vy1 && vx0) ? *(const float2*)(bh + WW * CC) : z2;
                float2 v11 = (vy1 && vx1) ? *(const float2*)(bh + WW * CC + CC) : z2;
                float rx = w00 * v00.x + w01 * v01.x + w10 * v10.x + w11 * v11.x;
                float ry = w00 * v00.y + w01 * v01.y + w10 * v10.y + w11 * v11.y;
                __nv_bfloat162 h2 = __floats2bfloat162_rn(rx, ry);
                float hx = __bfloat162float(h2.x);
                float hy = __bfloat162float(h2.y);
                __nv_bfloat162 l2 = __floats2bfloat162_rn(rx - hx, ry - hy);
                uint32_t off = rowbase + (((uint32_t)(4 * l + 64 * h)) ^ xorm);
                *(uint32_t*)(sm + off) = *(const uint32_t*)&h2;
                *(uint32_t*)(sm + 8192 + off) = *(const uint32_t*)&l2;
            }
        }
    }

    int m0 = (wid & 3) * 16;
    int wn = wid >> 2;
    int rA = (lane & 7) + 8 * ((lane >> 3) & 1);
    int cg = lane >> 4;
    uint32_t xorA0 = ((uint32_t)rA & 7) << 4;
    uint32_t bcol[2];
#pragma unroll
    for (int nt = 0; nt < 2; nt++)
        bcol[nt] = (((uint32_t)(wn * 64 + nt * 32 + cg * 16)) ^ xorA0);

    float acc[4][4];
#pragma unroll
    for (int j = 0; j < 4; j++)
#pragma unroll
        for (int q = 0; q < 4; q++) acc[j][q] = 0.f;

    for (int kk = 0; kk < K2; kk++) {
        cp_wait0();
        __syncthreads();
        int buf = kk & 1;
        uint32_t aHbase = sbase + buf * 16384;
        uint32_t aLbase = aHbase + 8192;
        uint32_t wHbase = sbase + 32768 + buf * 16384;
        uint32_t wLbase = wHbase + 8192;

        bool pre = (kk + 1 < K2);
        int nb = buf ^ 1;
        char* AHn = sm + nb * 16384;
        char* ALn = AHn + 8192;

        int ki = 0, kj = 0;
        float2 offs2[4];
        if (pre) {
            copy_W_async(kk + 1, sbase + 32768 + nb * 16384, tid);
            cp_commit();
            ki = (kk + 1) / 3;
            kj = (kk + 1) % 3;
#pragma unroll
            for (int s = 0; s < 4; s++) {
                int p = s * 16 + hw;
                offs2[s] = make_float2(offs_s[p * 20 + 2 * (kk + 1)],
                                       offs_s[p * 20 + 2 * (kk + 1) + 1]);
            }
        }

        float2 z2 = make_float2(0.f, 0.f);
#pragma unroll
        for (int s = 0; s < 4; s++) {
            // --- issue gather LDGs for pass s of chunk kk+1 ---
            float2 c00a, c01a, c10a, c11a, c00b, c01b, c10b, c11b;
            float fy = 0.f, fx = 0.f;
            if (pre) {
                int p = s * 16 + hw;
                float ys = (float)(y - 1 + ki) + offs2[s].x;
                float xs = (float)(x0 + p - 1 + kj) + offs2[s].y;
                float y0f = floorf(ys), x0f = floorf(xs);
                fy = ys - y0f; fx = xs - x0f;
                int iy = (int)y0f, ix = (int)x0f;
                bool vy0 = ((unsigned)iy < (unsigned)HH);
                bool vy1 = ((unsigned)(iy + 1) < (unsigned)HH);
                bool vx0 = ((unsigned)ix < (unsigned)WW);
                bool vx1 = ((unsigned)(ix + 1) < (unsigned)WW);
                const float* b0 = xTb + ((long)iy * WW + ix) * CC + 2 * l;
                c00a = (vy0 && vx0) ? *(const float2*)(b0) : z2;
                c01a = (vy0 && vx1) ? *(const float2*)(b0 + CC) : z2;
                c10a = (vy1 && vx0) ? *(const float2*)(b0 + WW * CC) : z2;
                c11a = (vy1 && vx1) ? *(const float2*)(b0 + WW * CC + CC) : z2;
                const float* b1 = b0 + 32;
                c00b = (vy0 && vx0) ? *(const float2*)(b1) : z2;
                c01b = (vy0 && vx1) ? *(const float2*)(b1 + CC) : z2;
                c10b = (vy1 && vx0) ? *(const float2*)(b1 + WW * CC) : z2;
                c11b = (vy1 && vx1) ? *(const float2*)(b1 + WW * CC + CC) : z2;
            }

            // --- MMA step s on chunk kk ---
            {
                int k0 = s * 16;
                uint32_t a_hi[4], a_lo[4];
                uint32_t acolb = ((uint32_t)(2 * k0 + cg * 16)) ^ xorA0;
                uint32_t arow = (uint32_t)(m0 + rA) * 128;
                ldsm4(aHbase + arow + acolb, a_hi);
                ldsm4(aLbase + arow + acolb, a_lo);
                uint32_t b_hi[2][4], b_lo[2][4];
                uint32_t brow = (uint32_t)(k0 + rA) * 128;
#pragma unroll
                for (int nt = 0; nt < 2; nt++) {
                    ldsm4t(wHbase + brow + bcol[nt], b_hi[nt]);
                    ldsm4t(wLbase + brow + bcol[nt], b_lo[nt]);
                }
#pragma unroll
                for (int n8 = 0; n8 < 4; n8++) {
                    const uint32_t* bh = &b_hi[n8 >> 1][(n8 & 1) * 2];
                    const uint32_t* bl = &b_lo[n8 >> 1][(n8 & 1) * 2];
                    mma16816(acc[n8], a_hi, bh);
                    mma16816(acc[n8], a_hi, bl);
                    mma16816(acc[n8], a_lo, bh);
                }
            }

            // --- interp + STS pass s to next buffers ---
            if (pre) {
                int p = s * 16 + hw;
                float w00 = (1.f - fy) * (1.f - fx);
                float w01 = (1.f - fy) * fx;
                float w10 = fy * (1.f - fx);
                float w11 = fy * fx;
                uint32_t rowbase = (uint32_t)p * 128;
                uint32_t xorm = ((uint32_t)p & 7) << 4;
                {
                    float rx = w00 * c00a.x + w01 * c01a.x + w10 * c10a.x + w11 * c11a.x;
                    float ry = w00 * c00a.y + w01 * c01a.y + w10 * c10a.y + w11 * c11a.y;
                    __nv_bfloat162 h2 = __floats2bfloat162_rn(rx, ry);
                    float hx = __bfloat162float(h2.x);
                    float hy = __bfloat162float(h2.y);
                    __nv_bfloat162 l2 = __floats2bfloat162_rn(rx - hx, ry - hy);
                    uint32_t off = rowbase + (((uint32_t)(4 * l)) ^ xorm);
                    *(uint32_t*)(AHn + off) = *(const uint32_t*)&h2;
                    *(uint32_t*)(ALn + off) = *(const uint32_t*)&l2;
                }
                {
                    float rx = w00 * c00b.x + w01 * c01b.x + w10 * c10b.x + w11 * c11b.x;
                    float ry = w00 * c00b.y + w01 * c01b.y + w10 * c10b.y + w11 * c11b.y;
                    __nv_bfloat162 h2 = __floats2bfloat162_rn(rx, ry);
                    float hx = __bfloat162float(h2.x);
                    float hy = __bfloat162float(h2.y);
                    __nv_bfloat162 l2 = __floats2bfloat162_rn(rx - hx, ry - hy);
                    uint32_t off = rowbase + (((uint32_t)(4 * l + 64)) ^ xorm);
                    *(uint32_t*)(AHn + off) = *(const uint32_t*)&h2;
                    *(uint32_t*)(ALn + off) = *(const uint32_t*)&l2;
                }
            }
        }
    }

    // ---- epilogue ----
    __syncthreads();
    float* Sd = (float*)sm;
#pragma unroll
    for (int n8 = 0; n8 < 4; n8++) {
        int pr = m0 + (lane >> 2);
        int o0 = wn * 32 + n8 * 8 + 2 * (lane & 3);
        float* bse = Sd + o0 * PD;
        bse[pr]          = acc[n8][0];
        bse[PD + pr]     = acc[n8][1];
        bse[pr + 8]      = acc[n8][2];
        bse[PD + pr + 8] = acc[n8][3];
    }
    __syncthreads();

    size_t obase = (size_t)b * COUT * (HH * WW) + (size_t)y * WW + x0;
#pragma unroll
    for (int i = tid; i < 64 * 16; i += 256) {
        int o  = i >> 4;
        int pq = i & 15;
        float4 v = *(const float4*)&Sd[o * PD + pq * 4];
        *(float4*)(out + obase + (size_t)o * (HH * WW) + pq * 4) = v;
    }
}

// ---------------------------------------------------------------------------
extern "C" void kernel_launch(void* const* d_in, const int* in_sizes, int n_in,
                              void* d_out, int out_size) {
    const float* x  = (const float*)d_in[0];
    const float* wo = (const float*)d_in[1];
    const float* wd = (const float*)d_in[2];
    float* out = (float*)d_out;

    cudaFuncSetAttribute(k_fused, cudaFuncAttributeMaxDynamicSharedMemorySize,
                         SMEM_TOTAL);

    dim3 tb(32, 8);
    dim3 tg(HH * WW / 32, CC / 32, BB);
    k_transpose<<<tg, tb>>>(x);

    k_wprep<<<(K2 * 64 * 64 + 255) / 256, 256>>>(wd);
    k_woprep<<<(K2 * 64 * 32 + 255) / 256, 256>>>(wo);

    k_fused<<<NPIX / TP, 256, SMEM_TOTAL>>>(out);
}

// round 11
// speedup vs baseline: 4.9084x; 1.2665x over previous
#include <cuda_runtime.h>
#include <cuda_fp16.h>
#include <cstdint>

#define HH 128
#define WW 128
#define CC 64
#define BB 4
#define COUT 64
#define K2 9
#define NPIX (BB * HH * WW)   // 65536
#define TP 64                 // pixels per block
#define PD 68                 // epilogue smem pitch (floats)

#define APLANE 26112          // 3*68*128 bytes (halo A plane, fp16)
#define WAOFF  52224          // phase-A W buffers (2 x 4096)
#define OFFS_OFF 60416        // offs_s: 64*20 floats = 5120 B
#define SMEM_TOTAL 65536

// Scratch (device globals)
__device__ __align__(16) float g_xT[BB * HH * WW * CC];       // x as (b,y,x,c)
__device__ __align__(16) unsigned short g_wB[K2][64 * 64];    // deform W fp16, swizzled [c rows 128B][o]
__device__ __align__(16) unsigned short g_wO[K2][64 * 32];    // offset W fp16, swizzled [c rows 64B][n]

// ---- helpers ---------------------------------------------------------------
__device__ __forceinline__ uint32_t smem_u32(const void* p) {
    uint32_t a;
    asm("{ .reg .u64 t; cvta.to.shared.u64 t, %1; cvt.u32.u64 %0, t; }" : "=r"(a) : "l"(p));
    return a;
}
__device__ __forceinline__ void ldsm4(uint32_t addr, uint32_t* r) {
    asm volatile("ldmatrix.sync.aligned.m8n8.x4.shared.b16 {%0,%1,%2,%3}, [%4];"
                 : "=r"(r[0]), "=r"(r[1]), "=r"(r[2]), "=r"(r[3]) : "r"(addr));
}
__device__ __forceinline__ void ldsm4t(uint32_t addr, uint32_t* r) {
    asm volatile("ldmatrix.sync.aligned.m8n8.x4.trans.shared.b16 {%0,%1,%2,%3}, [%4];"
                 : "=r"(r[0]), "=r"(r[1]), "=r"(r[2]), "=r"(r[3]) : "r"(addr));
}
__device__ __forceinline__ void mma16816(float* d, const uint32_t* a, const uint32_t* b) {
    asm volatile(
        "mma.sync.aligned.m16n8k16.row.col.f32.f16.f16.f32 "
        "{%0,%1,%2,%3}, {%4,%5,%6,%7}, {%8,%9}, {%0,%1,%2,%3};"
        : "+f"(d[0]), "+f"(d[1]), "+f"(d[2]), "+f"(d[3])
        : "r"(a[0]), "r"(a[1]), "r"(a[2]), "r"(a[3]), "r"(b[0]), "r"(b[1]));
}
__device__ __forceinline__ void cp16(uint32_t dst, const void* src) {
    asm volatile("cp.async.cg.shared.global [%0], [%1], 16;"
                 :: "r"(dst), "l"(src) : "memory");
}
__device__ __forceinline__ void cp_commit() {
    asm volatile("cp.async.commit_group;" ::: "memory");
}
__device__ __forceinline__ void cp_wait0() {
    asm volatile("cp.async.wait_group 0;" ::: "memory");
}

// interp 4 channels, split fp16 hi/lo, store 8B to each plane
__device__ __forceinline__ void interp_store4(
    float w00, float w01, float w10, float w11,
    float4 v00, float4 v01, float4 v10, float4 v11,
    char* AH, char* AL, uint32_t off)
{
    float rx = w00 * v00.x + w01 * v01.x + w10 * v10.x + w11 * v11.x;
    float ry = w00 * v00.y + w01 * v01.y + w10 * v10.y + w11 * v11.y;
    float rz = w00 * v00.z + w01 * v01.z + w10 * v10.z + w11 * v11.z;
    float rw = w00 * v00.w + w01 * v01.w + w10 * v10.w + w11 * v11.w;
    __half2 ha = __floats2half2_rn(rx, ry);
    __half2 hb = __floats2half2_rn(rz, rw);
    float2 fa = __half22float2(ha);
    float2 fb = __half22float2(hb);
    __half2 la = __floats2half2_rn(rx - fa.x, ry - fa.y);
    __half2 lb = __floats2half2_rn(rz - fb.x, rw - fb.y);
    uint2 hv = make_uint2(*(uint32_t*)&ha, *(uint32_t*)&hb);
    uint2 lv = make_uint2(*(uint32_t*)&la, *(uint32_t*)&lb);
    *(uint2*)(AH + off) = hv;
    *(uint2*)(AL + off) = lv;
}

// ---------------------------------------------------------------------------
// 1) Transpose x: NCHW -> NHWC
// ---------------------------------------------------------------------------
__global__ void k_transpose(const float* __restrict__ x) {
    __shared__ float tile[32][33];
    int b  = blockIdx.z;
    int c0 = blockIdx.y * 32;
    int p0 = blockIdx.x * 32;
    int tx = threadIdx.x, ty = threadIdx.y;   // (32, 8)
    const float* src = x + (size_t)b * CC * HH * WW;
    float* dst = g_xT + (size_t)b * HH * WW * CC;
#pragma unroll
    for (int i = 0; i < 32; i += 8)
        tile[ty + i][tx] = src[(size_t)(c0 + ty + i) * (HH * WW) + p0 + tx];
    __syncthreads();
#pragma unroll
    for (int i = 0; i < 32; i += 8)
        dst[(size_t)(p0 + ty + i) * CC + c0 + tx] = tile[tx][ty + i];
}

// ---------------------------------------------------------------------------
// 2a) Deform-weight prep: single fp16 plane
// ---------------------------------------------------------------------------
__global__ void k_wprep(const float* __restrict__ wd) {
    int i = blockIdx.x * 256 + threadIdx.x;
    if (i >= K2 * 64 * 64) return;
    int kk = i >> 12;
    int r  = i & 4095;
    int c  = r >> 6;
    int o  = r & 63;
    __half h = __float2half_rn(wd[((size_t)o * CC + c) * K2 + kk]);
    uint32_t off = (uint32_t)c * 128 + (((uint32_t)o * 2) ^ (((uint32_t)c & 7) << 4));
    g_wB[kk][off >> 1] = *(const unsigned short*)&h;
}

// 2b) Offset-weight prep: single fp16 plane
__global__ void k_woprep(const float* __restrict__ wo) {
    int i = blockIdx.x * 256 + threadIdx.x;
    if (i >= K2 * 64 * 32) return;
    int n  = i & 31;
    int c  = (i >> 5) & 63;
    int kk = i >> 11;
    float val = (n < 18) ? wo[((size_t)n * CC + c) * K2 + kk] : 0.f;
    __half h = __float2half_rn(val);
    uint32_t off = (uint32_t)c * 64 + (((uint32_t)n * 2) ^ (((uint32_t)c & 3) << 4));
    g_wO[kk][off >> 1] = *(const unsigned short*)&h;
}

// ---------------------------------------------------------------------------
// 3) Fused kernel
// ---------------------------------------------------------------------------
__device__ __forceinline__ void copy_W_async(int kk, uint32_t Wd, int tid) {
    const char* src = (const char*)&g_wB[kk][0];   // 8192 B
#pragma unroll
    for (int i = 0; i < 2; i++) {
        int off = (tid + i * 256) * 16;
        cp16(Wd + off, src + off);
    }
}

__global__ __launch_bounds__(256, 3) void k_fused(float* __restrict__ out) {
    extern __shared__ __align__(16) char sm[];

    int tid  = threadIdx.x;
    int lane = tid & 31;
    int wid  = tid >> 5;

    int pix0 = blockIdx.x * TP;
    int b    = pix0 >> 14;
    int y    = (pix0 & 16383) >> 7;
    int x0   = pix0 & 127;
    const float* xTb = g_xT + (size_t)b * HH * WW * CC;

    uint32_t sbase = smem_u32(sm);
    float* offs_s = (float*)(sm + OFFS_OFF);   // [p][20]

    // ============================ PHASE A ============================
    {
        const char* src = (const char*)&g_wO[0][0];   // 4096 B
        cp16(sbase + WAOFF + tid * 16, src + tid * 16);
        cp_commit();
    }

    // stage halo A view once: 3 y-rows x 66 x-rows x 64ch, fp16 hi/lo
    {
        float4 z4 = make_float4(0.f, 0.f, 0.f, 0.f);
        for (int it = tid; it < 3 * 66 * 4; it += 256) {
            int i = it / 264;
            int r = it - i * 264;
            int j = r >> 2;
            int q = r & 3;
            int yy = y - 1 + i;
            int xx = x0 - 1 + j;
            bool v = ((unsigned)yy < (unsigned)HH) && ((unsigned)xx < (unsigned)WW);
            const float4* src = (const float4*)(xTb + ((long)yy * WW + xx) * CC + q * 16);
            uint32_t hi[4], lo[4];
#pragma unroll
            for (int u = 0; u < 2; u++) {
                float4 f0 = v ? src[2 * u] : z4;
                float4 f1 = v ? src[2 * u + 1] : z4;
                __half2 ha = __floats2half2_rn(f0.x, f0.y);
                __half2 hb = __floats2half2_rn(f0.z, f0.w);
                __half2 hc = __floats2half2_rn(f1.x, f1.y);
                __half2 hd = __floats2half2_rn(f1.z, f1.w);
                float2 fa = __half22float2(ha), fb = __half22float2(hb);
                float2 fc = __half22float2(hc), fd = __half22float2(hd);
                __half2 la = __floats2half2_rn(f0.x - fa.x, f0.y - fa.y);
                __half2 lb = __floats2half2_rn(f0.z - fb.x, f0.w - fb.y);
                __half2 lc = __floats2half2_rn(f1.x - fc.x, f1.y - fc.y);
                __half2 ld = __floats2half2_rn(f1.z - fd.x, f1.w - fd.y);
                hi[0] = *(uint32_t*)&ha; hi[1] = *(uint32_t*)&hb;
                hi[2] = *(uint32_t*)&hc; hi[3] = *(uint32_t*)&hd;
                lo[0] = *(uint32_t*)&la; lo[1] = *(uint32_t*)&lb;
                lo[2] = *(uint32_t*)&lc; lo[3] = *(uint32_t*)&ld;
                uint32_t row = (uint32_t)(i * 68 + j);
                uint32_t addr = row * 128 + (((uint32_t)(q * 32 + u * 16)) ^ ((row & 7) << 4));
                *(uint4*)(sm + addr) = *(uint4*)hi;
                *(uint4*)(sm + APLANE + addr) = *(uint4*)lo;
            }
        }
    }
    __syncthreads();

    {
        int m0 = (wid & 3) * 16;
        int n0 = (wid >> 2) * 16;
        int rA = (lane & 7) + 8 * ((lane >> 3) & 1);
        int cg = lane >> 4;
        uint32_t bcol = (((uint32_t)(n0 * 2 + cg * 16)) ^ (((uint32_t)rA & 3) << 4));

        float acc[2][4];
#pragma unroll
        for (int j = 0; j < 2; j++)
#pragma unroll
            for (int q = 0; q < 4; q++) acc[j][q] = 0.f;

        for (int kk = 0; kk < K2; kk++) {
            cp_wait0();
            __syncthreads();
            int buf = kk & 1;
            uint32_t wBase = sbase + WAOFF + buf * 4096;
            if (kk + 1 < K2) {
                int nb = buf ^ 1;
                const char* src = (const char*)&g_wO[kk + 1][0];
                cp16(sbase + WAOFF + nb * 4096 + tid * 16, src + tid * 16);
                cp_commit();
            }
            int ki = kk / 3, kj = kk % 3;
            uint32_t prow = (uint32_t)(ki * 68 + m0 + rA + kj);
            uint32_t arowb = prow * 128;
            uint32_t xorA = (prow & 7) << 4;
#pragma unroll
            for (int ks = 0; ks < 4; ks++) {
                int k0 = ks * 16;
                uint32_t a_hi[4], a_lo[4];
                uint32_t acolb = ((uint32_t)(2 * k0 + cg * 16)) ^ xorA;
                ldsm4(sbase + arowb + acolb, a_hi);
                ldsm4(sbase + APLANE + arowb + acolb, a_lo);
                uint32_t bb[4];
                uint32_t brow = (uint32_t)(k0 + rA) * 64;
                ldsm4t(wBase + brow + bcol, bb);
#pragma unroll
                for (int n8 = 0; n8 < 2; n8++) {
                    const uint32_t* bp = &bb[n8 * 2];
                    mma16816(acc[n8], a_hi, bp);
                    mma16816(acc[n8], a_lo, bp);
                }
            }
        }

        // phase-A epilogue: frags -> offs_s[p][n]
        __syncthreads();
#pragma unroll
        for (int n8 = 0; n8 < 2; n8++) {
            int pr = m0 + (lane >> 2);
            int nn = n0 + n8 * 8 + 2 * (lane & 3);
            if (nn < 18) {
                offs_s[pr * 20 + nn]           = acc[n8][0];
                offs_s[pr * 20 + nn + 1]       = acc[n8][1];
                offs_s[(pr + 8) * 20 + nn]     = acc[n8][2];
                offs_s[(pr + 8) * 20 + nn + 1] = acc[n8][3];
            }
        }
    }
    __syncthreads();

    // ============================ PHASE B ============================
    // smem reuse: AH0=0 AL0=8192 AH1=16384 AL1=24576 | W0=32768 W1=40960
    int l  = tid & 15;
    int hw = tid >> 4;

    copy_W_async(0, sbase + 32768, tid);
    cp_commit();
    {
        float4 z4 = make_float4(0.f, 0.f, 0.f, 0.f);
#pragma unroll
        for (int pass = 0; pass < 4; pass++) {
            int p = pass * 16 + hw;
            float dy = offs_s[p * 20 + 0];
            float dx = offs_s[p * 20 + 1];
            float ys = (float)(y - 1) + dy;
            float xs = (float)(x0 + p - 1) + dx;
            float y0f = floorf(ys), x0f = floorf(xs);
            float fy = ys - y0f, fx = xs - x0f;
            int iy = (int)y0f, ix = (int)x0f;
            bool vy0 = ((unsigned)iy < (unsigned)HH);
            bool vy1 = ((unsigned)(iy + 1) < (unsigned)HH);
            bool vx0 = ((unsigned)ix < (unsigned)WW);
            bool vx1 = ((unsigned)(ix + 1) < (unsigned)WW);
            float w00 = (1.f - fy) * (1.f - fx);
            float w01 = (1.f - fy) * fx;
            float w10 = fy * (1.f - fx);
            float w11 = fy * fx;
            const float4* bp = (const float4*)(xTb + ((long)iy * WW + ix) * CC) + l;
            float4 v00 = (vy0 && vx0) ? bp[0] : z4;
            float4 v01 = (vy0 && vx1) ? bp[16] : z4;
            float4 v10 = (vy1 && vx0) ? bp[WW * 16] : z4;
            float4 v11 = (vy1 && vx1) ? bp[WW * 16 + 16] : z4;
            uint32_t off = (uint32_t)p * 128 +
                (((uint32_t)(8 * l)) ^ (((uint32_t)p & 7) << 4));
            interp_store4(w00, w01, w10, w11, v00, v01, v10, v11,
                          sm, sm + 8192, off);
        }
    }

    int m0 = (wid & 3) * 16;
    int wn = wid >> 2;
    int rA = (lane & 7) + 8 * ((lane >> 3) & 1);
    int cg = lane >> 4;
    uint32_t xorA0 = ((uint32_t)rA & 7) << 4;
    uint32_t bcol[2];
#pragma unroll
    for (int nt = 0; nt < 2; nt++)
        bcol[nt] = (((uint32_t)(wn * 64 + nt * 32 + cg * 16)) ^ xorA0);

    float acc[4][4];
#pragma unroll
    for (int j = 0; j < 4; j++)
#pragma unroll
        for (int q = 0; q < 4; q++) acc[j][q] = 0.f;

    for (int kk = 0; kk < K2; kk++) {
        cp_wait0();
        __syncthreads();
        int buf = kk & 1;
        uint32_t aHbase = sbase + buf * 16384;
        uint32_t aLbase = aHbase + 8192;
        uint32_t wBase  = sbase + 32768 + buf * 8192;

        bool pre = (kk + 1 < K2);
        int nb = buf ^ 1;
        char* AHn = sm + nb * 16384;
        char* ALn = AHn + 8192;

        int ki = 0, kj = 0;
        float2 offs2[4];
        if (pre) {
            copy_W_async(kk + 1, sbase + 32768 + nb * 8192, tid);
            cp_commit();
            ki = (kk + 1) / 3;
            kj = (kk + 1) % 3;
#pragma unroll
            for (int s = 0; s < 4; s++) {
                int p = s * 16 + hw;
                offs2[s] = make_float2(offs_s[p * 20 + 2 * (kk + 1)],
                                       offs_s[p * 20 + 2 * (kk + 1) + 1]);
            }
        }

        float4 z4 = make_float4(0.f, 0.f, 0.f, 0.f);
#pragma unroll
        for (int s = 0; s < 4; s++) {
            // --- issue gather LDG.128s for pass s of chunk kk+1 ---
            float4 c00, c01, c10, c11;
            float fy = 0.f, fx = 0.f;
            if (pre) {
                int p = s * 16 + hw;
                float ys = (float)(y - 1 + ki) + offs2[s].x;
                float xs = (float)(x0 + p - 1 + kj) + offs2[s].y;
                float y0f = floorf(ys), x0f = floorf(xs);
                fy = ys - y0f; fx = xs - x0f;
                int iy = (int)y0f, ix = (int)x0f;
                bool vy0 = ((unsigned)iy < (unsigned)HH);
                bool vy1 = ((unsigned)(iy + 1) < (unsigned)HH);
                bool vx0 = ((unsigned)ix < (unsigned)WW);
                bool vx1 = ((unsigned)(ix + 1) < (unsigned)WW);
                const float4* bp = (const float4*)(xTb + ((long)iy * WW + ix) * CC) + l;
                c00 = (vy0 && vx0) ? bp[0] : z4;
                c01 = (vy0 && vx1) ? bp[16] : z4;
                c10 = (vy1 && vx0) ? bp[WW * 16] : z4;
                c11 = (vy1 && vx1) ? bp[WW * 16 + 16] : z4;
            }

            // --- MMA step s on chunk kk ---
            {
                int k0 = s * 16;
                uint32_t a_hi[4], a_lo[4];
                uint32_t acolb = ((uint32_t)(2 * k0 + cg * 16)) ^ xorA0;
                uint32_t arow = (uint32_t)(m0 + rA) * 128;
                ldsm4(aHbase + arow + acolb, a_hi);
                ldsm4(aLbase + arow + acolb, a_lo);
                uint32_t bb[2][4];
                uint32_t brow = (uint32_t)(k0 + rA) * 128;
#pragma unroll
                for (int nt = 0; nt < 2; nt++)
                    ldsm4t(wBase + brow + bcol[nt], bb[nt]);
#pragma unroll
                for (int n8 = 0; n8 < 4; n8++) {
                    const uint32_t* bp = &bb[n8 >> 1][(n8 & 1) * 2];
                    mma16816(acc[n8], a_hi, bp);
                    mma16816(acc[n8], a_lo, bp);
                }
            }

            // --- interp + STS pass s to next buffers ---
            if (pre) {
                int p = s * 16 + hw;
                float w00 = (1.f - fy) * (1.f - fx);
                float w01 = (1.f - fy) * fx;
                float w10 = fy * (1.f - fx);
                float w11 = fy * fx;
                uint32_t off = (uint32_t)p * 128 +
                    (((uint32_t)(8 * l)) ^ (((uint32_t)p & 7) << 4));
                interp_store4(w00, w01, w10, w11, c00, c01, c10, c11,
                              AHn, ALn, off);
            }
        }
    }

    // ---- epilogue ----
    __syncthreads();
    float* Sd = (float*)sm;
#pragma unroll
    for (int n8 = 0; n8 < 4; n8++) {
        int pr = m0 + (lane >> 2);
        int o0 = wn * 32 + n8 * 8 + 2 * (lane & 3);
        float* bse = Sd + o0 * PD;
        bse[pr]          = acc[n8][0];
        bse[PD + pr]     = acc[n8][1];
        bse[pr + 8]      = acc[n8][2];
        bse[PD + pr + 8] = acc[n8][3];
    }
    __syncthreads();

    size_t obase = (size_t)b * COUT * (HH * WW) + (size_t)y * WW + x0;
#pragma unroll
    for (int i = tid; i < 64 * 16; i += 256) {
        int o  = i >> 4;
        int pq = i & 15;
        float4 v = *(const float4*)&Sd[o * PD + pq * 4];
        *(float4*)(out + obase + (size_t)o * (HH * WW) + pq * 4) = v;
    }
}

// ---------------------------------------------------------------------------
extern "C" void kernel_launch(void* const* d_in, const int* in_sizes, int n_in,
                              void* d_out, int out_size) {
    const float* x  = (const float*)d_in[0];
    const float* wo = (const float*)d_in[1];
    const float* wd = (const float*)d_in[2];
    float* out = (float*)d_out;

    cudaFuncSetAttribute(k_fused, cudaFuncAttributeMaxDynamicSharedMemorySize,
                         SMEM_TOTAL);

    dim3 tb(32, 8);
    dim3 tg(HH * WW / 32, CC / 32, BB);
    k_transpose<<<tg, tb>>>(x);

    k_wprep<<<(K2 * 64 * 64 + 255) / 256, 256>>>(wd);
    k_woprep<<<(K2 * 64 * 32 + 255) / 256, 256>>>(wo);

    k_fused<<<NPIX / TP, 256, SMEM_TOTAL>>>(out);
}

// round 13
// speedup vs baseline: 4.9951x; 1.0177x over previous
#include <cuda_runtime.h>
#include <cuda_fp16.h>
#include <cstdint>

#define HH 128
#define WW 128
#define CC 64
#define BB 4
#define COUT 64
#define K2 9
#define NPIX (BB * HH * WW)   // 65536
#define TP 64                 // pixels per block
#define PD 68                 // epilogue smem pitch (floats)

#define APLANE 26112          // 3*68*128 bytes (halo A plane, fp16)
#define WAOFF  52224          // phase-A W buffers (2 x 4096)
#define OFFS_OFF 60416        // offs_s: 64*20 floats = 5120 B
#define WB0_OFF 65536         // phase-B W chunk-0 slot (8 KB), prefetched at entry
#define SMEM_TOTAL 73728

// Scratch (device globals)
__device__ __align__(16) float g_xT[BB * HH * WW * CC];       // x as (b,y,x,c)
__device__ __align__(16) unsigned short g_wB[K2][64 * 64];    // deform W fp16, swizzled [c rows 128B][o]
__device__ __align__(16) unsigned short g_wO[K2][64 * 32];    // offset W fp16, swizzled [c rows 64B][n]

// ---- helpers ---------------------------------------------------------------
__device__ __forceinline__ uint32_t smem_u32(const void* p) {
    uint32_t a;
    asm("{ .reg .u64 t; cvta.to.shared.u64 t, %1; cvt.u32.u64 %0, t; }" : "=r"(a) : "l"(p));
    return a;
}
__device__ __forceinline__ void ldsm4(uint32_t addr, uint32_t* r) {
    asm volatile("ldmatrix.sync.aligned.m8n8.x4.shared.b16 {%0,%1,%2,%3}, [%4];"
                 : "=r"(r[0]), "=r"(r[1]), "=r"(r[2]), "=r"(r[3]) : "r"(addr));
}
__device__ __forceinline__ void ldsm4t(uint32_t addr, uint32_t* r) {
    asm volatile("ldmatrix.sync.aligned.m8n8.x4.trans.shared.b16 {%0,%1,%2,%3}, [%4];"
                 : "=r"(r[0]), "=r"(r[1]), "=r"(r[2]), "=r"(r[3]) : "r"(addr));
}
__device__ __forceinline__ void mma16816(float* d, const uint32_t* a, const uint32_t* b) {
    asm volatile(
        "mma.sync.aligned.m16n8k16.row.col.f32.f16.f16.f32 "
        "{%0,%1,%2,%3}, {%4,%5,%6,%7}, {%8,%9}, {%0,%1,%2,%3};"
        : "+f"(d[0]), "+f"(d[1]), "+f"(d[2]), "+f"(d[3])
        : "r"(a[0]), "r"(a[1]), "r"(a[2]), "r"(a[3]), "r"(b[0]), "r"(b[1]));
}
__device__ __forceinline__ void cp16(uint32_t dst, const void* src) {
    asm volatile("cp.async.cg.shared.global [%0], [%1], 16;"
                 :: "r"(dst), "l"(src) : "memory");
}
__device__ __forceinline__ void cp_commit() {
    asm volatile("cp.async.commit_group;" ::: "memory");
}
__device__ __forceinline__ void cp_wait0() {
    asm volatile("cp.async.wait_group 0;" ::: "memory");
}

// interp 4 channels, split fp16 hi/lo, store 8B to each plane
__device__ __forceinline__ void interp_store4(
    float w00, float w01, float w10, float w11,
    float4 v00, float4 v01, float4 v10, float4 v11,
    char* AH, char* AL, uint32_t off)
{
    float rx = w00 * v00.x + w01 * v01.x + w10 * v10.x + w11 * v11.x;
    float ry = w00 * v00.y + w01 * v01.y + w10 * v10.y + w11 * v11.y;
    float rz = w00 * v00.z + w01 * v01.z + w10 * v10.z + w11 * v11.z;
    float rw = w00 * v00.w + w01 * v01.w + w10 * v10.w + w11 * v11.w;
    __half2 ha = __floats2half2_rn(rx, ry);
    __half2 hb = __floats2half2_rn(rz, rw);
    float2 fa = __half22float2(ha);
    float2 fb = __half22float2(hb);
    __half2 la = __floats2half2_rn(rx - fa.x, ry - fa.y);
    __half2 lb = __floats2half2_rn(rz - fb.x, rw - fb.y);
    uint2 hv = make_uint2(*(uint32_t*)&ha, *(uint32_t*)&hb);
    uint2 lv = make_uint2(*(uint32_t*)&la, *(uint32_t*)&lb);
    *(uint2*)(AH + off) = hv;
    *(uint2*)(AL + off) = lv;
}

// ---------------------------------------------------------------------------
// 1) Transpose x: NCHW -> NHWC
// ---------------------------------------------------------------------------
__global__ void k_transpose(const float* __restrict__ x) {
    __shared__ float tile[32][33];
    int b  = blockIdx.z;
    int c0 = blockIdx.y * 32;
    int p0 = blockIdx.x * 32;
    int tx = threadIdx.x, ty = threadIdx.y;   // (32, 8)
    const float* src = x + (size_t)b * CC * HH * WW;
    float* dst = g_xT + (size_t)b * HH * WW * CC;
#pragma unroll
    for (int i = 0; i < 32; i += 8)
        tile[ty + i][tx] = src[(size_t)(c0 + ty + i) * (HH * WW) + p0 + tx];
    __syncthreads();
#pragma unroll
    for (int i = 0; i < 32; i += 8)
        dst[(size_t)(p0 + ty + i) * CC + c0 + tx] = tile[tx][ty + i];
}

// ---------------------------------------------------------------------------
// 2) Merged weight prep: deform W (items 0..36863) + offset W (36864..55295)
// ---------------------------------------------------------------------------
__global__ void k_wprep2(const float* __restrict__ wd, const float* __restrict__ wo) {
    int i = blockIdx.x * 256 + threadIdx.x;
    if (i < K2 * 64 * 64) {
        int kk = i >> 12;
        int r  = i & 4095;
        int c  = r >> 6;
        int o  = r & 63;
        __half h = __float2half_rn(wd[((size_t)o * CC + c) * K2 + kk]);
        uint32_t off = (uint32_t)c * 128 + (((uint32_t)o * 2) ^ (((uint32_t)c & 7) << 4));
        g_wB[kk][off >> 1] = *(const unsigned short*)&h;
    } else if (i < K2 * 64 * 64 + K2 * 64 * 32) {
        int j = i - K2 * 64 * 64;
        int n  = j & 31;
        int c  = (j >> 5) & 63;
        int kk = j >> 11;
        float val = (n < 18) ? wo[((size_t)n * CC + c) * K2 + kk] : 0.f;
        __half h = __float2half_rn(val);
        uint32_t off = (uint32_t)c * 64 + (((uint32_t)n * 2) ^ (((uint32_t)c & 3) << 4));
        g_wO[kk][off >> 1] = *(const unsigned short*)&h;
    }
}

// ---------------------------------------------------------------------------
// 3) Fused kernel
// ---------------------------------------------------------------------------
__global__ __launch_bounds__(256, 3) void k_fused(float* __restrict__ out) {
    extern __shared__ __align__(16) char sm[];

    int tid  = threadIdx.x;
    int lane = tid & 31;
    int wid  = tid >> 5;

    int pix0 = blockIdx.x * TP;
    int b    = pix0 >> 14;
    int y    = (pix0 & 16383) >> 7;
    int x0   = pix0 & 127;
    const float* xTb = g_xT + (size_t)b * HH * WW * CC;

    uint32_t sbase = smem_u32(sm);
    float* offs_s = (float*)(sm + OFFS_OFF);   // [p][20]

    // ============================ PHASE A ============================
    // entry prefetch: phase-A W chunk 0 AND phase-B W chunk 0 (into WB0 slot)
    {
        const char* srcA = (const char*)&g_wO[0][0];   // 4096 B
        cp16(sbase + WAOFF + tid * 16, srcA + tid * 16);
        const char* srcB = (const char*)&g_wB[0][0];   // 8192 B
#pragma unroll
        for (int i = 0; i < 2; i++) {
            int off = (tid + i * 256) * 16;
            cp16(sbase + WB0_OFF + off, srcB + off);
        }
        cp_commit();
    }

    // stage halo A view once: 3 y-rows x 66 x-rows x 64ch, fp16 hi/lo
    {
        float4 z4 = make_float4(0.f, 0.f, 0.f, 0.f);
        for (int it = tid; it < 3 * 66 * 4; it += 256) {
            int i = it / 264;
            int r = it - i * 264;
            int j = r >> 2;
            int q = r & 3;
            int yy = y - 1 + i;
            int xx = x0 - 1 + j;
            bool v = ((unsigned)yy < (unsigned)HH) && ((unsigned)xx < (unsigned)WW);
            const float4* src = (const float4*)(xTb + (yy * WW + xx) * CC + q * 16);
            uint32_t hi[4], lo[4];
#pragma unroll
            for (int u = 0; u < 2; u++) {
                float4 f0 = v ? src[2 * u] : z4;
                float4 f1 = v ? src[2 * u + 1] : z4;
                __half2 ha = __floats2half2_rn(f0.x, f0.y);
                __half2 hb = __floats2half2_rn(f0.z, f0.w);
                __half2 hc = __floats2half2_rn(f1.x, f1.y);
                __half2 hd = __floats2half2_rn(f1.z, f1.w);
                float2 fa = __half22float2(ha), fb = __half22float2(hb);
                float2 fc = __half22float2(hc), fd = __half22float2(hd);
                __half2 la = __floats2half2_rn(f0.x - fa.x, f0.y - fa.y);
                __half2 lb = __floats2half2_rn(f0.z - fb.x, f0.w - fb.y);
                __half2 lc = __floats2half2_rn(f1.x - fc.x, f1.y - fc.y);
                __half2 ld = __floats2half2_rn(f1.z - fd.x, f1.w - fd.y);
                hi[0] = *(uint32_t*)&ha; hi[1] = *(uint32_t*)&hb;
                hi[2] = *(uint32_t*)&hc; hi[3] = *(uint32_t*)&hd;
                lo[0] = *(uint32_t*)&la; lo[1] = *(uint32_t*)&lb;
                lo[2] = *(uint32_t*)&lc; lo[3] = *(uint32_t*)&ld;
                uint32_t row = (uint32_t)(i * 68 + j);
                uint32_t addr = row * 128 + (((uint32_t)(q * 32 + u * 16)) ^ ((row & 7) << 4));
                *(uint4*)(sm + addr) = *(uint4*)hi;
                *(uint4*)(sm + APLANE + addr) = *(uint4*)lo;
            }
        }
    }
    __syncthreads();

    {
        int m0 = (wid & 3) * 16;
        int n0 = (wid >> 2) * 16;
        int rA = (lane & 7) + 8 * ((lane >> 3) & 1);
        int cg = lane >> 4;
        uint32_t bcol = (((uint32_t)(n0 * 2 + cg * 16)) ^ (((uint32_t)rA & 3) << 4));

        float acc[2][4];
#pragma unroll
        for (int j = 0; j < 2; j++)
#pragma unroll
            for (int q = 0; q < 4; q++) acc[j][q] = 0.f;

        for (int kk = 0; kk < K2; kk++) {
            cp_wait0();
            __syncthreads();
            int buf = kk & 1;
            uint32_t wBase = sbase + WAOFF + buf * 4096;
            if (kk + 1 < K2) {
                int nb = buf ^ 1;
                const char* src = (const char*)&g_wO[kk + 1][0];
                cp16(sbase + WAOFF + nb * 4096 + tid * 16, src + tid * 16);
                cp_commit();
            }
            int ki = kk / 3, kj = kk % 3;
            uint32_t prow = (uint32_t)(ki * 68 + m0 + rA + kj);
            uint32_t arowb = prow * 128;
            uint32_t xorA = (prow & 7) << 4;
#pragma unroll
            for (int ks = 0; ks < 4; ks++) {
                int k0 = ks * 16;
                uint32_t a_hi[4], a_lo[4];
                uint32_t acolb = ((uint32_t)(2 * k0 + cg * 16)) ^ xorA;
                ldsm4(sbase + arowb + acolb, a_hi);
                ldsm4(sbase + APLANE + arowb + acolb, a_lo);
                uint32_t bb[4];
                uint32_t brow = (uint32_t)(k0 + rA) * 64;
                ldsm4t(wBase + brow + bcol, bb);
#pragma unroll
                for (int n8 = 0; n8 < 2; n8++) {
                    const uint32_t* bp = &bb[n8 * 2];
                    mma16816(acc[n8], a_hi, bp);
                    mma16816(acc[n8], a_lo, bp);
                }
            }
        }

        // phase-A epilogue: frags -> offs_s[p][n]
        __syncthreads();
#pragma unroll
        for (int n8 = 0; n8 < 2; n8++) {
            int pr = m0 + (lane >> 2);
            int nn = n0 + n8 * 8 + 2 * (lane & 3);
            if (nn < 18) {
                offs_s[pr * 20 + nn]           = acc[n8][0];
                offs_s[pr * 20 + nn + 1]       = acc[n8][1];
                offs_s[(pr + 8) * 20 + nn]     = acc[n8][2];
                offs_s[(pr + 8) * 20 + nn + 1] = acc[n8][3];
            }
        }
    }
    __syncthreads();

    // ============================ PHASE B ============================
    // smem: AH0=0 AL0=8192 AH1=16384 AL1=24576
    // W slots: chunk 0 -> WB0_OFF; chunk kk>=1 -> 32768 + ((kk-1)&1)*8192.
    // Prefetch cadence: chunk 1 in prologue (slot 0); during iter kk>=1,
    // prefetch chunk kk+1 into slot (kk&1) (held chunk kk-1, consumed).
    int l  = tid & 15;
    int hw = tid >> 4;

    // prologue: prefetch W chunk 1 (halo region now free) + sample chunk 0
    {
        const char* src = (const char*)&g_wB[1][0];
#pragma unroll
        for (int i = 0; i < 2; i++) {
            int off = (tid + i * 256) * 16;
            cp16(sbase + 32768 + off, src + off);
        }
        cp_commit();
    }
    {
        float4 z4 = make_float4(0.f, 0.f, 0.f, 0.f);
#pragma unroll
        for (int pass = 0; pass < 4; pass++) {
            int p = pass * 16 + hw;
            float dy = offs_s[p * 20 + 0];
            float dx = offs_s[p * 20 + 1];
            float ys = (float)(y - 1) + dy;
            float xs = (float)(x0 + p - 1) + dx;
            float y0f = floorf(ys), x0f = floorf(xs);
            float fy = ys - y0f, fx = xs - x0f;
            int iy = (int)y0f, ix = (int)x0f;
            bool vy0 = ((unsigned)iy < (unsigned)HH);
            bool vy1 = ((unsigned)(iy + 1) < (unsigned)HH);
            bool vx0 = ((unsigned)ix < (unsigned)WW);
            bool vx1 = ((unsigned)(ix + 1) < (unsigned)WW);
            float w00 = (1.f - fy) * (1.f - fx);
            float w01 = (1.f - fy) * fx;
            float w10 = fy * (1.f - fx);
            float w11 = fy * fx;
            const float4* bp = (const float4*)(xTb + (iy * WW + ix) * CC) + l;
            float4 v00 = (vy0 && vx0) ? bp[0] : z4;
            float4 v01 = (vy0 && vx1) ? bp[16] : z4;
            float4 v10 = (vy1 && vx0) ? bp[WW * 16] : z4;
            float4 v11 = (vy1 && vx1) ? bp[WW * 16 + 16] : z4;
            uint32_t off = (uint32_t)p * 128 +
                (((uint32_t)(8 * l)) ^ (((uint32_t)p & 7) << 4));
            interp_store4(w00, w01, w10, w11, v00, v01, v10, v11,
                          sm, sm + 8192, off);
        }
    }

    int m0 = (wid & 3) * 16;
    int wn = wid >> 2;
    int rA = (lane & 7) + 8 * ((lane >> 3) & 1);
    int cg = lane >> 4;
    uint32_t xorA0 = ((uint32_t)rA & 7) << 4;
    uint32_t bcol[2];
#pragma unroll
    for (int nt = 0; nt < 2; nt++)
        bcol[nt] = (((uint32_t)(wn * 64 + nt * 32 + cg * 16)) ^ xorA0);

    float acc[4][4];
#pragma unroll
    for (int j = 0; j < 4; j++)
#pragma unroll
        for (int q = 0; q < 4; q++) acc[j][q] = 0.f;

    for (int kk = 0; kk < K2; kk++) {
        cp_wait0();
        __syncthreads();
        int buf = kk & 1;
        uint32_t aHbase = sbase + buf * 16384;
        uint32_t aLbase = aHbase + 8192;
        uint32_t wBase  = (kk == 0) ? (sbase + WB0_OFF)
                                    : (sbase + 32768 + (uint32_t)(((kk - 1) & 1) * 8192));

        bool pre = (kk + 1 < K2);
        int nb = buf ^ 1;
        char* AHn = sm + nb * 16384;
        char* ALn = AHn + 8192;

        int ki = 0, kj = 0;
        float2 offs2[4];
        if (pre) {
            // prefetch W chunk kk+1 into slot (kk&1); chunk 1 already done in prologue.
            if (kk >= 1) {
                const char* src = (const char*)&g_wB[kk + 1][0];
                uint32_t dst = sbase + 32768 + (uint32_t)((kk & 1) * 8192);
#pragma unroll
                for (int i = 0; i < 2; i++) {
                    int off = (tid + i * 256) * 16;
                    cp16(dst + off, src + off);
                }
                cp_commit();
            }
            ki = (kk + 1) / 3;
            kj = (kk + 1) % 3;
#pragma unroll
            for (int s = 0; s < 4; s++) {
                int p = s * 16 + hw;
                offs2[s] = make_float2(offs_s[p * 20 + 2 * (kk + 1)],
                                       offs_s[p * 20 + 2 * (kk + 1) + 1]);
            }
        }

        float4 z4 = make_float4(0.f, 0.f, 0.f, 0.f);
#pragma unroll
        for (int s = 0; s < 4; s++) {
            // --- issue gather LDG.128s for pass s of chunk kk+1 ---
            float4 c00, c01, c10, c11;
            float fy = 0.f, fx = 0.f;
            if (pre) {
                int p = s * 16 + hw;
                float ys = (float)(y - 1 + ki) + offs2[s].x;
                float xs = (float)(x0 + p - 1 + kj) + offs2[s].y;
                float y0f = floorf(ys), x0f = floorf(xs);
                fy = ys - y0f; fx = xs - x0f;
                int iy = (int)y0f, ix = (int)x0f;
                bool vy0 = ((unsigned)iy < (unsigned)HH);
                bool vy1 = ((unsigned)(iy + 1) < (unsigned)HH);
                bool vx0 = ((unsigned)ix < (unsigned)WW);
                bool vx1 = ((unsigned)(ix + 1) < (unsigned)WW);
                const float4* bp = (const float4*)(xTb + (iy * WW + ix) * CC) + l;
                c00 = (vy0 && vx0) ? bp[0] : z4;
                c01 = (vy0 && vx1) ? bp[16] : z4;
                c10 = (vy1 && vx0) ? bp[WW * 16] : z4;
                c11 = (vy1 && vx1) ? bp[WW * 16 + 16] : z4;
            }

            // --- MMA step s on chunk kk ---
            {
                int k0 = s * 16;
                uint32_t a_hi[4], a_lo[4];
                uint32_t acolb = ((uint32_t)(2 * k0 + cg * 16)) ^ xorA0;
                uint32_t arow = (uint32_t)(m0 + rA) * 128;
                ldsm4(aHbase + arow + acolb, a_hi);
                ldsm4(aLbase + arow + acolb, a_lo);
                uint32_t bb[2][4];
                uint32_t brow = (uint32_t)(k0 + rA) * 128;
#pragma unroll
                for (int nt = 0; nt < 2; nt++)
                    ldsm4t(wBase + brow + bcol[nt], bb[nt]);
#pragma unroll
                for (int n8 = 0; n8 < 4; n8++) {
                    const uint32_t* bp = &bb[n8 >> 1][(n8 & 1) * 2];
                    mma16816(acc[n8], a_hi, bp);
                    mma16816(acc[n8], a_lo, bp);
                }
            }

            // --- interp + STS pass s to next buffers ---
            if (pre) {
                int p = s * 16 + hw;
                float w00 = (1.f - fy) * (1.f - fx);
                float w01 = (1.f - fy) * fx;
                float w10 = fy * (1.f - fx);
                float w11 = fy * fx;
                uint32_t off = (uint32_t)p * 128 +
                    (((uint32_t)(8 * l)) ^ (((uint32_t)p & 7) << 4));
                interp_store4(w00, w01, w10, w11, c00, c01, c10, c11,
                              AHn, ALn, off);
            }
        }
    }

    // ---- epilogue ----
    __syncthreads();
    float* Sd = (float*)sm;
#pragma unroll
    for (int n8 = 0; n8 < 4; n8++) {
        int pr = m0 + (lane >> 2);
        int o0 = wn * 32 + n8 * 8 + 2 * (lane & 3);
        float* bse = Sd + o0 * PD;
        bse[pr]          = acc[n8][0];
        bse[PD + pr]     = acc[n8][1];
        bse[pr + 8]      = acc[n8][2];
        bse[PD + pr + 8] = acc[n8][3];
    }
    __syncthreads();

    size_t obase = (size_t)b * COUT * (HH * WW) + (size_t)y * WW + x0;
#pragma unroll
    for (int i = tid; i < 64 * 16; i += 256) {
        int o  = i >> 4;
        int pq = i & 15;
        float4 v = *(const float4*)&Sd[o * PD + pq * 4];
        *(float4*)(out + obase + (size_t)o * (HH * WW) + pq * 4) = v;
    }
}

// ---------------------------------------------------------------------------
extern "C" void kernel_launch(void* const* d_in, const int* in_sizes, int n_in,
                              void* d_out, int out_size) {
    const float* x  = (const float*)d_in[0];
    const float* wo = (const float*)d_in[1];
    const float* wd = (const float*)d_in[2];
    float* out = (float*)d_out;

    cudaFuncSetAttribute(k_fused, cudaFuncAttributeMaxDynamicSharedMemorySize,
                         SMEM_TOTAL);

    dim3 tb(32, 8);
    dim3 tg(HH * WW / 32, CC / 32, BB);
    k_transpose<<<tg, tb>>>(x);

    k_wprep2<<<(K2 * 64 * 64 + K2 * 64 * 32 + 255) / 256, 256>>>(wd, wo);

    k_fused<<<NPIX / TP, 256, SMEM_TOTAL>>>(out);
}

// round 15
// speedup vs baseline: 5.7598x; 1.1531x over previous
#include <cuda_runtime.h>
#include <cuda_fp16.h>
#include <cstdint>

#define HH 128
#define WW 128
#define CC 64
#define BB 4
#define COUT 64
#define K2 9
#define NPIX (BB * HH * WW)   // 65536
#define TP 64                 // pixels per block
#define PD 68                 // epilogue smem pitch (floats)

// smem layout (audited, non-overlapping):
//  Phase A: halo [0,26112) ; WA 2x4096 [26112,34304)
//  WB0 (phase-B chunk-0 W, written at entry, read at B kk=0): [34304,42496)
//  Phase B: AH0=0 AL0=8192 AH1=16384 AL1=24576 ; WSLOT 2x8192 [42496,58880)
//  offs_s: [58880,64000)
#define HALO_ROWS 68          // pitch rows per y-line (66 used)
#define WAOFF   26112
#define WB0_OFF 34304
#define WSLOT   42496
#define OFFS_OFF 58880
#define SMEM_TOTAL 64000

// Scratch (device globals)
__device__ __align__(16) __half g_xTh[BB * HH * WW * CC];     // x as (b,y,x,c), fp16
__device__ __align__(16) unsigned short g_wB[K2][64 * 64];    // deform W fp16, swizzled [c rows 128B][o]
__device__ __align__(16) unsigned short g_wO[K2][64 * 32];    // offset W fp16, swizzled [c rows 64B][n]

// ---- helpers ---------------------------------------------------------------
__device__ __forceinline__ uint32_t smem_u32(const void* p) {
    uint32_t a;
    asm("{ .reg .u64 t; cvta.to.shared.u64 t, %1; cvt.u32.u64 %0, t; }" : "=r"(a) : "l"(p));
    return a;
}
__device__ __forceinline__ void ldsm4(uint32_t addr, uint32_t* r) {
    asm volatile("ldmatrix.sync.aligned.m8n8.x4.shared.b16 {%0,%1,%2,%3}, [%4];"
                 : "=r"(r[0]), "=r"(r[1]), "=r"(r[2]), "=r"(r[3]) : "r"(addr));
}
__device__ __forceinline__ void ldsm4t(uint32_t addr, uint32_t* r) {
    asm volatile("ldmatrix.sync.aligned.m8n8.x4.trans.shared.b16 {%0,%1,%2,%3}, [%4];"
                 : "=r"(r[0]), "=r"(r[1]), "=r"(r[2]), "=r"(r[3]) : "r"(addr));
}
__device__ __forceinline__ void mma16816(float* d, const uint32_t* a, const uint32_t* b) {
    asm volatile(
        "mma.sync.aligned.m16n8k16.row.col.f32.f16.f16.f32 "
        "{%0,%1,%2,%3}, {%4,%5,%6,%7}, {%8,%9}, {%0,%1,%2,%3};"
        : "+f"(d[0]), "+f"(d[1]), "+f"(d[2]), "+f"(d[3])
        : "r"(a[0]), "r"(a[1]), "r"(a[2]), "r"(a[3]), "r"(b[0]), "r"(b[1]));
}
__device__ __forceinline__ void cp16(uint32_t dst, const void* src) {
    asm volatile("cp.async.cg.shared.global [%0], [%1], 16;"
                 :: "r"(dst), "l"(src) : "memory");
}
__device__ __forceinline__ void cp_commit() {
    asm volatile("cp.async.commit_group;" ::: "memory");
}
__device__ __forceinline__ void cp_wait0() {
    asm volatile("cp.async.wait_group 0;" ::: "memory");
}

// interp 4 channels from fp16 corners, split fp16 hi/lo, store 8B per plane
__device__ __forceinline__ void interp_store4h(
    float w00, float w01, float w10, float w11,
    uint2 r00, uint2 r01, uint2 r10, uint2 r11,
    char* AH, char* AL, uint32_t off)
{
    float2 a00 = __half22float2(*(__half2*)&r00.x);
    float2 b00 = __half22float2(*(__half2*)&r00.y);
    float2 a01 = __half22float2(*(__half2*)&r01.x);
    float2 b01 = __half22float2(*(__half2*)&r01.y);
    float2 a10 = __half22float2(*(__half2*)&r10.x);
    float2 b10 = __half22float2(*(__half2*)&r10.y);
    float2 a11 = __half22float2(*(__half2*)&r11.x);
    float2 b11 = __half22float2(*(__half2*)&r11.y);
    float rx = w00 * a00.x + w01 * a01.x + w10 * a10.x + w11 * a11.x;
    float ry = w00 * a00.y + w01 * a01.y + w10 * a10.y + w11 * a11.y;
    float rz = w00 * b00.x + w01 * b01.x + w10 * b10.x + w11 * b11.x;
    float rw = w00 * b00.y + w01 * b01.y + w10 * b10.y + w11 * b11.y;
    __half2 ha = __floats2half2_rn(rx, ry);
    __half2 hb = __floats2half2_rn(rz, rw);
    float2 fa = __half22float2(ha);
    float2 fb = __half22float2(hb);
    __half2 la = __floats2half2_rn(rx - fa.x, ry - fa.y);
    __half2 lb = __floats2half2_rn(rz - fb.x, rw - fb.y);
    uint2 hv = make_uint2(*(uint32_t*)&ha, *(uint32_t*)&hb);
    uint2 lv = make_uint2(*(uint32_t*)&la, *(uint32_t*)&lb);
    *(uint2*)(AH + off) = hv;
    *(uint2*)(AL + off) = lv;
}

// ---------------------------------------------------------------------------
// 1) Transpose x: NCHW fp32 -> NHWC fp16
// ---------------------------------------------------------------------------
__global__ void k_transpose(const float* __restrict__ x) {
    __shared__ float tile[32][33];
    int b  = blockIdx.z;
    int c0 = blockIdx.y * 32;
    int p0 = blockIdx.x * 32;
    int tx = threadIdx.x, ty = threadIdx.y;   // (32, 8)
    int tid = ty * 32 + tx;
    const float* src = x + (size_t)b * CC * HH * WW;
    __half* dst = g_xTh + (size_t)b * HH * WW * CC;
#pragma unroll
    for (int i = 0; i < 32; i += 8)
        tile[ty + i][tx] = src[(size_t)(c0 + ty + i) * (HH * WW) + p0 + tx];
    __syncthreads();
    // 512 half2 items: pp = item>>4 (pixel), cc = item&15 (channel pair)
    for (int it = tid; it < 512; it += 256) {
        int pp = it >> 4;
        int cc = it & 15;
        __half2 v = __floats2half2_rn(tile[2 * cc][pp], tile[2 * cc + 1][pp]);
        *(__half2*)(dst + (size_t)(p0 + pp) * CC + c0 + 2 * cc) = v;
    }
}

// ---------------------------------------------------------------------------
// 2) Merged weight prep: deform W + offset W (fp16, swizzled)
// ---------------------------------------------------------------------------
__global__ void k_wprep2(const float* __restrict__ wd, const float* __restrict__ wo) {
    int i = blockIdx.x * 256 + threadIdx.x;
    if (i < K2 * 64 * 64) {
        int kk = i >> 12;
        int r  = i & 4095;
        int c  = r >> 6;
        int o  = r & 63;
        __half h = __float2half_rn(wd[((size_t)o * CC + c) * K2 + kk]);
        uint32_t off = (uint32_t)c * 128 + (((uint32_t)o * 2) ^ (((uint32_t)c & 7) << 4));
        g_wB[kk][off >> 1] = *(const unsigned short*)&h;
    } else if (i < K2 * 64 * 64 + K2 * 64 * 32) {
        int j = i - K2 * 64 * 64;
        int n  = j & 31;
        int c  = (j >> 5) & 63;
        int kk = j >> 11;
        float val = (n < 18) ? wo[((size_t)n * CC + c) * K2 + kk] : 0.f;
        __half h = __float2half_rn(val);
        uint32_t off = (uint32_t)c * 64 + (((uint32_t)n * 2) ^ (((uint32_t)c & 3) << 4));
        g_wO[kk][off >> 1] = *(const unsigned short*)&h;
    }
}

// ---------------------------------------------------------------------------
// 3) Fused kernel
// ---------------------------------------------------------------------------
__global__ __launch_bounds__(256, 3) void k_fused(float* __restrict__ out) {
    extern __shared__ __align__(16) char sm[];

    int tid  = threadIdx.x;
    int lane = tid & 31;
    int wid  = tid >> 5;

    int pix0 = blockIdx.x * TP;
    int b    = pix0 >> 14;
    int y    = (pix0 & 16383) >> 7;
    int x0   = pix0 & 127;
    const __half* xTb = g_xTh + (size_t)b * HH * WW * CC;

    uint32_t sbase = smem_u32(sm);
    float* offs_s = (float*)(sm + OFFS_OFF);   // [p][20]

    // ============================ PHASE A ============================
    // entry prefetch: phase-A W chunk 0 + phase-B W chunk 0 (WB0 slot)
    {
        const char* srcA = (const char*)&g_wO[0][0];   // 4096 B
        cp16(sbase + WAOFF + tid * 16, srcA + tid * 16);
        const char* srcB = (const char*)&g_wB[0][0];   // 8192 B
#pragma unroll
        for (int i = 0; i < 2; i++) {
            int off = (tid + i * 256) * 16;
            cp16(sbase + WB0_OFF + off, srcB + off);
        }
        cp_commit();
    }

    // stage halo once: 3 y-rows x 66 x-rows x 64ch fp16 (single plane, exact)
    {
        uint4 z4 = make_uint4(0u, 0u, 0u, 0u);
        for (int it = tid; it < 3 * 66 * 8; it += 256) {   // 16B chunks (8 ch)
            int i  = it / 528;
            int r  = it - i * 528;
            int j  = r >> 3;
            int q8 = r & 7;
            int yy = y - 1 + i;
            int xx = x0 - 1 + j;
            bool v = ((unsigned)yy < (unsigned)HH) && ((unsigned)xx < (unsigned)WW);
            uint4 val = v ? *(const uint4*)(xTb + (yy * WW + xx) * CC + q8 * 8) : z4;
            uint32_t row = (uint32_t)(i * HALO_ROWS + j);
            uint32_t addr = row * 128 + (((uint32_t)(q8 * 16)) ^ ((row & 7) << 4));
            *(uint4*)(sm + addr) = val;
        }
    }
    __syncthreads();

    {
        int m0 = (wid & 3) * 16;
        int n0 = (wid >> 2) * 16;
        int rA = (lane & 7) + 8 * ((lane >> 3) & 1);
        int cg = lane >> 4;
        uint32_t bcol = (((uint32_t)(n0 * 2 + cg * 16)) ^ (((uint32_t)rA & 3) << 4));

        float acc[2][4];
#pragma unroll
        for (int j = 0; j < 2; j++)
#pragma unroll
            for (int q = 0; q < 4; q++) acc[j][q] = 0.f;

        for (int kk = 0; kk < K2; kk++) {
            cp_wait0();
            __syncthreads();
            int buf = kk & 1;
            uint32_t wBase = sbase + WAOFF + buf * 4096;
            if (kk + 1 < K2) {
                int nb = buf ^ 1;
                const char* src = (const char*)&g_wO[kk + 1][0];
                cp16(sbase + WAOFF + nb * 4096 + tid * 16, src + tid * 16);
                cp_commit();
            }
            int ki = kk / 3, kj = kk % 3;
            uint32_t prow = (uint32_t)(ki * HALO_ROWS + m0 + rA + kj);
            uint32_t arowb = prow * 128;
            uint32_t xorA = (prow & 7) << 4;
#pragma unroll
            for (int ks = 0; ks < 4; ks++) {
                int k0 = ks * 16;
                uint32_t aa[4];
                uint32_t acolb = ((uint32_t)(2 * k0 + cg * 16)) ^ xorA;
                ldsm4(sbase + arowb + acolb, aa);
                uint32_t bb[4];
                uint32_t brow = (uint32_t)(k0 + rA) * 64;
                ldsm4t(wBase + brow + bcol, bb);
#pragma unroll
                for (int n8 = 0; n8 < 2; n8++)
                    mma16816(acc[n8], aa, &bb[n8 * 2]);
            }
        }

        // phase-A epilogue: frags -> offs_s[p][n]
        __syncthreads();
#pragma unroll
        for (int n8 = 0; n8 < 2; n8++) {
            int pr = m0 + (lane >> 2);
            int nn = n0 + n8 * 8 + 2 * (lane & 3);
            if (nn < 18) {
                offs_s[pr * 20 + nn]           = acc[n8][0];
                offs_s[pr * 20 + nn + 1]       = acc[n8][1];
                offs_s[(pr + 8) * 20 + nn]     = acc[n8][2];
                offs_s[(pr + 8) * 20 + nn + 1] = acc[n8][3];
            }
        }
    }
    __syncthreads();

    // ============================ PHASE B ============================
    int l  = tid & 15;
    int hw = tid >> 4;

    // prologue: prefetch W chunk 1 + sample chunk 0
    {
        const char* src = (const char*)&g_wB[1][0];
#pragma unroll
        for (int i = 0; i < 2; i++) {
            int off = (tid + i * 256) * 16;
            cp16(sbase + WSLOT + off, src + off);
        }
        cp_commit();
    }
    {
        uint2 z2 = make_uint2(0u, 0u);
#pragma unroll
        for (int pass = 0; pass < 4; pass++) {
            int p = pass * 16 + hw;
            float dy = offs_s[p * 20 + 0];
            float dx = offs_s[p * 20 + 1];
            float ys = (float)(y - 1) + dy;
            float xs = (float)(x0 + p - 1) + dx;
            float y0f = floorf(ys), x0f = floorf(xs);
            float fy = ys - y0f, fx = xs - x0f;
            int iy = (int)y0f, ix = (int)x0f;
            bool vy0 = ((unsigned)iy < (unsigned)HH);
            bool vy1 = ((unsigned)(iy + 1) < (unsigned)HH);
            bool vx0 = ((unsigned)ix < (unsigned)WW);
            bool vx1 = ((unsigned)(ix + 1) < (unsigned)WW);
            float w00 = (1.f - fy) * (1.f - fx);
            float w01 = (1.f - fy) * fx;
            float w10 = fy * (1.f - fx);
            float w11 = fy * fx;
            const uint2* bp = (const uint2*)(xTb + (iy * WW + ix) * CC) + l;
            uint2 r00 = (vy0 && vx0) ? bp[0] : z2;
            uint2 r01 = (vy0 && vx1) ? bp[16] : z2;
            uint2 r10 = (vy1 && vx0) ? bp[WW * 16] : z2;
            uint2 r11 = (vy1 && vx1) ? bp[WW * 16 + 16] : z2;
            uint32_t off = (uint32_t)p * 128 +
                (((uint32_t)(8 * l)) ^ (((uint32_t)p & 7) << 4));
            interp_store4h(w00, w01, w10, w11, r00, r01, r10, r11,
                           sm, sm + 8192, off);
        }
    }

    int m0 = (wid & 3) * 16;
    int wn = wid >> 2;
    int rA = (lane & 7) + 8 * ((lane >> 3) & 1);
    int cg = lane >> 4;
    uint32_t xorA0 = ((uint32_t)rA & 7) << 4;
    uint32_t bcol[2];
#pragma unroll
    for (int nt = 0; nt < 2; nt++)
        bcol[nt] = (((uint32_t)(wn * 64 + nt * 32 + cg * 16)) ^ xorA0);

    float acc[4][4];
#pragma unroll
    for (int j = 0; j < 4; j++)
#pragma unroll
        for (int q = 0; q < 4; q++) acc[j][q] = 0.f;

    for (int kk = 0; kk < K2; kk++) {
        cp_wait0();
        __syncthreads();
        int buf = kk & 1;
        uint32_t aHbase = sbase + buf * 16384;
        uint32_t aLbase = aHbase + 8192;
        uint32_t wBase  = (kk == 0) ? (sbase + WB0_OFF)
                                    : (sbase + WSLOT + (uint32_t)(((kk - 1) & 1) * 8192));

        bool pre = (kk + 1 < K2);
        int nb = buf ^ 1;
        char* AHn = sm + nb * 16384;
        char* ALn = AHn + 8192;

        int ki = 0, kj = 0;
        float2 offs2[4];
        if (pre) {
            if (kk >= 1) {   // chunk kk+1 into slot (kk&1); chunk 1 done in prologue
                const char* src = (const char*)&g_wB[kk + 1][0];
                uint32_t dst = sbase + WSLOT + (uint32_t)((kk & 1) * 8192);
#pragma unroll
                for (int i = 0; i < 2; i++) {
                    int off = (tid + i * 256) * 16;
                    cp16(dst + off, src + off);
                }
                cp_commit();
            }
            ki = (kk + 1) / 3;
            kj = (kk + 1) % 3;
#pragma unroll
            for (int s = 0; s < 4; s++) {
                int p = s * 16 + hw;
                offs2[s] = make_float2(offs_s[p * 20 + 2 * (kk + 1)],
                                       offs_s[p * 20 + 2 * (kk + 1) + 1]);
            }
        }

        uint2 z2 = make_uint2(0u, 0u);
#pragma unroll
        for (int s = 0; s < 4; s++) {
            // --- issue gather LDG.64s for pass s of chunk kk+1 ---
            uint2 r00, r01, r10, r11;
            float fy = 0.f, fx = 0.f;
            if (pre) {
                int p = s * 16 + hw;
                float ys = (float)(y - 1 + ki) + offs2[s].x;
                float xs = (float)(x0 + p - 1 + kj) + offs2[s].y;
                float y0f = floorf(ys), x0f = floorf(xs);
                fy = ys - y0f; fx = xs - x0f;
                int iy = (int)y0f, ix = (int)x0f;
                bool vy0 = ((unsigned)iy < (unsigned)HH);
                bool vy1 = ((unsigned)(iy + 1) < (unsigned)HH);
                bool vx0 = ((unsigned)ix < (unsigned)WW);
                bool vx1 = ((unsigned)(ix + 1) < (unsigned)WW);
                const uint2* bp = (const uint2*)(xTb + (iy * WW + ix) * CC) + l;
                r00 = (vy0 && vx0) ? bp[0] : z2;
                r01 = (vy0 && vx1) ? bp[16] : z2;
                r10 = (vy1 && vx0) ? bp[WW * 16] : z2;
                r11 = (vy1 && vx1) ? bp[WW * 16 + 16] : z2;
            }

            // --- MMA step s on chunk kk ---
            {
                int k0 = s * 16;
                uint32_t a_hi[4], a_lo[4];
                uint32_t acolb = ((uint32_t)(2 * k0 + cg * 16)) ^ xorA0;
                uint32_t arow = (uint32_t)(m0 + rA) * 128;
                ldsm4(aHbase + arow + acolb, a_hi);
                ldsm4(aLbase + arow + acolb, a_lo);
                uint32_t bb[2][4];
                uint32_t brow = (uint32_t)(k0 + rA) * 128;
#pragma unroll
                for (int nt = 0; nt < 2; nt++)
                    ldsm4t(wBase + brow + bcol[nt], bb[nt]);
#pragma unroll
                for (int n8 = 0; n8 < 4; n8++) {
                    const uint32_t* bp2 = &bb[n8 >> 1][(n8 & 1) * 2];
                    mma16816(acc[n8], a_hi, bp2);
                    mma16816(acc[n8], a_lo, bp2);
                }
            }

            // --- interp + STS pass s to next buffers ---
            if (pre) {
                int p = s * 16 + hw;
                float w00 = (1.f - fy) * (1.f - fx);
                float w01 = (1.f - fy) * fx;
                float w10 = fy * (1.f - fx);
                float w11 = fy * fx;
                uint32_t off = (uint32_t)p * 128 +
                    (((uint32_t)(8 * l)) ^ (((uint32_t)p & 7) << 4));
                interp_store4h(w00, w01, w10, w11, r00, r01, r10, r11,
                               AHn, ALn, off);
            }
        }
    }

    // ---- epilogue ----
    __syncthreads();
    float* Sd = (float*)sm;
#pragma unroll
    for (int n8 = 0; n8 < 4; n8++) {
        int pr = m0 + (lane >> 2);
        int o0 = wn * 32 + n8 * 8 + 2 * (lane & 3);
        float* bse = Sd + o0 * PD;
        bse[pr]          = acc[n8][0];
        bse[PD + pr]     = acc[n8][1];
        bse[pr + 8]      = acc[n8][2];
        bse[PD + pr + 8] = acc[n8][3];
    }
    __syncthreads();

    size_t obase = (size_t)b * COUT * (HH * WW) + (size_t)y * WW + x0;
#pragma unroll
    for (int i = tid; i < 64 * 16; i += 256) {
        int o  = i >> 4;
        int pq = i & 15;
        float4 v = *(const float4*)&Sd[o * PD + pq * 4];
        *(float4*)(out + obase + (size_t)o * (HH * WW) + pq * 4) = v;
    }
}

// ---------------------------------------------------------------------------
extern "C" void kernel_launch(void* const* d_in, const int* in_sizes, int n_in,
                              void* d_out, int out_size) {
    const float* x  = (const float*)d_in[0];
    const float* wo = (const float*)d_in[1];
    const float* wd = (const float*)d_in[2];
    float* out = (float*)d_out;

    cudaFuncSetAttribute(k_fused, cudaFuncAttributeMaxDynamicSharedMemorySize,
                         SMEM_TOTAL);

    dim3 tb(32, 8);
    dim3 tg(HH * WW / 32, CC / 32, BB);
    k_transpose<<<tg, tb>>>(x);

    k_wprep2<<<(K2 * 64 * 64 + K2 * 64 * 32 + 255) / 256, 256>>>(wd, wo);

    k_fused<<<NPIX / TP, 256, SMEM_TOTAL>>>(out);
}

// round 17
// speedup vs baseline: 5.8094x; 1.0086x over previous
#include <cuda_runtime.h>
#include <cuda_fp16.h>
#include <cstdint>

#define HH 128
#define WW 128
#define CC 64
#define BB 4
#define COUT 64
#define K2 9
#define NPIX (BB * HH * WW)   // 65536
#define TP 64                 // pixels per block
#define PD 68                 // epilogue smem pitch (floats)

// smem layout (audited, non-overlapping):
//  Phase A: halo [0,26112) ; WA_ALL (all 9 offset-W chunks) [26112,62976)
//  offs_s: [62976,68096)
//  Phase B: AH0=0 AL0=8192 AH1=16384 AL1=24576 ; WSLOT 2x8192 [32768,49152)
//  Epilogue Sd: [0,17408) (post-barrier reuse of A buffers)
#define HALO_ROWS 68          // pitch rows per y-line (66 used)
#define WAOFF   26112
#define OFFS_OFF 62976
#define WSLOT   32768
#define SMEM_TOTAL 68096

// Scratch (device globals)
__device__ __align__(16) __half g_xTh[BB * HH * WW * CC];     // x as (b,y,x,c), fp16
__device__ __align__(16) unsigned short g_wB[K2][64 * 64];    // deform W fp16, swizzled [c rows 128B][o]
__device__ __align__(16) unsigned short g_wO[K2][64 * 32];    // offset W fp16, swizzled [c rows 64B][n]

// ---- helpers ---------------------------------------------------------------
__device__ __forceinline__ uint32_t smem_u32(const void* p) {
    uint32_t a;
    asm("{ .reg .u64 t; cvta.to.shared.u64 t, %1; cvt.u32.u64 %0, t; }" : "=r"(a) : "l"(p));
    return a;
}
__device__ __forceinline__ void ldsm4(uint32_t addr, uint32_t* r) {
    asm volatile("ldmatrix.sync.aligned.m8n8.x4.shared.b16 {%0,%1,%2,%3}, [%4];"
                 : "=r"(r[0]), "=r"(r[1]), "=r"(r[2]), "=r"(r[3]) : "r"(addr));
}
__device__ __forceinline__ void ldsm4t(uint32_t addr, uint32_t* r) {
    asm volatile("ldmatrix.sync.aligned.m8n8.x4.trans.shared.b16 {%0,%1,%2,%3}, [%4];"
                 : "=r"(r[0]), "=r"(r[1]), "=r"(r[2]), "=r"(r[3]) : "r"(addr));
}
__device__ __forceinline__ void mma16816(float* d, const uint32_t* a, const uint32_t* b) {
    asm volatile(
        "mma.sync.aligned.m16n8k16.row.col.f32.f16.f16.f32 "
        "{%0,%1,%2,%3}, {%4,%5,%6,%7}, {%8,%9}, {%0,%1,%2,%3};"
        : "+f"(d[0]), "+f"(d[1]), "+f"(d[2]), "+f"(d[3])
        : "r"(a[0]), "r"(a[1]), "r"(a[2]), "r"(a[3]), "r"(b[0]), "r"(b[1]));
}
__device__ __forceinline__ void cp16(uint32_t dst, const void* src) {
    asm volatile("cp.async.cg.shared.global [%0], [%1], 16;"
                 :: "r"(dst), "l"(src) : "memory");
}
__device__ __forceinline__ void cp_commit() {
    asm volatile("cp.async.commit_group;" ::: "memory");
}
__device__ __forceinline__ void cp_wait0() {
    asm volatile("cp.async.wait_group 0;" ::: "memory");
}

// interp 4 channels from fp16 corners, split fp16 hi/lo, store 8B per plane
__device__ __forceinline__ void interp_store4h(
    float w00, float w01, float w10, float w11,
    uint2 r00, uint2 r01, uint2 r10, uint2 r11,
    char* AH, char* AL, uint32_t off)
{
    float2 a00 = __half22float2(*(__half2*)&r00.x);
    float2 b00 = __half22float2(*(__half2*)&r00.y);
    float2 a01 = __half22float2(*(__half2*)&r01.x);
    float2 b01 = __half22float2(*(__half2*)&r01.y);
    float2 a10 = __half22float2(*(__half2*)&r10.x);
    float2 b10 = __half22float2(*(__half2*)&r10.y);
    float2 a11 = __half22float2(*(__half2*)&r11.x);
    float2 b11 = __half22float2(*(__half2*)&r11.y);
    float rx = w00 * a00.x + w01 * a01.x + w10 * a10.x + w11 * a11.x;
    float ry = w00 * a00.y + w01 * a01.y + w10 * a10.y + w11 * a11.y;
    float rz = w00 * b00.x + w01 * b01.x + w10 * b10.x + w11 * b11.x;
    float rw = w00 * b00.y + w01 * b01.y + w10 * b10.y + w11 * b11.y;
    __half2 ha = __floats2half2_rn(rx, ry);
    __half2 hb = __floats2half2_rn(rz, rw);
    float2 fa = __half22float2(ha);
    float2 fb = __half22float2(hb);
    __half2 la = __floats2half2_rn(rx - fa.x, ry - fa.y);
    __half2 lb = __floats2half2_rn(rz - fb.x, rw - fb.y);
    uint2 hv = make_uint2(*(uint32_t*)&ha, *(uint32_t*)&hb);
    uint2 lv = make_uint2(*(uint32_t*)&la, *(uint32_t*)&lb);
    *(uint2*)(AH + off) = hv;
    *(uint2*)(AL + off) = lv;
}

// ---------------------------------------------------------------------------
// 1) Transpose x: NCHW fp32 -> NHWC fp16 (uint2 coalesced stores)
// ---------------------------------------------------------------------------
__global__ void k_transpose(const float* __restrict__ x) {
    __shared__ float tile[32][33];
    int b  = blockIdx.z;
    int c0 = blockIdx.y * 32;
    int p0 = blockIdx.x * 32;
    int tx = threadIdx.x, ty = threadIdx.y;   // (32, 8)
    int tid = ty * 32 + tx;
    const float* src = x + (size_t)b * CC * HH * WW;
    __half* dst = g_xTh + (size_t)b * HH * WW * CC;
#pragma unroll
    for (int i = 0; i < 32; i += 8)
        tile[ty + i][tx] = src[(size_t)(c0 + ty + i) * (HH * WW) + p0 + tx];
    __syncthreads();
    // one uint2 (4 channels) per thread: pp = tid>>3 (32 px), q = tid&7 (8 x 4ch)
    {
        int pp = tid >> 3;
        int q  = tid & 7;
        __half2 h[2];
#pragma unroll
        for (int j = 0; j < 2; j++) {
            int c = 4 * q + 2 * j;   // <= 30
            h[j] = __floats2half2_rn(tile[c][pp], tile[c + 1][pp]);
        }
        *(uint2*)(dst + (size_t)(p0 + pp) * CC + c0 + 4 * q) = *(uint2*)h;
    }
}

// ---------------------------------------------------------------------------
// 2) Merged weight prep: deform W + offset W (fp16, swizzled)
// ---------------------------------------------------------------------------
__global__ void k_wprep2(const float* __restrict__ wd, const float* __restrict__ wo) {
    int i = blockIdx.x * 256 + threadIdx.x;
    if (i < K2 * 64 * 64) {
        int kk = i >> 12;
        int r  = i & 4095;
        int c  = r >> 6;
        int o  = r & 63;
        __half h = __float2half_rn(wd[((size_t)o * CC + c) * K2 + kk]);
        uint32_t off = (uint32_t)c * 128 + (((uint32_t)o * 2) ^ (((uint32_t)c & 7) << 4));
        g_wB[kk][off >> 1] = *(const unsigned short*)&h;
    } else if (i < K2 * 64 * 64 + K2 * 64 * 32) {
        int j = i - K2 * 64 * 64;
        int n  = j & 31;
        int c  = (j >> 5) & 63;
        int kk = j >> 11;
        float val = (n < 18) ? wo[((size_t)n * CC + c) * K2 + kk] : 0.f;
        __half h = __float2half_rn(val);
        uint32_t off = (uint32_t)c * 64 + (((uint32_t)n * 2) ^ (((uint32_t)c & 3) << 4));
        g_wO[kk][off >> 1] = *(const unsigned short*)&h;
    }
}

// ---------------------------------------------------------------------------
// 3) Fused kernel
// ---------------------------------------------------------------------------
__global__ __launch_bounds__(256, 3) void k_fused(float* __restrict__ out) {
    extern __shared__ __align__(16) char sm[];

    int tid  = threadIdx.x;
    int lane = tid & 31;
    int wid  = tid >> 5;

    int pix0 = blockIdx.x * TP;
    int b    = pix0 >> 14;
    int y    = (pix0 & 16383) >> 7;
    int x0   = pix0 & 127;
    const __half* xTb = g_xTh + (size_t)b * HH * WW * CC;

    uint32_t sbase = smem_u32(sm);
    float* offs_s = (float*)(sm + OFFS_OFF);   // [p][20]

    // ============================ PHASE A ============================
    // entry prefetch: ALL 9 offset-W chunks (36,864 B flat)
    {
        const char* srcA = (const char*)&g_wO[0][0];
#pragma unroll
        for (int i = 0; i < 9; i++) {
            int off = (tid + i * 256) * 16;
            cp16(sbase + WAOFF + off, srcA + off);
        }
        cp_commit();
    }

    // stage halo once: 3 y-rows x 66 x-rows x 64ch fp16 (single plane, exact)
    {
        uint4 z4 = make_uint4(0u, 0u, 0u, 0u);
        for (int it = tid; it < 3 * 66 * 8; it += 256) {   // 16B chunks (8 ch)
            int i  = it / 528;
            int r  = it - i * 528;
            int j  = r >> 3;
            int q8 = r & 7;
            int yy = y - 1 + i;
            int xx = x0 - 1 + j;
            bool v = ((unsigned)yy < (unsigned)HH) && ((unsigned)xx < (unsigned)WW);
            uint4 val = v ? *(const uint4*)(xTb + (yy * WW + xx) * CC + q8 * 8) : z4;
            uint32_t row = (uint32_t)(i * HALO_ROWS + j);
            uint32_t addr = row * 128 + (((uint32_t)(q8 * 16)) ^ ((row & 7) << 4));
            *(uint4*)(sm + addr) = val;
        }
    }
    cp_wait0();
    __syncthreads();

    {
        int m0 = (wid & 3) * 16;
        int n0 = (wid >> 2) * 16;
        int rA = (lane & 7) + 8 * ((lane >> 3) & 1);
        int cg = lane >> 4;
        uint32_t bcol = (((uint32_t)(n0 * 2 + cg * 16)) ^ (((uint32_t)rA & 3) << 4));

        float acc[2][4];
#pragma unroll
        for (int j = 0; j < 2; j++)
#pragma unroll
            for (int q = 0; q < 4; q++) acc[j][q] = 0.f;

        // straight-line: no barriers, all W resident, halo read-only
#pragma unroll
        for (int kk = 0; kk < K2; kk++) {
            uint32_t wBase = sbase + WAOFF + (uint32_t)kk * 4096;
            int ki = kk / 3, kj = kk % 3;
            uint32_t prow = (uint32_t)(ki * HALO_ROWS + m0 + rA + kj);
            uint32_t arowb = prow * 128;
            uint32_t xorA = (prow & 7) << 4;
#pragma unroll
            for (int ks = 0; ks < 4; ks++) {
                int k0 = ks * 16;
                uint32_t aa[4];
                uint32_t acolb = ((uint32_t)(2 * k0 + cg * 16)) ^ xorA;
                ldsm4(sbase + arowb + acolb, aa);
                uint32_t bb[4];
                uint32_t brow = (uint32_t)(k0 + rA) * 64;
                ldsm4t(wBase + brow + bcol, bb);
#pragma unroll
                for (int n8 = 0; n8 < 2; n8++)
                    mma16816(acc[n8], aa, &bb[n8 * 2]);
            }
        }

        // phase-A epilogue: frags -> offs_s[p][n] (disjoint region)
#pragma unroll
        for (int n8 = 0; n8 < 2; n8++) {
            int pr = m0 + (lane >> 2);
            int nn = n0 + n8 * 8 + 2 * (lane & 3);
            if (nn < 18) {
                offs_s[pr * 20 + nn]           = acc[n8][0];
                offs_s[pr * 20 + nn + 1]       = acc[n8][1];
                offs_s[(pr + 8) * 20 + nn]     = acc[n8][2];
                offs_s[(pr + 8) * 20 + nn + 1] = acc[n8][3];
            }
        }
    }
    __syncthreads();

    // ============================ PHASE B ============================
    int l  = tid & 15;
    int hw = tid >> 4;

    // prologue: prefetch W chunk 0 into slot 0 + sample chunk 0
    {
        const char* src = (const char*)&g_wB[0][0];
#pragma unroll
        for (int i = 0; i < 2; i++) {
            int off = (tid + i * 256) * 16;
            cp16(sbase + WSLOT + off, src + off);
        }
        cp_commit();
    }
    {
        uint2 z2 = make_uint2(0u, 0u);
#pragma unroll
        for (int pass = 0; pass < 4; pass++) {
            int p = pass * 16 + hw;
            float dy = offs_s[p * 20 + 0];
            float dx = offs_s[p * 20 + 1];
            float ys = (float)(y - 1) + dy;
            float xs = (float)(x0 + p - 1) + dx;
            float y0f = floorf(ys), x0f = floorf(xs);
            float fy = ys - y0f, fx = xs - x0f;
            int iy = (int)y0f, ix = (int)x0f;
            bool vy0 = ((unsigned)iy < (unsigned)HH);
            bool vy1 = ((unsigned)(iy + 1) < (unsigned)HH);
            bool vx0 = ((unsigned)ix < (unsigned)WW);
            bool vx1 = ((unsigned)(ix + 1) < (unsigned)WW);
            float w00 = (1.f - fy) * (1.f - fx);
            float w01 = (1.f - fy) * fx;
            float w10 = fy * (1.f - fx);
            float w11 = fy * fx;
            const uint2* bp = (const uint2*)(xTb + (iy * WW + ix) * CC) + l;
            uint2 r00 = (vy0 && vx0) ? bp[0] : z2;
            uint2 r01 = (vy0 && vx1) ? bp[16] : z2;
            uint2 r10 = (vy1 && vx0) ? bp[WW * 16] : z2;
            uint2 r11 = (vy1 && vx1) ? bp[WW * 16 + 16] : z2;
            uint32_t off = (uint32_t)p * 128 +
                (((uint32_t)(8 * l)) ^ (((uint32_t)p & 7) << 4));
            interp_store4h(w00, w01, w10, w11, r00, r01, r10, r11,
                           sm, sm + 8192, off);
        }
    }

    int m0 = (wid & 3) * 16;
    int wn = wid >> 2;
    int rA = (lane & 7) + 8 * ((lane >> 3) & 1);
    int cg = lane >> 4;
    uint32_t xorA0 = ((uint32_t)rA & 7) << 4;
    uint32_t bcol[2];
#pragma unroll
    for (int nt = 0; nt < 2; nt++)
        bcol[nt] = (((uint32_t)(wn * 64 + nt * 32 + cg * 16)) ^ xorA0);

    float acc[4][4];
#pragma unroll
    for (int j = 0; j < 4; j++)
#pragma unroll
        for (int q = 0; q < 4; q++) acc[j][q] = 0.f;

    for (int kk = 0; kk < K2; kk++) {
        cp_wait0();
        __syncthreads();
        int buf = kk & 1;
        uint32_t aHbase = sbase + buf * 16384;
        uint32_t aLbase = aHbase + 8192;
        uint32_t wBase  = sbase + WSLOT + (uint32_t)(buf * 8192);   // slot kk&1

        bool pre = (kk + 1 < K2);
        int nb = buf ^ 1;
        char* AHn = sm + nb * 16384;
        char* ALn = AHn + 8192;

        int ki = 0, kj = 0;
        float2 offs2[4];
        if (pre) {
            // prefetch W chunk kk+1 into slot (kk+1)&1 (disjoint from read slot)
            const char* src = (const char*)&g_wB[kk + 1][0];
            uint32_t dst = sbase + WSLOT + (uint32_t)(nb * 8192);
#pragma unroll
            for (int i = 0; i < 2; i++) {
                int off = (tid + i * 256) * 16;
                cp16(dst + off, src + off);
            }
            cp_commit();
            ki = (kk + 1) / 3;
            kj = (kk + 1) % 3;
#pragma unroll
            for (int s = 0; s < 4; s++) {
                int p = s * 16 + hw;
                offs2[s] = make_float2(offs_s[p * 20 + 2 * (kk + 1)],
                                       offs_s[p * 20 + 2 * (kk + 1) + 1]);
            }
        }

        uint2 z2 = make_uint2(0u, 0u);
#pragma unroll
        for (int s = 0; s < 4; s++) {
            // --- issue gather LDG.64s for pass s of chunk kk+1 ---
            uint2 r00, r01, r10, r11;
            float fy = 0.f, fx = 0.f;
            if (pre) {
                int p = s * 16 + hw;
                float ys = (float)(y - 1 + ki) + offs2[s].x;
                float xs = (float)(x0 + p - 1 + kj) + offs2[s].y;
                float y0f = floorf(ys), x0f = floorf(xs);
                fy = ys - y0f; fx = xs - x0f;
                int iy = (int)y0f, ix = (int)x0f;
                bool vy0 = ((unsigned)iy < (unsigned)HH);
                bool vy1 = ((unsigned)(iy + 1) < (unsigned)HH);
                bool vx0 = ((unsigned)ix < (unsigned)WW);
                bool vx1 = ((unsigned)(ix + 1) < (unsigned)WW);
                const uint2* bp = (const uint2*)(xTb + (iy * WW + ix) * CC) + l;
                r00 = (vy0 && vx0) ? bp[0] : z2;
                r01 = (vy0 && vx1) ? bp[16] : z2;
                r10 = (vy1 && vx0) ? bp[WW * 16] : z2;
                r11 = (vy1 && vx1) ? bp[WW * 16 + 16] : z2;
            }

            // --- MMA step s on chunk kk ---
            {
                int k0 = s * 16;
                uint32_t a_hi[4], a_lo[4];
                uint32_t acolb = ((uint32_t)(2 * k0 + cg * 16)) ^ xorA0;
                uint32_t arow = (uint32_t)(m0 + rA) * 128;
                ldsm4(aHbase + arow + acolb, a_hi);
                ldsm4(aLbase + arow + acolb, a_lo);
                uint32_t bb[2][4];
                uint32_t brow = (uint32_t)(k0 + rA) * 128;
#pragma unroll
                for (int nt = 0; nt < 2; nt++)
                    ldsm4t(wBase + brow + bcol[nt], bb[nt]);
#pragma unroll
                for (int n8 = 0; n8 < 4; n8++) {
                    const uint32_t* bp2 = &bb[n8 >> 1][(n8 & 1) * 2];
                    mma16816(acc[n8], a_hi, bp2);
                    mma16816(acc[n8], a_lo, bp2);
                }
            }

            // --- interp + STS pass s to next buffers ---
            if (pre) {
                int p = s * 16 + hw;
                float w00 = (1.f - fy) * (1.f - fx);
                float w01 = (1.f - fy) * fx;
                float w10 = fy * (1.f - fx);
                float w11 = fy * fx;
                uint32_t off = (uint32_t)p * 128 +
                    (((uint32_t)(8 * l)) ^ (((uint32_t)p & 7) << 4));
                interp_store4h(w00, w01, w10, w11, r00, r01, r10, r11,
                               AHn, ALn, off);
            }
        }
    }

    // ---- epilogue ----
    __syncthreads();
    float* Sd = (float*)sm;
#pragma unroll
    for (int n8 = 0; n8 < 4; n8++) {
        int pr = m0 + (lane >> 2);
        int o0 = wn * 32 + n8 * 8 + 2 * (lane & 3);
        float* bse = Sd + o0 * PD;
        bse[pr]          = acc[n8][0];
        bse[PD + pr]     = acc[n8][1];
        bse[pr + 8]      = acc[n8][2];
        bse[PD + pr + 8] = acc[n8][3];
    }
    __syncthreads();

    size_t obase = (size_t)b * COUT * (HH * WW) + (size_t)y * WW + x0;
#pragma unroll
    for (int i = tid; i < 64 * 16; i += 256) {
        int o  = i >> 4;
        int pq = i & 15;
        float4 v = *(const float4*)&Sd[o * PD + pq * 4];
        *(float4*)(out + obase + (size_t)o * (HH * WW) + pq * 4) = v;
    }
}

// ---------------------------------------------------------------------------
extern "C" void kernel_launch(void* const* d_in, const int* in_sizes, int n_in,
                              void* d_out, int out_size) {
    const float* x  = (const float*)d_in[0];
    const float* wo = (const float*)d_in[1];
    const float* wd = (const float*)d_in[2];
    float* out = (float*)d_out;

    cudaFuncSetAttribute(k_fused, cudaFuncAttributeMaxDynamicSharedMemorySize,
                         SMEM_TOTAL);

    dim3 tb(32, 8);
    dim3 tg(HH * WW / 32, CC / 32, BB);
    k_transpose<<<tg, tb>>>(x);

    k_wprep2<<<(K2 * 64 * 64 + K2 * 64 * 32 + 255) / 256, 256>>>(wd, wo);

    k_fused<<<NPIX / TP, 256, SMEM_TOTAL>>>(out);
}